// round 9
// baseline (speedup 1.0000x reference)
#include <cuda_runtime.h>
#include <cuda_fp16.h>
#include <math.h>
#include <stdint.h>

#define HIDDEN 256
#define T_HOR  24
#define FMET   16
#define B_SZ   16
#define N_SZ   1000
#define GRP    5
#define TPB    256
#define NCTA   296            // persistent: 2 per SM
#define TOTAL_G (B_SZ * (N_SZ / GRP))   // 3200 groups
#define EPS_LN 1e-5f

// ---- smem layout (bytes) ----
#define OFF_A     0        // A fragments (in-place streamed), 65536
#define OFF_QBH   65536    // step_q half2, 24 x 129 x 4 = 12384 -> 12416
#define OFF_FH    77952    // final_h + b_fm, 5 x 260 x 4 = 5200 -> 5248
#define OFF_FM    83200    // future_met, 5x24x16x4 = 7680
#define OFF_GAM   90880    // 1024
#define OFF_STS   91904    // 2 bufs x 1024
#define OFF_STS2  93952    // 2 bufs x 1024
#define OFF_RED   96000    // 8192
#define OFF_CS    104192   // 1024
#define OFF_GS    105216   // 1024
#define OFF_W2S   106240   // 1024
#define SMEM_TOTAL 107264  // x2 CTAs = 214528 <= 228KB

typedef unsigned long long u64;

// W1 fragment-packed (u32): [kstep 16]{2048} [ntpair 16]{128} [lane 32]{4} [slot 4]
__device__ __align__(16) uint32_t g_Bpk[16 * 2048];
// W_fm as f32x2 pairs: [cp 128][f 16] u64
__device__ __align__(16) u64 g_Wfm2[128 * 16];
__device__ float g_C[HIDDEN];
__device__ float g_G[HIDDEN];
__device__ float g_W2[HIDDEN];

__device__ __forceinline__ u64 pk2(float lo, float hi) {
    u64 r; asm("mov.b64 %0, {%1, %2};" : "=l"(r) : "f"(lo), "f"(hi)); return r;
}
__device__ __forceinline__ void upk2(u64 v, float &lo, float &hi) {
    asm("mov.b64 {%0, %1}, %2;" : "=f"(lo), "=f"(hi) : "l"(v));
}
__device__ __forceinline__ void ffma2(u64 &d, u64 a, u64 b) {
    asm("fma.rn.f32x2 %0, %1, %2, %0;" : "+l"(d) : "l"(a), "l"(b));
}
__device__ __forceinline__ u64 fadd2(u64 a, u64 b) {
    u64 d; asm("add.rn.f32x2 %0, %1, %2;" : "=l"(d) : "l"(a), "l"(b)); return d;
}
__device__ __forceinline__ u64 fmul2(u64 a, u64 b) {
    u64 d; asm("mul.rn.f32x2 %0, %1, %2;" : "=l"(d) : "l"(a), "l"(b)); return d;
}

__global__ void prep_w1(const float* __restrict__ W1) {
    const int k0 = blockIdx.x * 2;
    const int n  = threadIdx.x;
    float v0 = W1[k0 * 256 + n];
    float v1 = W1[(k0 + 1) * 256 + n];
    __half2 hp = __floats2half2_rn(v0, v1);
    const int ks    = k0 >> 4;
    const int kk    = k0 & 15;
    const int ntile = n >> 3;
    const int lane  = ((n & 7) << 2) | ((kk & 7) >> 1);
    const int reg   = (kk >> 3) & 1;
    const int pair  = ntile >> 1;
    const int slot  = (ntile & 1) * 2 + reg;
    g_Bpk[ks * 2048 + pair * 128 + lane * 4 + slot] = *(uint32_t*)&hp;
}

__global__ void prep_wfm(const float* __restrict__ W_fm) {
    int idx = blockIdx.x * 256 + threadIdx.x;   // 2048 entries
    int cp = idx >> 4, f = idx & 15;
    g_Wfm2[cp * 16 + f] = pk2(W_fm[f * 256 + 2 * cp], W_fm[f * 256 + 2 * cp + 1]);
}

__global__ void prep_cg(const float* __restrict__ W1, const float* __restrict__ gamma,
                        const float* __restrict__ beta, const float* __restrict__ b1,
                        const float* __restrict__ W2) {
    int j = threadIdx.x;
    float P = 0.f, G = 0.f;
    for (int c = 0; c < 256; c++) {
        float w = W1[c * 256 + j];
        P = fmaf(beta[c], w, P);
        G = fmaf(gamma[c], w, G);
    }
    g_C[j]  = P + b1[j];
    g_G[j]  = G;
    g_W2[j] = W2[j];
}

__device__ __forceinline__ uint32_t smem_u32(const void* p) {
    uint32_t a;
    asm("{ .reg .u64 t; cvta.to.shared.u64 t, %1; cvt.u32.u64 %0, t; }" : "=r"(a) : "l"(p));
    return a;
}

#define LDS128(r, addr) \
    asm volatile("ld.shared.v4.b32 {%0,%1,%2,%3}, [%4];" \
        : "=r"((r)[0]), "=r"((r)[1]), "=r"((r)[2]), "=r"((r)[3]) : "r"(addr))

#define MMA_F32(d, a, b0, b1v) \
    asm volatile("mma.sync.aligned.m16n8k16.row.col.f32.f16.f16.f32 " \
        "{%0,%1,%2,%3}, {%4,%5,%6,%7}, {%8,%9}, {%0,%1,%2,%3};" \
        : "+f"((d)[0]), "+f"((d)[1]), "+f"((d)[2]), "+f"((d)[3]) \
        : "r"((a)[0]), "r"((a)[1]), "r"((a)[2]), "r"((a)[3]), \
          "r"(b0), "r"(b1v))

__device__ __forceinline__ float gelu_exact(float x) {
    return 0.5f * x * (1.0f + erff(x * 0.70710678118654752440f));
}

// stage FH (final_h + b_fm) and FM for group g into single buffers
__device__ __forceinline__ void stage_group(float* smf, int g,
        const float* __restrict__ final_h, const float* __restrict__ future_met,
        const float* __restrict__ b_fm, int tid)
{
    const int b = g / (N_SZ / GRP), n0 = (g % (N_SZ / GRP)) * GRP;
    for (int i = tid; i < GRP * 256; i += TPB) {
        int lni = i >> 8, c = i & 255;
        smf[OFF_FH / 4 + lni * 260 + c] =
            final_h[((size_t)b * N_SZ + n0) * 256 + i] + b_fm[c];
    }
    for (int i = tid; i < GRP * T_HOR * FMET; i += TPB) {
        int lni = i / (T_HOR * FMET), r = i % (T_HOR * FMET);
        int tt = r >> 4, f = r & 15;
        smf[OFF_FM / 4 + (lni * T_HOR + tt) * FMET + f] =
            future_met[((size_t)(b * T_HOR + tt) * N_SZ + (n0 + lni)) * FMET + f];
    }
}

// phase A for one k-chunk (16 cols): compute combined, stats, STS gamma-scaled fp16
__device__ __forceinline__ void phaseA_chunk(char* smem, float* smf, int ks,
        int t, int ln, const float* fmv, u64& accS, u64& accS2,
        uint32_t mbase, uint32_t lane_m, uint32_t reg_m)
{
    const __half2* qbp = (const __half2*)(smem + OFF_QBH) + t * 129;
    const u64* fhp = (const u64*)(smf + OFF_FH / 4 + ln * 260);
    const u64* gmp = (const u64*)(smf + OFF_GAM / 4);
#pragma unroll
    for (int j = 0; j < 8; j++) {
        const int cp = ks * 8 + j;
        const int c  = cp * 2;
        float2 qf = __half22float2(qbp[cp]);
        u64 v = fadd2(pk2(qf.x, qf.y), fhp[cp]);
        const ulonglong2* wfp = (const ulonglong2*)(g_Wfm2 + (size_t)cp * 16);
#pragma unroll
        for (int f8 = 0; f8 < 8; f8++) {
            ulonglong2 wp = __ldg(&wfp[f8]);
            ffma2(v, pk2(fmv[2 * f8],     fmv[2 * f8]),     wp.x);
            ffma2(v, pk2(fmv[2 * f8 + 1], fmv[2 * f8 + 1]), wp.y);
        }
        accS = fadd2(accS, v);
        ffma2(accS2, v, v);
        u64 a = fmul2(v, gmp[cp]);
        float a0, a1; upk2(a, a0, a1);
        __half2 hp = __floats2half2_rn(a0, a1);
        const uint32_t kk  = (uint32_t)(c & 15);
        const uint32_t lnA = lane_m | ((kk & 7) >> 1);
        const uint32_t reg = ((kk & 8) ? 2u : 0u) | reg_m;
        uint32_t off = ((mbase + (uint32_t)(c >> 4)) << 9) + (lnA << 4) + (reg << 2);
        off ^= (off >> 2) & 0x60;
        *(uint32_t*)(smem + OFF_A + off) = *(uint32_t*)&hp;
    }
}

__device__ __forceinline__ void load_fmv(const float* smf, int ln, int t, float* fmv) {
    const float4* p = (const float4*)(smf + OFF_FM / 4 + (ln * T_HOR + t) * FMET);
    float4 x0 = p[0], x1 = p[1], x2 = p[2], x3 = p[3];
    fmv[0]=x0.x; fmv[1]=x0.y; fmv[2]=x0.z; fmv[3]=x0.w;
    fmv[4]=x1.x; fmv[5]=x1.y; fmv[6]=x1.z; fmv[7]=x1.w;
    fmv[8]=x2.x; fmv[9]=x2.y; fmv[10]=x2.z; fmv[11]=x2.w;
    fmv[12]=x3.x; fmv[13]=x3.y; fmv[14]=x3.z; fmv[15]=x3.w;
}

// fused epilogue for one N-half
__device__ __forceinline__ void epi_half(const float* smf, int nh, int gi,
        const float acc[4][4][4], float part[8], int wm, int wn, int g8, int cq)
{
    float rstd[8], mr[8];
#pragma unroll
    for (int idx = 0; idx < 8; idx++) {
        const int row = wm * 64 + (idx >> 1) * 16 + (idx & 1) * 8 + g8;
        const float ssum = smf[OFF_STS / 4 + gi * 256 + row * 2] +
                           smf[OFF_STS / 4 + gi * 256 + row * 2 + 1];
        const float q2   = smf[OFF_STS2 / 4 + gi * 256 + row * 2] +
                           smf[OFF_STS2 / 4 + gi * 256 + row * 2 + 1];
        const float mu   = ssum * (1.0f / HIDDEN);
        const float var  = q2 * (1.0f / HIDDEN) - mu * mu;
        rstd[idx] = rsqrtf(var + EPS_LN);
        mr[idx]   = mu * rstd[idx];
    }
#pragma unroll
    for (int mt = 0; mt < 4; mt++)
#pragma unroll
        for (int nt = 0; nt < 4; nt++) {
            const int j = nh * 128 + wn * 32 + nt * 8 + cq * 2;
            const float cs0 = smf[OFF_CS / 4 + j],  cs1 = smf[OFF_CS / 4 + j + 1];
            const float gs0 = smf[OFF_GS / 4 + j],  gs1 = smf[OFF_GS / 4 + j + 1];
            const float w20 = smf[OFF_W2S / 4 + j], w21 = smf[OFF_W2S / 4 + j + 1];
#pragma unroll
            for (int q = 0; q < 2; q++) {
                const int idx = mt * 2 + q;
                const float o0 = fmaf(rstd[idx], acc[mt][nt][q * 2 + 0],
                                      fmaf(-mr[idx], gs0, cs0));
                const float o1 = fmaf(rstd[idx], acc[mt][nt][q * 2 + 1],
                                      fmaf(-mr[idx], gs1, cs1));
                part[idx] = fmaf(gelu_exact(o0), w20, part[idx]);
                part[idx] = fmaf(gelu_exact(o1), w21, part[idx]);
            }
        }
}

__global__ void __launch_bounds__(TPB, 2)
dhh_main(const float* __restrict__ final_h,
         const float* __restrict__ future_met,
         const float* __restrict__ step_q,
         const float* __restrict__ b_fm,
         const float* __restrict__ gamma,
         const float* __restrict__ b2,
         float* __restrict__ out)
{
    extern __shared__ __align__(1024) char smem[];
    float* smf = (float*)smem;
    const uint32_t sbase = smem_u32(smem);
    const int tid  = threadIdx.x;
    const int w    = tid >> 5;
    const int lane = tid & 31;
    const int m    = tid & 127, half = tid >> 7;
    int ln = m / 24; if (ln > 4) ln = 4;
    const int t = m % 24;
    const int wm = w & 1, wn = w >> 1;
    const int g8 = lane >> 2, cq = lane & 3;
    const uint32_t laneOff = ((uint32_t)lane << 4) ^ (((uint32_t)lane & 0x18) << 2);
    const uint32_t mbase  = (uint32_t)(m >> 4) * 16;
    const uint32_t lane_m = (uint32_t)(m & 7) << 2;
    const uint32_t reg_m  = ((m & 15) >= 8) ? 1u : 0u;

    // ---- stage constants once ----
    for (int i = tid; i < T_HOR * 128; i += TPB) {
        int tt = i >> 7, cp = i & 127;
        float2 qv = *(const float2*)&step_q[tt * 256 + 2 * cp];
        ((__half2*)(smem + OFF_QBH))[tt * 129 + cp] = __floats2half2_rn(qv.x, qv.y);
    }
    smf[OFF_GAM / 4 + tid] = gamma[tid];
    smf[OFF_CS  / 4 + tid] = g_C[tid];
    smf[OFF_GS  / 4 + tid] = g_G[tid];
    smf[OFF_W2S / 4 + tid] = g_W2[tid];
    stage_group(smf, blockIdx.x, final_h, future_met, b_fm, tid);
    __syncthreads();

    // ---- prologue: phase A for first group ----
    {
        float fmv[16];
        load_fmv(smf, ln, t, fmv);
        u64 accS = 0ull, accS2 = 0ull;
#pragma unroll
        for (int k8 = 0; k8 < 8; k8++)
            phaseA_chunk(smem, smf, half * 8 + k8, t, ln, fmv, accS, accS2,
                         mbase, lane_m, reg_m);
        float sl, sh, s2l, s2h;
        upk2(accS, sl, sh); upk2(accS2, s2l, s2h);
        smf[OFF_STS  / 4 + m * 2 + half] = sl + sh;
        smf[OFF_STS2 / 4 + m * 2 + half] = s2l + s2h;
    }
    __syncthreads();

    const uint4* gBp = (const uint4*)g_Bpk;
    int gi = 0;
    for (int i = blockIdx.x; i < TOTAL_G; i += NCTA, gi ^= 1) {
        int inext = i + NCTA; if (inext >= TOTAL_G) inext = i;
        const int b  = i / (N_SZ / GRP);
        const int n0 = (i % (N_SZ / GRP)) * GRP;

        // prefetch next group's FH/FM (current group's were consumed last pass2)
        stage_group(smf, inext, final_h, future_met, b_fm, tid);

        float part[8] = {0.f, 0.f, 0.f, 0.f, 0.f, 0.f, 0.f, 0.f};

        // ================= pass 1 (nh = 0) =================
        {
            float acc[4][4][4];
#pragma unroll
            for (int mt = 0; mt < 4; mt++)
#pragma unroll
                for (int nt = 0; nt < 4; nt++)
#pragma unroll
                    for (int e = 0; e < 4; e++) acc[mt][nt][e] = 0.f;

            const int pbase = wn * 2;
            uint4 bh[2][2];
            bh[0][0] = __ldg(gBp + 0 * 512 + (pbase + 0) * 32 + lane);
            bh[0][1] = __ldg(gBp + 0 * 512 + (pbase + 1) * 32 + lane);
            bh[1][0] = __ldg(gBp + 1 * 512 + (pbase + 0) * 32 + lane);
            bh[1][1] = __ldg(gBp + 1 * 512 + (pbase + 1) * 32 + lane);
#pragma unroll 4
            for (int ks = 0; ks < 16; ks++) {
                uint32_t ah[4][4];
#pragma unroll
                for (int mt = 0; mt < 4; mt++) {
                    const uint32_t aRow = (((uint32_t)((wm * 4 + mt) * 16 + ks)) << 9) + laneOff;
                    LDS128(ah[mt], sbase + OFF_A + aRow);
                }
                const uint4 b0 = bh[ks & 1][0];
                const uint4 b1 = bh[ks & 1][1];
                if (ks + 2 < 16) {
                    bh[ks & 1][0] = __ldg(gBp + (ks + 2) * 512 + (pbase + 0) * 32 + lane);
                    bh[ks & 1][1] = __ldg(gBp + (ks + 2) * 512 + (pbase + 1) * 32 + lane);
                }
#pragma unroll
                for (int mt = 0; mt < 4; mt++) {
                    MMA_F32(acc[mt][0], ah[mt], b0.x, b0.y);
                    MMA_F32(acc[mt][1], ah[mt], b0.z, b0.w);
                    MMA_F32(acc[mt][2], ah[mt], b1.x, b1.y);
                    MMA_F32(acc[mt][3], ah[mt], b1.z, b1.w);
                }
            }
            epi_half(smf, 0, gi, acc, part, wm, wn, g8, cq);
        }
        __syncthreads();   // pass1 A reads + staging STS complete

        // ====== pass 2 (nh = 1) with interleaved phase A(next) ======
        {
            float acc[4][4][4];
#pragma unroll
            for (int mt = 0; mt < 4; mt++)
#pragma unroll
                for (int nt = 0; nt < 4; nt++)
#pragma unroll
                    for (int e = 0; e < 4; e++) acc[mt][nt][e] = 0.f;
            u64 accS = 0ull, accS2 = 0ull;

            const int pbase = 8 + wn * 2;
            uint4 bh[2][2];
            bh[0][0] = __ldg(gBp + 0 * 512 + (pbase + 0) * 32 + lane);
            bh[0][1] = __ldg(gBp + 0 * 512 + (pbase + 1) * 32 + lane);
            bh[1][0] = __ldg(gBp + 1 * 512 + (pbase + 0) * 32 + lane);
            bh[1][1] = __ldg(gBp + 1 * 512 + (pbase + 1) * 32 + lane);

            for (int ks = 0; ks < 16; ks++) {
                uint32_t ah[4][4];
#pragma unroll
                for (int mt = 0; mt < 4; mt++) {
                    const uint32_t aRow = (((uint32_t)((wm * 4 + mt) * 16 + ks)) << 9) + laneOff;
                    LDS128(ah[mt], sbase + OFF_A + aRow);
                }
                const uint4 b0 = bh[ks & 1][0];
                const uint4 b1 = bh[ks & 1][1];
                if (ks + 2 < 16) {
                    bh[ks & 1][0] = __ldg(gBp + (ks + 2) * 512 + (pbase + 0) * 32 + lane);
                    bh[ks & 1][1] = __ldg(gBp + (ks + 2) * 512 + (pbase + 1) * 32 + lane);
                }
#pragma unroll
                for (int mt = 0; mt < 4; mt++) {
                    MMA_F32(acc[mt][0], ah[mt], b0.x, b0.y);
                    MMA_F32(acc[mt][1], ah[mt], b0.z, b0.w);
                    MMA_F32(acc[mt][2], ah[mt], b1.x, b1.y);
                    MMA_F32(acc[mt][3], ah[mt], b1.z, b1.w);
                }
                __syncthreads();   // all reads of A[ks] done -> safe to overwrite
                if (half == (ks >> 3)) {
                    float fmv[16];
                    load_fmv(smf, ln, t, fmv);
                    phaseA_chunk(smem, smf, ks, t, ln, fmv, accS, accS2,
                                 mbase, lane_m, reg_m);
                }
            }
            // stats for next group
            float sl, sh, s2l, s2h;
            upk2(accS, sl, sh); upk2(accS2, s2l, s2h);
            smf[OFF_STS  / 4 + (gi ^ 1) * 256 + m * 2 + half] = sl + sh;
            smf[OFF_STS2 / 4 + (gi ^ 1) * 256 + m * 2 + half] = s2l + s2h;

            epi_half(smf, 1, gi, acc, part, wm, wn, g8, cq);
        }

        // ---- reduce + output ----
#pragma unroll
        for (int idx = 0; idx < 8; idx++) {
            const int row = wm * 64 + (idx >> 1) * 16 + (idx & 1) * 8 + g8;
            smf[OFF_RED / 4 + row * 16 + wn * 4 + cq] = part[idx];
        }
        __syncthreads();
        if (tid < GRP * T_HOR) {
            const int lno = tid / T_HOR, to = tid % T_HOR;
            const float4* rr = (const float4*)&smf[OFF_RED / 4 + tid * 16];
            float4 r0 = rr[0], r1 = rr[1], r2 = rr[2], r3 = rr[3];
            float s = ((r0.x + r0.y) + (r0.z + r0.w)) + ((r1.x + r1.y) + (r1.z + r1.w)) +
                      ((r2.x + r2.y) + (r2.z + r2.w)) + ((r3.x + r3.y) + (r3.z + r3.w));
            out[(size_t)(b * T_HOR + to) * N_SZ + (n0 + lno)] = s + b2[0];
        }
        __syncthreads();   // protect RED + stats buffers before next iteration
    }
}

extern "C" void kernel_launch(void* const* d_in, const int* in_sizes, int n_in,
                              void* d_out, int out_size) {
    const float* final_h    = (const float*)d_in[0];
    const float* future_met = (const float*)d_in[1];
    const float* step_q     = (const float*)d_in[2];
    const float* W_fm       = (const float*)d_in[3];
    const float* b_fm       = (const float*)d_in[4];
    const float* gamma      = (const float*)d_in[5];
    const float* beta       = (const float*)d_in[6];
    const float* W1         = (const float*)d_in[7];
    const float* b1         = (const float*)d_in[8];
    const float* W2         = (const float*)d_in[9];
    const float* b2         = (const float*)d_in[10];
    float* out = (float*)d_out;

    prep_w1<<<128, 256>>>(W1);
    prep_wfm<<<8, 256>>>(W_fm);
    prep_cg<<<1, 256>>>(W1, gamma, beta, b1, W2);

    cudaFuncSetAttribute(dhh_main, cudaFuncAttributeMaxDynamicSharedMemorySize, SMEM_TOTAL);
    dhh_main<<<NCTA, TPB, SMEM_TOTAL>>>(final_h, future_met, step_q, b_fm,
                                        gamma, b2, out);
}

// round 10
// speedup vs baseline: 2.9661x; 2.9661x over previous
#include <cuda_runtime.h>
#include <cuda_fp16.h>
#include <math.h>
#include <stdint.h>

#define HIDDEN 256
#define T_HOR  24
#define FMET   16
#define B_SZ   16
#define N_SZ   1000
#define GRP    5
#define TPB    256
#define NCTA   (B_SZ * (N_SZ / GRP))   // 3200
#define NBN    (B_SZ * N_SZ)           // 16000
#define EPS_LN 1e-5f

// ---- smem layout (bytes) ----
#define OFF_A     0        // A fragments: 8 mtiles x 17 ksteps x 512 = 69632
#define OFF_QBG   69632    // (q+b_fm)*gamma, f32, 24 x 262 = 25152 -> 94784
#define OFF_FHG   94784    // fh*gamma, f32, 5 x 260 = 5200 -> 99984
#define OFF_RSTD  99984    // 512
#define OFF_MR    100496   // 512
#define OFF_CS    101008   // 1024
#define OFF_GS    102032   // 1024
#define OFF_W2S   103056   // 1024
#define OFF_RED   104080   // 8192
#define SMEM_TOTAL 112384  // x2 = 224768 <= 228KB

typedef unsigned long long u64;

// B pack: [kstep 17]{2048 u32} [ntpair 16]{128} [lane 32]{4} [slot 4]
__device__ __align__(16) uint32_t g_Bpk[17 * 2048];
__device__ float g_Wfm1[16 * 256];
__device__ float g_C[HIDDEN];
__device__ float g_G[HIDDEN];
__device__ float g_W2[HIDDEN];
__device__ float g_qb[T_HOR * 256];
__device__ float g_Sqb[T_HOR];
__device__ float g_nqb[T_HOR];
__device__ float g_QB16[T_HOR * 16];
__device__ float g_sfm[16];
__device__ float g_Gm[16 * 16];
__device__ float g_Sfh[NBN];
__device__ float g_nfh[NBN];
__device__ float g_F16[NBN * 16];
__device__ float g_DOT[NBN * T_HOR];

__device__ __forceinline__ u64 pk2(float lo, float hi) {
    u64 r; asm("mov.b64 %0, {%1, %2};" : "=l"(r) : "f"(lo), "f"(hi)); return r;
}
__device__ __forceinline__ void upk2(u64 v, float &lo, float &hi) {
    asm("mov.b64 {%0, %1}, %2;" : "=f"(lo), "=f"(hi) : "l"(v));
}
__device__ __forceinline__ u64 fadd2(u64 a, u64 b) {
    u64 d; asm("add.rn.f32x2 %0, %1, %2;" : "=l"(d) : "l"(a), "l"(b)); return d;
}
__device__ __forceinline__ uint32_t smem_u32(const void* p) {
    uint32_t a;
    asm("{ .reg .u64 t; cvta.to.shared.u64 t, %1; cvt.u32.u64 %0, t; }" : "=r"(a) : "l"(p));
    return a;
}
#define LDS128(r, addr) \
    asm volatile("ld.shared.v4.b32 {%0,%1,%2,%3}, [%4];" \
        : "=r"((r)[0]), "=r"((r)[1]), "=r"((r)[2]), "=r"((r)[3]) : "r"(addr))
#define MMA_F32(d, a, b0, b1v) \
    asm volatile("mma.sync.aligned.m16n8k16.row.col.f32.f16.f16.f32 " \
        "{%0,%1,%2,%3}, {%4,%5,%6,%7}, {%8,%9}, {%0,%1,%2,%3};" \
        : "+f"((d)[0]), "+f"((d)[1]), "+f"((d)[2]), "+f"((d)[3]) \
        : "r"((a)[0]), "r"((a)[1]), "r"((a)[2]), "r"((a)[3]), \
          "r"(b0), "r"(b1v))

__device__ __forceinline__ float gelu_exact(float x) {
    return 0.5f * x * (1.0f + erff(x * 0.70710678118654752440f));
}

// warp+block reduce (256 threads); result valid on tid 0
__device__ __forceinline__ float block_sum(float v, float* red, int tid) {
#pragma unroll
    for (int o = 16; o; o >>= 1) v += __shfl_xor_sync(0xffffffffu, v, o);
    if ((tid & 31) == 0) red[tid >> 5] = v;
    __syncthreads();
    float x = 0.f;
    if (tid < 32) {
        x = (tid < 8) ? red[tid] : 0.f;
#pragma unroll
        for (int o = 4; o; o >>= 1) x += __shfl_xor_sync(0xffffffffu, x, o);
    }
    __syncthreads();
    return x;
}

// ================= prep kernels =================
__global__ void prep_w1(const float* __restrict__ W1) {
    const int k0 = blockIdx.x * 2;
    const int n  = threadIdx.x;
    __half2 hp = __floats2half2_rn(W1[k0 * 256 + n], W1[(k0 + 1) * 256 + n]);
    const int ks = k0 >> 4, kk = k0 & 15;
    const int ntile = n >> 3;
    const int lane  = ((n & 7) << 2) | ((kk & 7) >> 1);
    const int reg   = (kk >> 3) & 1;
    g_Bpk[ks * 2048 + (ntile >> 1) * 128 + lane * 4 + (ntile & 1) * 2 + reg] = *(uint32_t*)&hp;
}

__global__ void prep_cg(const float* __restrict__ W1, const float* __restrict__ gamma,
                        const float* __restrict__ beta, const float* __restrict__ b1,
                        const float* __restrict__ W2) {
    int j = threadIdx.x;
    float P = 0.f, G = 0.f;
    for (int c = 0; c < 256; c++) {
        float w = W1[c * 256 + j];
        P = fmaf(beta[c], w, P);
        G = fmaf(gamma[c], w, G);
    }
    g_C[j]  = P + b1[j];
    g_G[j]  = G;
    g_W2[j] = W2[j];
}

__global__ void prep_wfm1(const float* __restrict__ W_fm, const float* __restrict__ gamma,
                          const float* __restrict__ W1) {
    int f = blockIdx.x, n = threadIdx.x;
    float s = 0.f;
    for (int c = 0; c < 256; c++)
        s = fmaf(W_fm[f * 256 + c] * gamma[c], W1[c * 256 + n], s);
    g_Wfm1[f * 256 + n] = s;
}

__global__ void prep_packfm1() {
    const int k0 = blockIdx.x * 2;
    const int n  = threadIdx.x;
    __half2 hp = __floats2half2_rn(g_Wfm1[k0 * 256 + n], g_Wfm1[(k0 + 1) * 256 + n]);
    const int kk = k0 & 15;
    const int ntile = n >> 3;
    const int lane  = ((n & 7) << 2) | ((kk & 7) >> 1);
    const int reg   = (kk >> 3) & 1;
    g_Bpk[16 * 2048 + (ntile >> 1) * 128 + lane * 4 + (ntile & 1) * 2 + reg] = *(uint32_t*)&hp;
}

__global__ void prep_qt(const float* __restrict__ step_q, const float* __restrict__ b_fm,
                        const float* __restrict__ W_fm) {
    __shared__ float qb_s[256];
    __shared__ float red[8];
    const int t = blockIdx.x, c = threadIdx.x;
    const int w = c >> 5, lane = c & 31;
    float qb = step_q[t * 256 + c] + b_fm[c];
    qb_s[c] = qb;
    g_qb[t * 256 + c] = qb;
    __syncthreads();
    float s = block_sum(qb, red, c);
    if (c == 0) g_Sqb[t] = s;
    float s2 = block_sum(qb * qb, red, c);
    if (c == 0) g_nqb[t] = s2;
    // QB16: warp w handles f = 2w, 2w+1
#pragma unroll
    for (int q = 0; q < 2; q++) {
        int f = w * 2 + q;
        float d = 0.f;
#pragma unroll
        for (int i = 0; i < 8; i++)
            d = fmaf(W_fm[f * 256 + lane + 32 * i], qb_s[lane + 32 * i], d);
#pragma unroll
        for (int o = 16; o; o >>= 1) d += __shfl_xor_sync(0xffffffffu, d, o);
        if (lane == 0) g_QB16[t * 16 + f] = d;
    }
}

__global__ void prep_gm(const float* __restrict__ W_fm) {
    __shared__ float wf_s[256];
    __shared__ float red[8];
    const int f = blockIdx.x, c = threadIdx.x;
    const int w = c >> 5, lane = c & 31;
    float wf = W_fm[f * 256 + c];
    wf_s[c] = wf;
    __syncthreads();
    float s = block_sum(wf, red, c);
    if (c == 0) g_sfm[f] = s;
#pragma unroll
    for (int q = 0; q < 2; q++) {
        int g = w * 2 + q;
        float d = 0.f;
#pragma unroll
        for (int i = 0; i < 8; i++)
            d = fmaf(W_fm[g * 256 + lane + 32 * i], wf_s[lane + 32 * i], d);
#pragma unroll
        for (int o = 16; o; o >>= 1) d += __shfl_xor_sync(0xffffffffu, d, o);
        if (lane == 0) g_Gm[f * 16 + g] = d;
    }
}

__global__ void prep_bn(const float* __restrict__ final_h, const float* __restrict__ W_fm) {
    __shared__ float fh_s[256];
    __shared__ float red[8];
    const int bn = blockIdx.x, c = threadIdx.x;
    const int w = c >> 5, lane = c & 31;
    float fh = final_h[(size_t)bn * 256 + c];
    fh_s[c] = fh;
    __syncthreads();
    float s = block_sum(fh, red, c);
    if (c == 0) g_Sfh[bn] = s;
    float s2 = block_sum(fh * fh, red, c);
    if (c == 0) g_nfh[bn] = s2;
    // F16: warp w -> f = 2w, 2w+1
#pragma unroll
    for (int q = 0; q < 2; q++) {
        int f = w * 2 + q;
        float d = 0.f;
#pragma unroll
        for (int i = 0; i < 8; i++)
            d = fmaf(W_fm[f * 256 + lane + 32 * i], fh_s[lane + 32 * i], d);
#pragma unroll
        for (int o = 16; o; o >>= 1) d += __shfl_xor_sync(0xffffffffu, d, o);
        if (lane == 0) g_F16[bn * 16 + f] = d;
    }
    // DOT: warp w -> t = 3w, 3w+1, 3w+2
#pragma unroll
    for (int q = 0; q < 3; q++) {
        int t = w * 3 + q;
        float d = 0.f;
#pragma unroll
        for (int i = 0; i < 8; i++)
            d = fmaf(g_qb[t * 256 + lane + 32 * i], fh_s[lane + 32 * i], d);
#pragma unroll
        for (int o = 16; o; o >>= 1) d += __shfl_xor_sync(0xffffffffu, d, o);
        if (lane == 0) g_DOT[bn * T_HOR + t] = d;
    }
}

// ================= main kernel =================
__global__ void __launch_bounds__(TPB, 2)
dhh_main(const float* __restrict__ final_h,
         const float* __restrict__ future_met,
         const float* __restrict__ step_q,
         const float* __restrict__ b_fm,
         const float* __restrict__ gamma,
         const float* __restrict__ b2,
         float* __restrict__ out)
{
    extern __shared__ __align__(1024) char smem[];
    float* smf = (float*)smem;
    const uint32_t sbase = smem_u32(smem);
    const int tid  = threadIdx.x;
    const int w    = tid >> 5;
    const int lane = tid & 31;
    const int m    = tid & 127, half = tid >> 7;
    int ln = m / 24; if (ln > 4) ln = 4;
    const int t = m % 24;

    const int b  = blockIdx.x / (N_SZ / GRP);
    const int n0 = (blockIdx.x % (N_SZ / GRP)) * GRP;
    const int bn = b * N_SZ + n0 + ln;

    // ---- early LDG: this thread's future_met row ----
    float fmv[16];
    {
        const float4* fmp = (const float4*)&future_met[
            ((size_t)(b * T_HOR + t) * N_SZ + (n0 + ln)) * FMET];
        float4 x0 = fmp[0], x1 = fmp[1], x2 = fmp[2], x3 = fmp[3];
        fmv[0]=x0.x; fmv[1]=x0.y; fmv[2]=x0.z;  fmv[3]=x0.w;
        fmv[4]=x1.x; fmv[5]=x1.y; fmv[6]=x1.z;  fmv[7]=x1.w;
        fmv[8]=x2.x; fmv[9]=x2.y; fmv[10]=x2.z; fmv[11]=x2.w;
        fmv[12]=x3.x; fmv[13]=x3.y; fmv[14]=x3.z; fmv[15]=x3.w;
    }

    // ---- staging ----
    {
        const float bfc = b_fm[tid], gc = gamma[tid];
        // qbg[t][c] = (q + b_fm)*gamma, stride 262 floats, c = tid
        for (int tt = 0; tt < T_HOR; tt++)
            smf[OFF_QBG / 4 + tt * 262 + tid] =
                (step_q[tt * 256 + tid] + bfc) * gc;
        // fhg[ln][c] = fh*gamma, stride 260
        for (int lni = 0; lni < GRP; lni++)
            smf[OFF_FHG / 4 + lni * 260 + tid] =
                final_h[((size_t)(b * N_SZ + n0 + lni)) * 256 + tid] * gc;
        smf[OFF_CS  / 4 + tid] = g_C[tid];
        smf[OFF_GS  / 4 + tid] = g_G[tid];
        smf[OFF_W2S / 4 + tid] = g_W2[tid];
    }
    __syncthreads();

    // ---- phase A: base fragments (fadd2 + cvt + STS), fm block, stats ----
    {
        const uint32_t mbase  = (uint32_t)(m >> 4) * 17;
        const uint32_t lane_m = (uint32_t)(m & 7) << 2;
        const uint32_t reg_m  = ((m & 15) >= 8) ? 1u : 0u;
        const u64* qbp = (const u64*)(smf + OFF_QBG / 4) + t * 131;
        const u64* fhp = (const u64*)(smf + OFF_FHG / 4) + ln * 130;
#pragma unroll 8
        for (int i = 0; i < 64; i++) {
            const int cp = half * 64 + i;
            const int c  = 2 * cp;
            u64 v = fadd2(fhp[cp], qbp[cp]);
            float a0, a1; upk2(v, a0, a1);
            __half2 hp = __floats2half2_rn(a0, a1);
            const uint32_t kk  = (uint32_t)(c & 15);
            const uint32_t lnA = lane_m | ((kk & 7) >> 1);
            const uint32_t reg = ((kk & 8) ? 2u : 0u) | reg_m;
            uint32_t off = ((mbase + (uint32_t)(c >> 4)) << 9) + (lnA << 4) + (reg << 2);
            off ^= (off >> 2) & 0x60;
            *(uint32_t*)(smem + OFF_A + off) = *(uint32_t*)&hp;
        }
        if (half == 0) {
            // fm block: kstep 16, cols 2j
#pragma unroll
            for (int j = 0; j < 8; j++) {
                __half2 hp = __floats2half2_rn(fmv[2 * j], fmv[2 * j + 1]);
                const uint32_t kk  = (uint32_t)(2 * j);
                const uint32_t lnA = lane_m | ((kk & 7) >> 1);
                const uint32_t reg = ((kk & 8) ? 2u : 0u) | reg_m;
                uint32_t off = ((mbase + 16u) << 9) + (lnA << 4) + (reg << 2);
                off ^= (off >> 2) & 0x60;
                *(uint32_t*)(smem + OFF_A + off) = *(uint32_t*)&hp;
            }
            // stats (algebraic)
            float mean256 = __ldg(&g_Sfh[bn]) + __ldg(&g_Sqb[t]);
            float ss = __ldg(&g_nfh[bn]) + __ldg(&g_nqb[t]) +
                       2.0f * __ldg(&g_DOT[bn * T_HOR + t]);
            float cross = 0.f, mf = 0.f;
#pragma unroll
            for (int f = 0; f < 16; f++) {
                mf    = fmaf(fmv[f], __ldg(&g_sfm[f]), mf);
                cross = fmaf(fmv[f], __ldg(&g_F16[bn * 16 + f]) + __ldg(&g_QB16[t * 16 + f]), cross);
            }
            mean256 += mf;
            ss += 2.0f * cross;
            float quad = 0.f;
#pragma unroll
            for (int f = 0; f < 16; f++) {
                float rd = 0.f;
#pragma unroll
                for (int g = 0; g < 16; g++)
                    rd = fmaf(__ldg(&g_Gm[f * 16 + g]), fmv[g], rd);
                quad = fmaf(fmv[f], rd, quad);
            }
            ss += quad;
            const float mu   = mean256 * (1.0f / HIDDEN);
            const float var  = ss * (1.0f / HIDDEN) - mu * mu;
            const float rstd = rsqrtf(var + EPS_LN);
            smf[OFF_RSTD / 4 + m] = rstd;
            smf[OFF_MR   / 4 + m] = mu * rstd;
        }
    }
    __syncthreads();

    // ---- GEMM (17 ksteps) + fused epilogue, two N-halves ----
    const int wm = w & 1, wn = w >> 1;
    const int g8 = lane >> 2, cq = lane & 3;
    const uint32_t laneOff = ((uint32_t)lane << 4) ^ (((uint32_t)lane & 0x18) << 2);
    const uint4* gBp = (const uint4*)g_Bpk;
    float part[8] = {0.f, 0.f, 0.f, 0.f, 0.f, 0.f, 0.f, 0.f};

    float rstd[8], mr[8];
#pragma unroll
    for (int idx = 0; idx < 8; idx++) {
        const int row = wm * 64 + (idx >> 1) * 16 + (idx & 1) * 8 + g8;
        rstd[idx] = smf[OFF_RSTD / 4 + row];
        mr[idx]   = smf[OFF_MR   / 4 + row];
    }

#pragma unroll
    for (int nh = 0; nh < 2; nh++) {
        float acc[4][4][4];
#pragma unroll
        for (int mt = 0; mt < 4; mt++)
#pragma unroll
            for (int nt = 0; nt < 4; nt++)
#pragma unroll
                for (int e = 0; e < 4; e++) acc[mt][nt][e] = 0.f;

        const int pbase = nh * 8 + wn * 2;
        uint4 bh[2][2];
        bh[0][0] = __ldg(gBp + 0 * 512 + (pbase + 0) * 32 + lane);
        bh[0][1] = __ldg(gBp + 0 * 512 + (pbase + 1) * 32 + lane);
        bh[1][0] = __ldg(gBp + 1 * 512 + (pbase + 0) * 32 + lane);
        bh[1][1] = __ldg(gBp + 1 * 512 + (pbase + 1) * 32 + lane);

#pragma unroll 4
        for (int ks = 0; ks < 17; ks++) {
            uint32_t ah[4][4];
#pragma unroll
            for (int mt = 0; mt < 4; mt++) {
                const uint32_t aRow = (((uint32_t)((wm * 4 + mt) * 17 + ks)) << 9) + laneOff;
                LDS128(ah[mt], sbase + OFF_A + aRow);
            }
            const uint4 b0 = bh[ks & 1][0];
            const uint4 b1 = bh[ks & 1][1];
            if (ks + 2 < 17) {
                bh[ks & 1][0] = __ldg(gBp + (ks + 2) * 512 + (pbase + 0) * 32 + lane);
                bh[ks & 1][1] = __ldg(gBp + (ks + 2) * 512 + (pbase + 1) * 32 + lane);
            }
#pragma unroll
            for (int mt = 0; mt < 4; mt++) {
                MMA_F32(acc[mt][0], ah[mt], b0.x, b0.y);
                MMA_F32(acc[mt][1], ah[mt], b0.z, b0.w);
                MMA_F32(acc[mt][2], ah[mt], b1.x, b1.y);
                MMA_F32(acc[mt][3], ah[mt], b1.z, b1.w);
            }
        }

        // fused epilogue for this half
#pragma unroll
        for (int mt = 0; mt < 4; mt++)
#pragma unroll
            for (int nt = 0; nt < 4; nt++) {
                const int j = nh * 128 + wn * 32 + nt * 8 + cq * 2;
                const float cs0 = smf[OFF_CS / 4 + j],  cs1 = smf[OFF_CS / 4 + j + 1];
                const float gs0 = smf[OFF_GS / 4 + j],  gs1 = smf[OFF_GS / 4 + j + 1];
                const float w20 = smf[OFF_W2S / 4 + j], w21 = smf[OFF_W2S / 4 + j + 1];
#pragma unroll
                for (int q = 0; q < 2; q++) {
                    const int idx = mt * 2 + q;
                    const float o0 = fmaf(rstd[idx], acc[mt][nt][q * 2 + 0],
                                          fmaf(-mr[idx], gs0, cs0));
                    const float o1 = fmaf(rstd[idx], acc[mt][nt][q * 2 + 1],
                                          fmaf(-mr[idx], gs1, cs1));
                    part[idx] = fmaf(gelu_exact(o0), w20, part[idx]);
                    part[idx] = fmaf(gelu_exact(o1), w21, part[idx]);
                }
            }
    }

#pragma unroll
    for (int idx = 0; idx < 8; idx++) {
        const int row = wm * 64 + (idx >> 1) * 16 + (idx & 1) * 8 + g8;
        smf[OFF_RED / 4 + row * 16 + wn * 4 + cq] = part[idx];
    }
    __syncthreads();

    if (tid < GRP * T_HOR) {
        const int lno = tid / T_HOR, to = tid % T_HOR;
        const float4* rr = (const float4*)&smf[OFF_RED / 4 + tid * 16];
        float4 r0 = rr[0], r1 = rr[1], r2 = rr[2], r3 = rr[3];
        float s = ((r0.x + r0.y) + (r0.z + r0.w)) + ((r1.x + r1.y) + (r1.z + r1.w)) +
                  ((r2.x + r2.y) + (r2.z + r2.w)) + ((r3.x + r3.y) + (r3.z + r3.w));
        out[(size_t)(b * T_HOR + to) * N_SZ + (n0 + lno)] = s + b2[0];
    }
}

extern "C" void kernel_launch(void* const* d_in, const int* in_sizes, int n_in,
                              void* d_out, int out_size) {
    const float* final_h    = (const float*)d_in[0];
    const float* future_met = (const float*)d_in[1];
    const float* step_q     = (const float*)d_in[2];
    const float* W_fm       = (const float*)d_in[3];
    const float* b_fm       = (const float*)d_in[4];
    const float* gamma      = (const float*)d_in[5];
    const float* beta       = (const float*)d_in[6];
    const float* W1         = (const float*)d_in[7];
    const float* b1         = (const float*)d_in[8];
    const float* W2         = (const float*)d_in[9];
    const float* b2         = (const float*)d_in[10];
    float* out = (float*)d_out;

    prep_w1<<<128, 256>>>(W1);
    prep_cg<<<1, 256>>>(W1, gamma, beta, b1, W2);
    prep_wfm1<<<16, 256>>>(W_fm, gamma, W1);
    prep_packfm1<<<8, 256>>>();
    prep_qt<<<24, 256>>>(step_q, b_fm, W_fm);
    prep_gm<<<16, 256>>>(W_fm);
    prep_bn<<<NBN, 256>>>(final_h, W_fm);

    cudaFuncSetAttribute(dhh_main, cudaFuncAttributeMaxDynamicSharedMemorySize, SMEM_TOTAL);
    dhh_main<<<NCTA, TPB, SMEM_TOTAL>>>(final_h, future_met, step_q, b_fm,
                                        gamma, b2, out);
}

// round 12
// speedup vs baseline: 3.2501x; 1.0957x over previous
#include <cuda_runtime.h>
#include <cuda_fp16.h>
#include <math.h>
#include <stdint.h>

#define HIDDEN 256
#define T_HOR  24
#define FMET   16
#define B_SZ   16
#define N_SZ   1000
#define GRP    5
#define TPB    256
#define NCTA   (B_SZ * (N_SZ / GRP))   // 3200
#define NBN    (B_SZ * N_SZ)           // 16000
#define EPS_LN 1e-5f

// ---- main kernel smem (bytes) ----
#define OFF_AHI  0        // fm hi fragments, 8 mtiles x 512 = 4096
#define OFF_ALO  4096     // fm lo fragments, 4096
#define OFF_Q1   8192     // Q1, 24 x 258 x 4 = 24768 -> 32960
#define OFF_FH1  32960    // FH1 rows, 6 x 258 x 4 = 6192 -> 39152
#define OFF_RSTD 39152    // 512
#define OFF_MR   39664    // 512
#define OFF_CS   40176    // 1024
#define OFF_GS   41200    // 1024
#define OFF_W2S  42224    // 1024
#define OFF_RED  43248    // 8192 -> 51440
#define SMEM_TOTAL 51456

typedef unsigned long long u64;

// Wfm1 fragment packs (single kstep)
__device__ __align__(16) uint32_t g_BFMhi[2048];
__device__ __align__(16) uint32_t g_BFMlo[2048];
__device__ float g_Wfm1[16 * 256];
__device__ float g_C[HIDDEN];
__device__ float g_G[HIDDEN];
__device__ float g_W2[HIDDEN];
__device__ float g_Q1[T_HOR * 256];
__device__ float g_FH1[(size_t)NBN * 256];
__device__ float g_qb[T_HOR * 256];
__device__ float g_Sqb[T_HOR];
__device__ float g_nqb[T_HOR];
__device__ float g_QB16[T_HOR * 16];
__device__ float g_sfm[16];
__device__ float g_Gm[16 * 16];
__device__ float g_Sfh[NBN];
__device__ float g_nfh[NBN];
__device__ float g_F16[NBN * 16];
__device__ float g_DOT[NBN * T_HOR];

__device__ __forceinline__ u64 pk2(float lo, float hi) {
    u64 r; asm("mov.b64 %0, {%1, %2};" : "=l"(r) : "f"(lo), "f"(hi)); return r;
}
__device__ __forceinline__ void upk2(u64 v, float &lo, float &hi) {
    asm("mov.b64 {%0, %1}, %2;" : "=f"(lo), "=f"(hi) : "l"(v));
}
__device__ __forceinline__ void ffma2(u64 &d, u64 a, u64 b) {
    asm("fma.rn.f32x2 %0, %1, %2, %0;" : "+l"(d) : "l"(a), "l"(b));
}
__device__ __forceinline__ uint32_t smem_u32(const void* p) {
    uint32_t a;
    asm("{ .reg .u64 t; cvta.to.shared.u64 t, %1; cvt.u32.u64 %0, t; }" : "=r"(a) : "l"(p));
    return a;
}
#define LDS128(r, addr) \
    asm volatile("ld.shared.v4.b32 {%0,%1,%2,%3}, [%4];" \
        : "=r"((r)[0]), "=r"((r)[1]), "=r"((r)[2]), "=r"((r)[3]) : "r"(addr))
#define MMA_F32(d, a, b0, b1v) \
    asm volatile("mma.sync.aligned.m16n8k16.row.col.f32.f16.f16.f32 " \
        "{%0,%1,%2,%3}, {%4,%5,%6,%7}, {%8,%9}, {%0,%1,%2,%3};" \
        : "+f"((d)[0]), "+f"((d)[1]), "+f"((d)[2]), "+f"((d)[3]) \
        : "r"((a)[0]), "r"((a)[1]), "r"((a)[2]), "r"((a)[3]), \
          "r"(b0), "r"(b1v))

__device__ __forceinline__ float gelu_exact(float x) {
    return 0.5f * x * (1.0f + erff(x * 0.70710678118654752440f));
}

__device__ __forceinline__ float block_sum(float v, float* red, int tid) {
#pragma unroll
    for (int o = 16; o; o >>= 1) v += __shfl_xor_sync(0xffffffffu, v, o);
    if ((tid & 31) == 0) red[tid >> 5] = v;
    __syncthreads();
    float x = 0.f;
    if (tid < 32) {
        x = (tid < 8) ? red[tid] : 0.f;
#pragma unroll
        for (int o = 4; o; o >>= 1) x += __shfl_xor_sync(0xffffffffu, x, o);
    }
    __syncthreads();
    return x;
}

// ================= prep kernels =================
__global__ void __launch_bounds__(256)
prep_cg(const float* __restrict__ W1, const float* __restrict__ gamma,
        const float* __restrict__ beta, const float* __restrict__ b1,
        const float* __restrict__ W2) {
    int j = threadIdx.x;
    float P = 0.f, G = 0.f;
    for (int c = 0; c < 256; c++) {
        float w = W1[c * 256 + j];
        P = fmaf(beta[c], w, P);
        G = fmaf(gamma[c], w, G);
    }
    g_C[j]  = P + b1[j];
    g_G[j]  = G;
    g_W2[j] = W2[j];
}

__global__ void __launch_bounds__(256)
prep_wfm1(const float* __restrict__ W_fm, const float* __restrict__ gamma,
          const float* __restrict__ W1) {
    int f = blockIdx.x, n = threadIdx.x;
    float s = 0.f;
    for (int c = 0; c < 256; c++)
        s = fmaf(W_fm[f * 256 + c] * gamma[c], W1[c * 256 + n], s);
    g_Wfm1[f * 256 + n] = s;
}

__global__ void __launch_bounds__(256) prep_packfm1() {
    const int k0 = blockIdx.x * 2;     // 8 blocks -> k0 0..14
    const int n  = threadIdx.x;
    float v0 = g_Wfm1[k0 * 256 + n];
    float v1 = g_Wfm1[(k0 + 1) * 256 + n];
    __half h0 = __float2half_rn(v0), h1 = __float2half_rn(v1);
    __half l0 = __float2half_rn(v0 - __half2float(h0));
    __half l1 = __float2half_rn(v1 - __half2float(h1));
    const int kk = k0 & 15;
    const int ntile = n >> 3;
    const int lane  = ((n & 7) << 2) | ((kk & 7) >> 1);
    const int reg   = (kk >> 3) & 1;
    const int idx = (ntile >> 1) * 128 + lane * 4 + (ntile & 1) * 2 + reg;
    __half2 hp = __halves2half2(h0, h1);
    __half2 lp = __halves2half2(l0, l1);
    g_BFMhi[idx] = *(uint32_t*)&hp;
    g_BFMlo[idx] = *(uint32_t*)&lp;
}

__global__ void __launch_bounds__(256)
prep_qt(const float* __restrict__ step_q, const float* __restrict__ b_fm,
        const float* __restrict__ W_fm) {
    __shared__ float qb_s[256];
    __shared__ float red[8];
    const int t = blockIdx.x, c = threadIdx.x;
    const int w = c >> 5, lane = c & 31;
    float qb = step_q[t * 256 + c] + b_fm[c];
    qb_s[c] = qb;
    g_qb[t * 256 + c] = qb;
    __syncthreads();
    float s = block_sum(qb, red, c);
    if (c == 0) g_Sqb[t] = s;
    float s2 = block_sum(qb * qb, red, c);
    if (c == 0) g_nqb[t] = s2;
#pragma unroll
    for (int q = 0; q < 2; q++) {
        int f = w * 2 + q;
        float d = 0.f;
#pragma unroll
        for (int i = 0; i < 8; i++)
            d = fmaf(W_fm[f * 256 + lane + 32 * i], qb_s[lane + 32 * i], d);
#pragma unroll
        for (int o = 16; o; o >>= 1) d += __shfl_xor_sync(0xffffffffu, d, o);
        if (lane == 0) g_QB16[t * 16 + f] = d;
    }
}

__global__ void __launch_bounds__(256)
prep_gm(const float* __restrict__ W_fm) {
    __shared__ float wf_s[256];
    __shared__ float red[8];
    const int f = blockIdx.x, c = threadIdx.x;
    const int w = c >> 5, lane = c & 31;
    float wf = W_fm[f * 256 + c];
    wf_s[c] = wf;
    __syncthreads();
    float s = block_sum(wf, red, c);
    if (c == 0) g_sfm[f] = s;
#pragma unroll
    for (int q = 0; q < 2; q++) {
        int g = w * 2 + q;
        float d = 0.f;
#pragma unroll
        for (int i = 0; i < 8; i++)
            d = fmaf(W_fm[g * 256 + lane + 32 * i], wf_s[lane + 32 * i], d);
#pragma unroll
        for (int o = 16; o; o >>= 1) d += __shfl_xor_sync(0xffffffffu, d, o);
        if (lane == 0) g_Gm[f * 16 + g] = d;
    }
}

__global__ void __launch_bounds__(256)
prep_bn(const float* __restrict__ final_h, const float* __restrict__ W_fm) {
    __shared__ float fh_s[256];
    __shared__ float red[8];
    const int bn = blockIdx.x, c = threadIdx.x;
    const int w = c >> 5, lane = c & 31;
    float fh = final_h[(size_t)bn * 256 + c];
    fh_s[c] = fh;
    __syncthreads();
    float s = block_sum(fh, red, c);
    if (c == 0) g_Sfh[bn] = s;
    float s2 = block_sum(fh * fh, red, c);
    if (c == 0) g_nfh[bn] = s2;
#pragma unroll
    for (int q = 0; q < 2; q++) {
        int f = w * 2 + q;
        float d = 0.f;
#pragma unroll
        for (int i = 0; i < 8; i++)
            d = fmaf(W_fm[f * 256 + lane + 32 * i], fh_s[lane + 32 * i], d);
#pragma unroll
        for (int o = 16; o; o >>= 1) d += __shfl_xor_sync(0xffffffffu, d, o);
        if (lane == 0) g_F16[bn * 16 + f] = d;
    }
#pragma unroll
    for (int q = 0; q < 3; q++) {
        int t = w * 3 + q;
        float d = 0.f;
#pragma unroll
        for (int i = 0; i < 8; i++)
            d = fmaf(g_qb[t * 256 + lane + 32 * i], fh_s[lane + 32 * i], d);
#pragma unroll
        for (int o = 16; o; o >>= 1) d += __shfl_xor_sync(0xffffffffu, d, o);
        if (lane == 0) g_DOT[bn * T_HOR + t] = d;
    }
}

// Q1[t][n] = sum_c qb[t][c]*gamma[c]*W1[c][n]  (exact fp32)
__global__ void __launch_bounds__(256)
prep_q1(const float* __restrict__ W1, const float* __restrict__ gamma) {
    int t = blockIdx.x, n = threadIdx.x;
    float s = 0.f;
    for (int c = 0; c < 256; c++)
        s = fmaf(g_qb[t * 256 + c] * gamma[c], W1[c * 256 + n], s);
    g_Q1[t * 256 + n] = s;
}

// FH1 = (fh * gamma) @ W1, exact fp32, scalar FFMA2. 1000 blocks x 16 rows.
#define FH1_ROWS 16
__global__ void __launch_bounds__(256)
prep_fh1s(const float* __restrict__ final_h, const float* __restrict__ gamma,
          const float* __restrict__ W1) {
    __shared__ float fhg[FH1_ROWS][260];   // stride 260 keeps float4 alignment
    const int tid = threadIdx.x;
    const int bn0 = blockIdx.x * FH1_ROWS;
    for (int i = tid; i < FH1_ROWS * 256; i += 256) {
        int r = i >> 8, c = i & 255;
        fhg[r][c] = final_h[(size_t)(bn0 + r) * 256 + c] * __ldg(&gamma[c]);
    }
    __syncthreads();
    const int cp = tid & 127;          // column pair
    const int rh = tid >> 7;           // rows rh*8 .. rh*8+7
    u64 acc[8];
#pragma unroll
    for (int r = 0; r < 8; r++) acc[r] = 0ull;
    for (int c = 0; c < 256; c += 4) {
        u64 wq[4];
#pragma unroll
        for (int q = 0; q < 4; q++) {
            float2 wv = *(const float2*)&W1[(size_t)(c + q) * 256 + 2 * cp];
            wq[q] = pk2(wv.x, wv.y);
        }
#pragma unroll
        for (int r = 0; r < 8; r++) {
            float4 xv = *(const float4*)&fhg[rh * 8 + r][c];
            ffma2(acc[r], pk2(xv.x, xv.x), wq[0]);
            ffma2(acc[r], pk2(xv.y, xv.y), wq[1]);
            ffma2(acc[r], pk2(xv.z, xv.z), wq[2]);
            ffma2(acc[r], pk2(xv.w, xv.w), wq[3]);
        }
    }
#pragma unroll
    for (int r = 0; r < 8; r++) {
        float lo, hi; upk2(acc[r], lo, hi);
        *(float2*)&g_FH1[(size_t)(bn0 + rh * 8 + r) * 256 + 2 * cp] = make_float2(lo, hi);
    }
}

// ================= main kernel =================
__global__ void __launch_bounds__(TPB, 2)
dhh_main(const float* __restrict__ future_met,
         const float* __restrict__ b2,
         float* __restrict__ out)
{
    extern __shared__ __align__(1024) char smem[];
    float* smf = (float*)smem;
    const uint32_t sbase = smem_u32(smem);
    const int tid  = threadIdx.x;
    const int w    = tid >> 5;
    const int lane = tid & 31;
    const int m    = tid & 127, half = tid >> 7;
    int ln = m / 24; if (ln > 4) ln = 4;
    const int t = m % 24;

    const int b  = blockIdx.x / (N_SZ / GRP);
    const int n0 = (blockIdx.x % (N_SZ / GRP)) * GRP;
    const int bn = b * N_SZ + n0 + ln;

    // ---- fm fragments + algebraic LN stats FIRST (fmv dies before GEMM) ----
    if (half == 0) {
        float fmv[16];
        {
            const float4* fmp = (const float4*)&future_met[
                ((size_t)(b * T_HOR + t) * N_SZ + (n0 + ln)) * FMET];
            float4 x0 = fmp[0], x1 = fmp[1], x2 = fmp[2], x3 = fmp[3];
            fmv[0]=x0.x; fmv[1]=x0.y; fmv[2]=x0.z;  fmv[3]=x0.w;
            fmv[4]=x1.x; fmv[5]=x1.y; fmv[6]=x1.z;  fmv[7]=x1.w;
            fmv[8]=x2.x; fmv[9]=x2.y; fmv[10]=x2.z; fmv[11]=x2.w;
            fmv[12]=x3.x; fmv[13]=x3.y; fmv[14]=x3.z; fmv[15]=x3.w;
        }
        const uint32_t mbase  = (uint32_t)(m >> 4);
        const uint32_t lane_m = (uint32_t)(m & 7) << 2;
        const uint32_t reg_m  = ((m & 15) >= 8) ? 1u : 0u;
#pragma unroll
        for (int j = 0; j < 8; j++) {
            float v0 = fmv[2 * j], v1 = fmv[2 * j + 1];
            __half h0 = __float2half_rn(v0), h1 = __float2half_rn(v1);
            __half l0 = __float2half_rn(v0 - __half2float(h0));
            __half l1 = __float2half_rn(v1 - __half2float(h1));
            __half2 hp = __halves2half2(h0, h1);
            __half2 lp = __halves2half2(l0, l1);
            const uint32_t kk  = (uint32_t)(2 * j);
            const uint32_t lnA = lane_m | ((kk & 7) >> 1);
            const uint32_t reg = ((kk & 8) ? 2u : 0u) | reg_m;
            uint32_t off = (mbase << 9) + (lnA << 4) + (reg << 2);
            off ^= (off >> 2) & 0x60;
            *(uint32_t*)(smem + OFF_AHI + off) = *(uint32_t*)&hp;
            *(uint32_t*)(smem + OFF_ALO + off) = *(uint32_t*)&lp;
        }
        // stats
        float mean256 = __ldg(&g_Sfh[bn]) + __ldg(&g_Sqb[t]);
        float ss = __ldg(&g_nfh[bn]) + __ldg(&g_nqb[t]) +
                   2.0f * __ldg(&g_DOT[bn * T_HOR + t]);
        float cross = 0.f, mf = 0.f;
#pragma unroll
        for (int f = 0; f < 16; f++) {
            mf    = fmaf(fmv[f], __ldg(&g_sfm[f]), mf);
            cross = fmaf(fmv[f], __ldg(&g_F16[bn * 16 + f]) + __ldg(&g_QB16[t * 16 + f]), cross);
        }
        mean256 += mf;
        ss += 2.0f * cross;
        float quad = 0.f;
#pragma unroll
        for (int f = 0; f < 16; f++) {
            float rd = 0.f;
#pragma unroll
            for (int g = 0; g < 16; g++)
                rd = fmaf(__ldg(&g_Gm[f * 16 + g]), fmv[g], rd);
            quad = fmaf(fmv[f], rd, quad);
        }
        ss += quad;
        const float mu   = mean256 * (1.0f / HIDDEN);
        const float var  = ss * (1.0f / HIDDEN) - mu * mu;
        const float rstd = rsqrtf(var + EPS_LN);
        smf[OFF_RSTD / 4 + m] = rstd;
        smf[OFF_MR   / 4 + m] = mu * rstd;
    }

    // ---- staging: Q1 (24 rows), FH1 (6 rows clamped), constants ----
#pragma unroll 4
    for (int tt = 0; tt < T_HOR; tt++)
        smf[OFF_Q1 / 4 + tt * 258 + tid] = __ldg(&g_Q1[tt * 256 + tid]);
#pragma unroll
    for (int lni = 0; lni < 6; lni++) {
        int src = lni < 4 ? lni : 4;
        smf[OFF_FH1 / 4 + lni * 258 + tid] =
            __ldg(&g_FH1[(size_t)(b * N_SZ + n0 + src) * 256 + tid]);
    }
    smf[OFF_CS  / 4 + tid] = g_C[tid];
    smf[OFF_GS  / 4 + tid] = g_G[tid];
    smf[OFF_W2S / 4 + tid] = g_W2[tid];
    __syncthreads();

    // ---- 1-kstep GEMM (3-term) + fused epilogue ----
    const int wm = w & 1, wn = w >> 1;
    const int g8 = lane >> 2, cq = lane & 3;
    const uint32_t laneOff = ((uint32_t)lane << 4) ^ (((uint32_t)lane & 0x18) << 2);
    const uint4* gFhi = (const uint4*)g_BFMhi;
    const uint4* gFlo = (const uint4*)g_BFMlo;
    float part[8] = {0.f, 0.f, 0.f, 0.f, 0.f, 0.f, 0.f, 0.f};

    float rstd[8], mr[8];
    int lnr[8], tr[8];
#pragma unroll
    for (int idx = 0; idx < 8; idx++) {
        const int row = wm * 64 + (idx >> 1) * 16 + (idx & 1) * 8 + g8;
        rstd[idx] = smf[OFF_RSTD / 4 + row];
        mr[idx]   = smf[OFF_MR   / 4 + row];
        lnr[idx]  = row / 24;
        tr[idx]   = row - lnr[idx] * 24;
    }

#pragma unroll
    for (int nh = 0; nh < 2; nh++) {
        const int pbase = nh * 8 + wn * 2;
        uint4 bh0 = __ldg(gFhi + (pbase + 0) * 32 + lane);
        uint4 bh1 = __ldg(gFhi + (pbase + 1) * 32 + lane);
        uint4 bl0 = __ldg(gFlo + (pbase + 0) * 32 + lane);
        uint4 bl1 = __ldg(gFlo + (pbase + 1) * 32 + lane);
#pragma unroll
        for (int mt = 0; mt < 4; mt++) {
            uint32_t ahi[4], alo[4];
            const uint32_t aRow = (((uint32_t)(wm * 4 + mt)) << 9) + laneOff;
            LDS128(ahi, sbase + OFF_AHI + aRow);
            LDS128(alo, sbase + OFF_ALO + aRow);
            float acc[4][4];
#pragma unroll
            for (int nt = 0; nt < 4; nt++)
#pragma unroll
                for (int e = 0; e < 4; e++) acc[nt][e] = 0.f;
            MMA_F32(acc[0], ahi, bh0.x, bh0.y);
            MMA_F32(acc[1], ahi, bh0.z, bh0.w);
            MMA_F32(acc[2], ahi, bh1.x, bh1.y);
            MMA_F32(acc[3], ahi, bh1.z, bh1.w);
            MMA_F32(acc[0], alo, bh0.x, bh0.y);
            MMA_F32(acc[1], alo, bh0.z, bh0.w);
            MMA_F32(acc[2], alo, bh1.x, bh1.y);
            MMA_F32(acc[3], alo, bh1.z, bh1.w);
            MMA_F32(acc[0], ahi, bl0.x, bl0.y);
            MMA_F32(acc[1], ahi, bl0.z, bl0.w);
            MMA_F32(acc[2], ahi, bl1.x, bl1.y);
            MMA_F32(acc[3], ahi, bl1.z, bl1.w);

#pragma unroll
            for (int nt = 0; nt < 4; nt++) {
                const int j = nh * 128 + wn * 32 + nt * 8 + cq * 2;
                const float cs0 = smf[OFF_CS / 4 + j],  cs1 = smf[OFF_CS / 4 + j + 1];
                const float gs0 = smf[OFF_GS / 4 + j],  gs1 = smf[OFF_GS / 4 + j + 1];
                const float w20 = smf[OFF_W2S / 4 + j], w21 = smf[OFF_W2S / 4 + j + 1];
#pragma unroll
                for (int q = 0; q < 2; q++) {
                    const int idx = mt * 2 + q;
                    const float2 f2  = *(const float2*)&smf[OFF_FH1 / 4 + lnr[idx] * 258 + j];
                    const float2 q2v = *(const float2*)&smf[OFF_Q1  / 4 + tr[idx]  * 258 + j];
                    const float S0 = acc[nt][q * 2 + 0] + f2.x + q2v.x;
                    const float S1 = acc[nt][q * 2 + 1] + f2.y + q2v.y;
                    const float o0 = fmaf(rstd[idx], S0, fmaf(-mr[idx], gs0, cs0));
                    const float o1 = fmaf(rstd[idx], S1, fmaf(-mr[idx], gs1, cs1));
                    part[idx] = fmaf(gelu_exact(o0), w20, part[idx]);
                    part[idx] = fmaf(gelu_exact(o1), w21, part[idx]);
                }
            }
        }
    }

#pragma unroll
    for (int idx = 0; idx < 8; idx++) {
        const int row = wm * 64 + (idx >> 1) * 16 + (idx & 1) * 8 + g8;
        smf[OFF_RED / 4 + row * 16 + wn * 4 + cq] = part[idx];
    }
    __syncthreads();

    if (tid < GRP * T_HOR) {
        const int lno = tid / T_HOR, to = tid % T_HOR;
        const float4* rr = (const float4*)&smf[OFF_RED / 4 + tid * 16];
        float4 r0 = rr[0], r1 = rr[1], r2 = rr[2], r3 = rr[3];
        float s = ((r0.x + r0.y) + (r0.z + r0.w)) + ((r1.x + r1.y) + (r1.z + r1.w)) +
                  ((r2.x + r2.y) + (r2.z + r2.w)) + ((r3.x + r3.y) + (r3.z + r3.w));
        out[(size_t)(b * T_HOR + to) * N_SZ + (n0 + lno)] = s + b2[0];
    }
}

extern "C" void kernel_launch(void* const* d_in, const int* in_sizes, int n_in,
                              void* d_out, int out_size) {
    const float* final_h    = (const float*)d_in[0];
    const float* future_met = (const float*)d_in[1];
    const float* step_q     = (const float*)d_in[2];
    const float* W_fm       = (const float*)d_in[3];
    const float* b_fm       = (const float*)d_in[4];
    const float* gamma      = (const float*)d_in[5];
    const float* beta       = (const float*)d_in[6];
    const float* W1         = (const float*)d_in[7];
    const float* b1         = (const float*)d_in[8];
    const float* W2         = (const float*)d_in[9];
    const float* b2         = (const float*)d_in[10];
    float* out = (float*)d_out;

    prep_cg<<<1, 256>>>(W1, gamma, beta, b1, W2);
    prep_wfm1<<<16, 256>>>(W_fm, gamma, W1);
    prep_packfm1<<<8, 256>>>();
    prep_qt<<<24, 256>>>(step_q, b_fm, W_fm);
    prep_gm<<<16, 256>>>(W_fm);
    prep_bn<<<NBN, 256>>>(final_h, W_fm);
    prep_q1<<<24, 256>>>(W1, gamma);
    prep_fh1s<<<NBN / FH1_ROWS, 256>>>(final_h, gamma, W1);

    cudaFuncSetAttribute(dhh_main, cudaFuncAttributeMaxDynamicSharedMemorySize, SMEM_TOTAL);
    dhh_main<<<NCTA, TPB, SMEM_TOTAL>>>(future_met, b2, out);
}

// round 13
// speedup vs baseline: 3.6039x; 1.1088x over previous
#include <cuda_runtime.h>
#include <cuda_fp16.h>
#include <math.h>
#include <stdint.h>

#define HIDDEN 256
#define T_HOR  24
#define FMET   16
#define B_SZ   16
#define N_SZ   1000
#define GRP    5
#define TPB    256
#define NCTA   (B_SZ * (N_SZ / GRP))   // 3200
#define NBN    (B_SZ * N_SZ)           // 16000
#define EPS_LN 1e-5f

// ---- main kernel smem (bytes) ----
#define OFF_AHI  0        // fm hi fragments, 8 mtiles x 512 = 4096
#define OFF_ALO  4096     // fm lo fragments, 4096
#define OFF_Q1   8192     // Q1, 24 x 258 x 4 = 24768 -> 32960
#define OFF_FH1  32960    // FH1 rows, 6 x 258 x 4 = 6192 -> 39152
#define OFF_RSTD 39152    // 512
#define OFF_MR   39664    // 512
#define OFF_CS   40176    // 1024
#define OFF_GS   41200    // 1024
#define OFF_W2S  42224    // 1024
#define OFF_RED  43248    // 8192 -> 51440
#define SMEM_TOTAL 51456

#define FH1_ROWS 16

typedef unsigned long long u64;

__device__ __align__(16) uint32_t g_BFMhi[2048];
__device__ __align__(16) uint32_t g_BFMlo[2048];
__device__ float g_Wfm1[16 * 256];
__device__ float g_C[HIDDEN];
__device__ float g_G[HIDDEN];
__device__ float g_W2[HIDDEN];
__device__ float g_Q1[T_HOR * 256];
__device__ float g_FH1[(size_t)NBN * 256];
__device__ float g_qb[T_HOR * 256];
__device__ float g_Sqb[T_HOR];
__device__ float g_nqb[T_HOR];
__device__ float g_QB16[T_HOR * 16];
__device__ float g_sfm[16];
__device__ float g_Gm[16 * 16];
__device__ float g_Sfh[NBN];
__device__ float g_nfh[NBN];
__device__ float g_F16[NBN * 16];
__device__ float g_DOT[NBN * T_HOR];

__device__ __forceinline__ u64 pk2(float lo, float hi) {
    u64 r; asm("mov.b64 %0, {%1, %2};" : "=l"(r) : "f"(lo), "f"(hi)); return r;
}
__device__ __forceinline__ void upk2(u64 v, float &lo, float &hi) {
    asm("mov.b64 {%0, %1}, %2;" : "=f"(lo), "=f"(hi) : "l"(v));
}
__device__ __forceinline__ void ffma2(u64 &d, u64 a, u64 b) {
    asm("fma.rn.f32x2 %0, %1, %2, %0;" : "+l"(d) : "l"(a), "l"(b));
}
__device__ __forceinline__ u64 fadd2(u64 a, u64 b) {
    u64 d; asm("add.rn.f32x2 %0, %1, %2;" : "=l"(d) : "l"(a), "l"(b)); return d;
}
__device__ __forceinline__ uint32_t smem_u32(const void* p) {
    uint32_t a;
    asm("{ .reg .u64 t; cvta.to.shared.u64 t, %1; cvt.u32.u64 %0, t; }" : "=r"(a) : "l"(p));
    return a;
}
#define LDS128(r, addr) \
    asm volatile("ld.shared.v4.b32 {%0,%1,%2,%3}, [%4];" \
        : "=r"((r)[0]), "=r"((r)[1]), "=r"((r)[2]), "=r"((r)[3]) : "r"(addr))
#define MMA_F32(d, a, b0, b1v) \
    asm volatile("mma.sync.aligned.m16n8k16.row.col.f32.f16.f16.f32 " \
        "{%0,%1,%2,%3}, {%4,%5,%6,%7}, {%8,%9}, {%0,%1,%2,%3};" \
        : "+f"((d)[0]), "+f"((d)[1]), "+f"((d)[2]), "+f"((d)[3]) \
        : "r"((a)[0]), "r"((a)[1]), "r"((a)[2]), "r"((a)[3]), \
          "r"(b0), "r"(b1v))

__device__ __forceinline__ float gelu_exact(float x) {
    return 0.5f * x * (1.0f + erff(x * 0.70710678118654752440f));
}

__device__ __forceinline__ float block_sum(float v, float* red, int tid) {
#pragma unroll
    for (int o = 16; o; o >>= 1) v += __shfl_xor_sync(0xffffffffu, v, o);
    if ((tid & 31) == 0) red[tid >> 5] = v;
    __syncthreads();
    float x = 0.f;
    if (tid < 32) {
        x = (tid < 8) ? red[tid] : 0.f;
#pragma unroll
        for (int o = 4; o; o >>= 1) x += __shfl_xor_sync(0xffffffffu, x, o);
    }
    __syncthreads();
    return x;
}

// ================= merged prep kernel 1 =================
// blocks [0,1000): FH1 gemm   [1000,1016): wfm1   [1016,1040): qt
// [1040,1056): gm             1056: cg
__global__ void __launch_bounds__(256)
prep_k1(const float* __restrict__ final_h, const float* __restrict__ gamma,
        const float* __restrict__ W1, const float* __restrict__ W_fm,
        const float* __restrict__ step_q, const float* __restrict__ b_fm,
        const float* __restrict__ beta, const float* __restrict__ b1,
        const float* __restrict__ W2)
{
    __shared__ float s_fhg[FH1_ROWS][260];
    __shared__ float s_buf[256];
    __shared__ float s_red[8];
    const int bid = blockIdx.x;
    const int tid = threadIdx.x;

    if (bid < 1000) {
        // FH1 = (fh * gamma) @ W1, exact fp32, FFMA2
        const int bn0 = bid * FH1_ROWS;
        for (int i = tid; i < FH1_ROWS * 256; i += 256) {
            int r = i >> 8, c = i & 255;
            s_fhg[r][c] = final_h[(size_t)(bn0 + r) * 256 + c] * __ldg(&gamma[c]);
        }
        __syncthreads();
        const int cp = tid & 127;
        const int rh = tid >> 7;
        u64 acc[8];
#pragma unroll
        for (int r = 0; r < 8; r++) acc[r] = 0ull;
        for (int c = 0; c < 256; c += 4) {
            u64 wq[4];
#pragma unroll
            for (int q = 0; q < 4; q++) {
                float2 wv = *(const float2*)&W1[(size_t)(c + q) * 256 + 2 * cp];
                wq[q] = pk2(wv.x, wv.y);
            }
#pragma unroll
            for (int r = 0; r < 8; r++) {
                float4 xv = *(const float4*)&s_fhg[rh * 8 + r][c];
                ffma2(acc[r], pk2(xv.x, xv.x), wq[0]);
                ffma2(acc[r], pk2(xv.y, xv.y), wq[1]);
                ffma2(acc[r], pk2(xv.z, xv.z), wq[2]);
                ffma2(acc[r], pk2(xv.w, xv.w), wq[3]);
            }
        }
#pragma unroll
        for (int r = 0; r < 8; r++) {
            float lo, hi; upk2(acc[r], lo, hi);
            *(float2*)&g_FH1[(size_t)(bn0 + rh * 8 + r) * 256 + 2 * cp] = make_float2(lo, hi);
        }
    } else if (bid < 1016) {
        // Wfm1[f] = (W_fm[f] * gamma) @ W1
        const int f = bid - 1000, n = tid;
        float s = 0.f;
        for (int c = 0; c < 256; c++)
            s = fmaf(W_fm[f * 256 + c] * gamma[c], W1[c * 256 + n], s);
        g_Wfm1[f * 256 + n] = s;
    } else if (bid < 1040) {
        // qt: qb, Sqb, nqb, QB16
        const int t = bid - 1016, c = tid;
        const int w = c >> 5, lane = c & 31;
        float qb = step_q[t * 256 + c] + b_fm[c];
        s_buf[c] = qb;
        g_qb[t * 256 + c] = qb;
        __syncthreads();
        float s = block_sum(qb, s_red, c);
        if (c == 0) g_Sqb[t] = s;
        float s2 = block_sum(qb * qb, s_red, c);
        if (c == 0) g_nqb[t] = s2;
#pragma unroll
        for (int q = 0; q < 2; q++) {
            int f = w * 2 + q;
            float d = 0.f;
#pragma unroll
            for (int i = 0; i < 8; i++)
                d = fmaf(W_fm[f * 256 + lane + 32 * i], s_buf[lane + 32 * i], d);
#pragma unroll
            for (int o = 16; o; o >>= 1) d += __shfl_xor_sync(0xffffffffu, d, o);
            if (lane == 0) g_QB16[t * 16 + f] = d;
        }
    } else if (bid < 1056) {
        // gm: sfm, Gm
        const int f = bid - 1040, c = tid;
        const int w = c >> 5, lane = c & 31;
        float wf = W_fm[f * 256 + c];
        s_buf[c] = wf;
        __syncthreads();
        float s = block_sum(wf, s_red, c);
        if (c == 0) g_sfm[f] = s;
#pragma unroll
        for (int q = 0; q < 2; q++) {
            int g = w * 2 + q;
            float d = 0.f;
#pragma unroll
            for (int i = 0; i < 8; i++)
                d = fmaf(W_fm[g * 256 + lane + 32 * i], s_buf[lane + 32 * i], d);
#pragma unroll
            for (int o = 16; o; o >>= 1) d += __shfl_xor_sync(0xffffffffu, d, o);
            if (lane == 0) g_Gm[f * 16 + g] = d;
        }
    } else {
        // cg
        const int j = tid;
        float P = 0.f, G = 0.f;
        for (int c = 0; c < 256; c++) {
            float w = W1[c * 256 + j];
            P = fmaf(beta[c], w, P);
            G = fmaf(gamma[c], w, G);
        }
        g_C[j]  = P + b1[j];
        g_G[j]  = G;
        g_W2[j] = W2[j];
    }
}

// ================= merged prep kernel 2 =================
// blocks [0,2000): bn stats (warp-per-row)  [2000,2008): packfm1  [2008,2032): q1
__global__ void __launch_bounds__(256)
prep_k2(const float* __restrict__ final_h, const float* __restrict__ W_fm,
        const float* __restrict__ W1, const float* __restrict__ gamma)
{
    const int bid = blockIdx.x;
    const int tid = threadIdx.x;

    if (bid < 2000) {
        const int wid = tid >> 5, lane = tid & 31;
        const int bn = bid * 8 + wid;
        const float4* fhp = (const float4*)&final_h[(size_t)bn * 256 + lane * 8];
        const float4 a0 = fhp[0], a1 = fhp[1];
        float s  = ((a0.x + a0.y) + (a0.z + a0.w)) + ((a1.x + a1.y) + (a1.z + a1.w));
        float s2 = fmaf(a0.x, a0.x, fmaf(a0.y, a0.y, fmaf(a0.z, a0.z, a0.w * a0.w)))
                 + fmaf(a1.x, a1.x, fmaf(a1.y, a1.y, fmaf(a1.z, a1.z, a1.w * a1.w)));
#pragma unroll
        for (int o = 16; o; o >>= 1) {
            s  += __shfl_xor_sync(0xffffffffu, s, o);
            s2 += __shfl_xor_sync(0xffffffffu, s2, o);
        }
        if (lane == 0) { g_Sfh[bn] = s; g_nfh[bn] = s2; }
#pragma unroll
        for (int f = 0; f < 16; f++) {
            const float4* wp = (const float4*)&W_fm[f * 256 + lane * 8];
            float4 w0 = __ldg(wp), w1 = __ldg(wp + 1);
            float d = fmaf(w0.x, a0.x, fmaf(w0.y, a0.y, fmaf(w0.z, a0.z, w0.w * a0.w)))
                    + fmaf(w1.x, a1.x, fmaf(w1.y, a1.y, fmaf(w1.z, a1.z, w1.w * a1.w)));
#pragma unroll
            for (int o = 16; o; o >>= 1) d += __shfl_xor_sync(0xffffffffu, d, o);
            if (lane == 0) g_F16[bn * 16 + f] = d;
        }
#pragma unroll
        for (int t = 0; t < T_HOR; t++) {
            const float4* qp = (const float4*)&g_qb[t * 256 + lane * 8];
            float4 q0 = qp[0], q1v = qp[1];
            float d = fmaf(q0.x, a0.x, fmaf(q0.y, a0.y, fmaf(q0.z, a0.z, q0.w * a0.w)))
                    + fmaf(q1v.x, a1.x, fmaf(q1v.y, a1.y, fmaf(q1v.z, a1.z, q1v.w * a1.w)));
#pragma unroll
            for (int o = 16; o; o >>= 1) d += __shfl_xor_sync(0xffffffffu, d, o);
            if (lane == 0) g_DOT[bn * T_HOR + t] = d;
        }
    } else if (bid < 2008) {
        // packfm1
        const int k0 = (bid - 2000) * 2;
        const int n  = tid;
        float v0 = g_Wfm1[k0 * 256 + n];
        float v1 = g_Wfm1[(k0 + 1) * 256 + n];
        __half h0 = __float2half_rn(v0), h1 = __float2half_rn(v1);
        __half l0 = __float2half_rn(v0 - __half2float(h0));
        __half l1 = __float2half_rn(v1 - __half2float(h1));
        const int kk = k0 & 15;
        const int ntile = n >> 3;
        const int lane  = ((n & 7) << 2) | ((kk & 7) >> 1);
        const int reg   = (kk >> 3) & 1;
        const int idx = (ntile >> 1) * 128 + lane * 4 + (ntile & 1) * 2 + reg;
        __half2 hp = __halves2half2(h0, h1);
        __half2 lp = __halves2half2(l0, l1);
        g_BFMhi[idx] = *(uint32_t*)&hp;
        g_BFMlo[idx] = *(uint32_t*)&lp;
    } else {
        // q1
        const int t = bid - 2008, n = tid;
        float s = 0.f;
        for (int c = 0; c < 256; c++)
            s = fmaf(g_qb[t * 256 + c] * gamma[c], W1[c * 256 + n], s);
        g_Q1[t * 256 + n] = s;
    }
}

// ================= main kernel =================
__global__ void __launch_bounds__(TPB, 2)
dhh_main(const float* __restrict__ future_met,
         const float* __restrict__ b2,
         float* __restrict__ out)
{
    extern __shared__ __align__(1024) char smem[];
    float* smf = (float*)smem;
    const uint32_t sbase = smem_u32(smem);
    const int tid  = threadIdx.x;
    const int w    = tid >> 5;
    const int lane = tid & 31;
    const int m    = tid & 127, half = tid >> 7;
    int ln = m / 24; if (ln > 4) ln = 4;
    const int t = m % 24;

    const int b  = blockIdx.x / (N_SZ / GRP);
    const int n0 = (blockIdx.x % (N_SZ / GRP)) * GRP;
    const int bn = b * N_SZ + n0 + ln;

    // ---- fm fragments + algebraic LN stats (half 0 only; fmv dies here) ----
    if (half == 0) {
        float fmv[16];
        {
            const float4* fmp = (const float4*)&future_met[
                ((size_t)(b * T_HOR + t) * N_SZ + (n0 + ln)) * FMET];
            float4 x0 = fmp[0], x1 = fmp[1], x2 = fmp[2], x3 = fmp[3];
            fmv[0]=x0.x; fmv[1]=x0.y; fmv[2]=x0.z;  fmv[3]=x0.w;
            fmv[4]=x1.x; fmv[5]=x1.y; fmv[6]=x1.z;  fmv[7]=x1.w;
            fmv[8]=x2.x; fmv[9]=x2.y; fmv[10]=x2.z; fmv[11]=x2.w;
            fmv[12]=x3.x; fmv[13]=x3.y; fmv[14]=x3.z; fmv[15]=x3.w;
        }
        const uint32_t mbase  = (uint32_t)(m >> 4);
        const uint32_t lane_m = (uint32_t)(m & 7) << 2;
        const uint32_t reg_m  = ((m & 15) >= 8) ? 1u : 0u;
#pragma unroll
        for (int j = 0; j < 8; j++) {
            float v0 = fmv[2 * j], v1 = fmv[2 * j + 1];
            __half h0 = __float2half_rn(v0), h1 = __float2half_rn(v1);
            __half l0 = __float2half_rn(v0 - __half2float(h0));
            __half l1 = __float2half_rn(v1 - __half2float(h1));
            __half2 hp = __halves2half2(h0, h1);
            __half2 lp = __halves2half2(l0, l1);
            const uint32_t kk  = (uint32_t)(2 * j);
            const uint32_t lnA = lane_m | ((kk & 7) >> 1);
            const uint32_t reg = ((kk & 8) ? 2u : 0u) | reg_m;
            uint32_t off = (mbase << 9) + (lnA << 4) + (reg << 2);
            off ^= (off >> 2) & 0x60;
            *(uint32_t*)(smem + OFF_AHI + off) = *(uint32_t*)&hp;
            *(uint32_t*)(smem + OFF_ALO + off) = *(uint32_t*)&lp;
        }
        float mean256 = __ldg(&g_Sfh[bn]) + __ldg(&g_Sqb[t]);
        float ss = __ldg(&g_nfh[bn]) + __ldg(&g_nqb[t]) +
                   2.0f * __ldg(&g_DOT[bn * T_HOR + t]);
        float cross = 0.f, mf = 0.f;
#pragma unroll
        for (int f = 0; f < 16; f++) {
            mf    = fmaf(fmv[f], __ldg(&g_sfm[f]), mf);
            cross = fmaf(fmv[f], __ldg(&g_F16[bn * 16 + f]) + __ldg(&g_QB16[t * 16 + f]), cross);
        }
        mean256 += mf;
        ss += 2.0f * cross;
        float quad = 0.f;
#pragma unroll
        for (int f = 0; f < 16; f++) {
            float rd = 0.f;
#pragma unroll
            for (int g = 0; g < 16; g++)
                rd = fmaf(__ldg(&g_Gm[f * 16 + g]), fmv[g], rd);
            quad = fmaf(fmv[f], rd, quad);
        }
        ss += quad;
        const float mu   = mean256 * (1.0f / HIDDEN);
        const float var  = ss * (1.0f / HIDDEN) - mu * mu;
        const float rstd = rsqrtf(var + EPS_LN);
        smf[OFF_RSTD / 4 + m] = rstd;
        smf[OFF_MR   / 4 + m] = mu * rstd;
    }

    // ---- staging: Q1 (24 rows), FH1 (6 rows clamped), constants ----
#pragma unroll 4
    for (int tt = 0; tt < T_HOR; tt++)
        smf[OFF_Q1 / 4 + tt * 258 + tid] = __ldg(&g_Q1[tt * 256 + tid]);
#pragma unroll
    for (int lni = 0; lni < 6; lni++) {
        int src = lni < 4 ? lni : 4;
        smf[OFF_FH1 / 4 + lni * 258 + tid] =
            __ldg(&g_FH1[(size_t)(b * N_SZ + n0 + src) * 256 + tid]);
    }
    smf[OFF_CS  / 4 + tid] = g_C[tid];
    smf[OFF_GS  / 4 + tid] = g_G[tid];
    smf[OFF_W2S / 4 + tid] = g_W2[tid];
    __syncthreads();

    // ---- 1-kstep GEMM (3-term) + packed fused epilogue ----
    const int wm = w & 1, wn = w >> 1;
    const int g8 = lane >> 2, cq = lane & 3;
    const uint32_t laneOff = ((uint32_t)lane << 4) ^ (((uint32_t)lane & 0x18) << 2);
    const uint4* gFhi = (const uint4*)g_BFMhi;
    const uint4* gFlo = (const uint4*)g_BFMlo;
    u64 part2[8];
#pragma unroll
    for (int idx = 0; idx < 8; idx++) part2[idx] = 0ull;

    float rstd[8], mrn[8];
    int fhoff[8], q1off[8];
#pragma unroll
    for (int idx = 0; idx < 8; idx++) {
        const int row = wm * 64 + (idx >> 1) * 16 + (idx & 1) * 8 + g8;
        rstd[idx] = smf[OFF_RSTD / 4 + row];
        mrn[idx]  = -smf[OFF_MR  / 4 + row];
        const int lnr = row / 24;
        fhoff[idx] = OFF_FH1 / 4 + lnr * 258;
        q1off[idx] = OFF_Q1  / 4 + (row - lnr * 24) * 258;
    }

#pragma unroll
    for (int nh = 0; nh < 2; nh++) {
        u64 cs2[4], gs2[4], w22[4];
#pragma unroll
        for (int nt = 0; nt < 4; nt++) {
            const int j = nh * 128 + wn * 32 + nt * 8 + cq * 2;
            cs2[nt] = *(const u64*)&smf[OFF_CS  / 4 + j];
            gs2[nt] = *(const u64*)&smf[OFF_GS  / 4 + j];
            w22[nt] = *(const u64*)&smf[OFF_W2S / 4 + j];
        }
        const int pbase = nh * 8 + wn * 2;
        uint4 bh0 = __ldg(gFhi + (pbase + 0) * 32 + lane);
        uint4 bh1 = __ldg(gFhi + (pbase + 1) * 32 + lane);
        uint4 bl0 = __ldg(gFlo + (pbase + 0) * 32 + lane);
        uint4 bl1 = __ldg(gFlo + (pbase + 1) * 32 + lane);
#pragma unroll
        for (int mt = 0; mt < 4; mt++) {
            uint32_t ahi[4], alo[4];
            const uint32_t aRow = (((uint32_t)(wm * 4 + mt)) << 9) + laneOff;
            LDS128(ahi, sbase + OFF_AHI + aRow);
            LDS128(alo, sbase + OFF_ALO + aRow);
            float acc[4][4];
#pragma unroll
            for (int nt = 0; nt < 4; nt++)
#pragma unroll
                for (int e = 0; e < 4; e++) acc[nt][e] = 0.f;
            MMA_F32(acc[0], ahi, bh0.x, bh0.y);
            MMA_F32(acc[1], ahi, bh0.z, bh0.w);
            MMA_F32(acc[2], ahi, bh1.x, bh1.y);
            MMA_F32(acc[3], ahi, bh1.z, bh1.w);
            MMA_F32(acc[0], alo, bh0.x, bh0.y);
            MMA_F32(acc[1], alo, bh0.z, bh0.w);
            MMA_F32(acc[2], alo, bh1.x, bh1.y);
            MMA_F32(acc[3], alo, bh1.z, bh1.w);
            MMA_F32(acc[0], ahi, bl0.x, bl0.y);
            MMA_F32(acc[1], ahi, bl0.z, bl0.w);
            MMA_F32(acc[2], ahi, bl1.x, bl1.y);
            MMA_F32(acc[3], ahi, bl1.z, bl1.w);

#pragma unroll
            for (int nt = 0; nt < 4; nt++) {
                const int j = nh * 128 + wn * 32 + nt * 8 + cq * 2;
#pragma unroll
                for (int q = 0; q < 2; q++) {
                    const int idx = mt * 2 + q;
                    u64 fq = fadd2(*(const u64*)&smf[fhoff[idx] + j],
                                   *(const u64*)&smf[q1off[idx] + j]);
                    u64 S2 = fadd2(pk2(acc[nt][q * 2], acc[nt][q * 2 + 1]), fq);
                    u64 o2 = cs2[nt];
                    ffma2(o2, pk2(mrn[idx], mrn[idx]), gs2[nt]);
                    ffma2(o2, S2, pk2(rstd[idx], rstd[idx]));
                    float o0, o1; upk2(o2, o0, o1);
                    ffma2(part2[idx], pk2(gelu_exact(o0), gelu_exact(o1)), w22[nt]);
                }
            }
        }
    }

#pragma unroll
    for (int idx = 0; idx < 8; idx++) {
        const int row = wm * 64 + (idx >> 1) * 16 + (idx & 1) * 8 + g8;
        float plo, phi; upk2(part2[idx], plo, phi);
        smf[OFF_RED / 4 + row * 16 + wn * 4 + cq] = plo + phi;
    }
    __syncthreads();

    if (tid < GRP * T_HOR) {
        const int lno = tid / T_HOR, to = tid % T_HOR;
        const float4* rr = (const float4*)&smf[OFF_RED / 4 + tid * 16];
        float4 r0 = rr[0], r1 = rr[1], r2 = rr[2], r3 = rr[3];
        float s = ((r0.x + r0.y) + (r0.z + r0.w)) + ((r1.x + r1.y) + (r1.z + r1.w)) +
                  ((r2.x + r2.y) + (r2.z + r2.w)) + ((r3.x + r3.y) + (r3.z + r3.w));
        out[(size_t)(b * T_HOR + to) * N_SZ + (n0 + lno)] = s + b2[0];
    }
}

extern "C" void kernel_launch(void* const* d_in, const int* in_sizes, int n_in,
                              void* d_out, int out_size) {
    const float* final_h    = (const float*)d_in[0];
    const float* future_met = (const float*)d_in[1];
    const float* step_q     = (const float*)d_in[2];
    const float* W_fm       = (const float*)d_in[3];
    const float* b_fm       = (const float*)d_in[4];
    const float* gamma      = (const float*)d_in[5];
    const float* beta       = (const float*)d_in[6];
    const float* W1         = (const float*)d_in[7];
    const float* b1         = (const float*)d_in[8];
    const float* W2         = (const float*)d_in[9];
    const float* b2         = (const float*)d_in[10];
    float* out = (float*)d_out;

    prep_k1<<<1057, 256>>>(final_h, gamma, W1, W_fm, step_q, b_fm, beta, b1, W2);
    prep_k2<<<2032, 256>>>(final_h, W_fm, W1, gamma);

    cudaFuncSetAttribute(dhh_main, cudaFuncAttributeMaxDynamicSharedMemorySize, SMEM_TOTAL);
    dhh_main<<<NCTA, TPB, SMEM_TOTAL>>>(future_met, b2, out);
}

// round 14
// speedup vs baseline: 4.1041x; 1.1388x over previous
#include <cuda_runtime.h>
#include <cuda_fp16.h>
#include <math.h>
#include <stdint.h>

#define HIDDEN 256
#define T_HOR  24
#define FMET   16
#define B_SZ   16
#define N_SZ   1000
#define GRP    5
#define TPB    256
#define NCTA   (B_SZ * (N_SZ / GRP))   // 3200
#define NBN    (B_SZ * N_SZ)           // 16000
#define EPS_LN 1e-5f

// ---- main kernel smem (bytes) ----
#define OFF_AHI  0
#define OFF_ALO  4096
#define OFF_Q1   8192
#define OFF_FH1  32960
#define OFF_RSTD 39152
#define OFF_MR   39664
#define OFF_CS   40176
#define OFF_GS   41200
#define OFF_W2S  42224
#define OFF_RED  43248
#define SMEM_TOTAL 51456

typedef unsigned long long u64;

__device__ __align__(16) uint32_t g_BW1hi[16 * 2048];   // W1 hi fragment pack
__device__ __align__(16) uint32_t g_BW1lo[16 * 2048];   // W1 lo fragment pack
__device__ __align__(16) uint32_t g_BFMhi[2048];
__device__ __align__(16) uint32_t g_BFMlo[2048];
__device__ float g_Wfm1[16 * 256];
__device__ float g_C[HIDDEN];
__device__ float g_G[HIDDEN];
__device__ float g_W2[HIDDEN];
__device__ float g_Q1[T_HOR * 256];
__device__ float g_FH1[(size_t)NBN * 256];
__device__ float g_qb[T_HOR * 256];
__device__ float g_Sqb[T_HOR];
__device__ float g_nqb[T_HOR];
__device__ float g_QB16[T_HOR * 16];
__device__ float g_sfm[16];
__device__ float g_Gm[16 * 16];
__device__ float g_Sfh[NBN];
__device__ float g_nfh[NBN];
__device__ float g_F16[NBN * 16];
__device__ float g_DOT[NBN * T_HOR];

__device__ __forceinline__ u64 pk2(float lo, float hi) {
    u64 r; asm("mov.b64 %0, {%1, %2};" : "=l"(r) : "f"(lo), "f"(hi)); return r;
}
__device__ __forceinline__ void upk2(u64 v, float &lo, float &hi) {
    asm("mov.b64 {%0, %1}, %2;" : "=f"(lo), "=f"(hi) : "l"(v));
}
__device__ __forceinline__ void ffma2(u64 &d, u64 a, u64 b) {
    asm("fma.rn.f32x2 %0, %1, %2, %0;" : "+l"(d) : "l"(a), "l"(b));
}
__device__ __forceinline__ u64 fadd2(u64 a, u64 b) {
    u64 d; asm("add.rn.f32x2 %0, %1, %2;" : "=l"(d) : "l"(a), "l"(b)); return d;
}
__device__ __forceinline__ uint32_t smem_u32(const void* p) {
    uint32_t a;
    asm("{ .reg .u64 t; cvta.to.shared.u64 t, %1; cvt.u32.u64 %0, t; }" : "=r"(a) : "l"(p));
    return a;
}
#define LDS128(r, addr) \
    asm volatile("ld.shared.v4.b32 {%0,%1,%2,%3}, [%4];" \
        : "=r"((r)[0]), "=r"((r)[1]), "=r"((r)[2]), "=r"((r)[3]) : "r"(addr))
#define MMA_F32(d, a, b0, b1v) \
    asm volatile("mma.sync.aligned.m16n8k16.row.col.f32.f16.f16.f32 " \
        "{%0,%1,%2,%3}, {%4,%5,%6,%7}, {%8,%9}, {%0,%1,%2,%3};" \
        : "+f"((d)[0]), "+f"((d)[1]), "+f"((d)[2]), "+f"((d)[3]) \
        : "r"((a)[0]), "r"((a)[1]), "r"((a)[2]), "r"((a)[3]), \
          "r"(b0), "r"(b1v))

__device__ __forceinline__ float gelu_exact(float x) {
    return 0.5f * x * (1.0f + erff(x * 0.70710678118654752440f));
}

__device__ __forceinline__ float block_sum(float v, float* red, int tid) {
#pragma unroll
    for (int o = 16; o; o >>= 1) v += __shfl_xor_sync(0xffffffffu, v, o);
    if ((tid & 31) == 0) red[tid >> 5] = v;
    __syncthreads();
    float x = 0.f;
    if (tid < 32) {
        x = (tid < 8) ? red[tid] : 0.f;
#pragma unroll
        for (int o = 4; o; o >>= 1) x += __shfl_xor_sync(0xffffffffu, x, o);
    }
    __syncthreads();
    return x;
}

// ================= prep kernel 1 =================
// [0,128): pack W1 hi/lo   [128,144): wfm1   [144,168): qt
// [168,184): gm            184: cg
__global__ void __launch_bounds__(256)
prep_k1(const float* __restrict__ final_h, const float* __restrict__ gamma,
        const float* __restrict__ W1, const float* __restrict__ W_fm,
        const float* __restrict__ step_q, const float* __restrict__ b_fm,
        const float* __restrict__ beta, const float* __restrict__ b1,
        const float* __restrict__ W2)
{
    __shared__ float s_buf[256];
    __shared__ float s_red[8];
    const int bid = blockIdx.x;
    const int tid = threadIdx.x;

    if (bid < 128) {
        const int k0 = bid * 2;
        const int n  = tid;
        float v0 = W1[k0 * 256 + n];
        float v1 = W1[(k0 + 1) * 256 + n];
        __half h0 = __float2half_rn(v0), h1 = __float2half_rn(v1);
        __half l0 = __float2half_rn(v0 - __half2float(h0));
        __half l1 = __float2half_rn(v1 - __half2float(h1));
        const int ks = k0 >> 4, kk = k0 & 15;
        const int ntile = n >> 3;
        const int lane  = ((n & 7) << 2) | ((kk & 7) >> 1);
        const int reg   = (kk >> 3) & 1;
        const int idx = ks * 2048 + (ntile >> 1) * 128 + lane * 4 + (ntile & 1) * 2 + reg;
        __half2 hp = __halves2half2(h0, h1);
        __half2 lp = __halves2half2(l0, l1);
        g_BW1hi[idx] = *(uint32_t*)&hp;
        g_BW1lo[idx] = *(uint32_t*)&lp;
    } else if (bid < 144) {
        const int f = bid - 128, n = tid;
        float s = 0.f;
        for (int c = 0; c < 256; c++)
            s = fmaf(W_fm[f * 256 + c] * gamma[c], W1[c * 256 + n], s);
        g_Wfm1[f * 256 + n] = s;
    } else if (bid < 168) {
        const int t = bid - 144, c = tid;
        const int w = c >> 5, lane = c & 31;
        float qb = step_q[t * 256 + c] + b_fm[c];
        s_buf[c] = qb;
        g_qb[t * 256 + c] = qb;
        __syncthreads();
        float s = block_sum(qb, s_red, c);
        if (c == 0) g_Sqb[t] = s;
        float s2 = block_sum(qb * qb, s_red, c);
        if (c == 0) g_nqb[t] = s2;
#pragma unroll
        for (int q = 0; q < 2; q++) {
            int f = w * 2 + q;
            float d = 0.f;
#pragma unroll
            for (int i = 0; i < 8; i++)
                d = fmaf(W_fm[f * 256 + lane + 32 * i], s_buf[lane + 32 * i], d);
#pragma unroll
            for (int o = 16; o; o >>= 1) d += __shfl_xor_sync(0xffffffffu, d, o);
            if (lane == 0) g_QB16[t * 16 + f] = d;
        }
    } else if (bid < 184) {
        const int f = bid - 168, c = tid;
        const int w = c >> 5, lane = c & 31;
        float wf = W_fm[f * 256 + c];
        s_buf[c] = wf;
        __syncthreads();
        float s = block_sum(wf, s_red, c);
        if (c == 0) g_sfm[f] = s;
#pragma unroll
        for (int q = 0; q < 2; q++) {
            int g = w * 2 + q;
            float d = 0.f;
#pragma unroll
            for (int i = 0; i < 8; i++)
                d = fmaf(W_fm[g * 256 + lane + 32 * i], s_buf[lane + 32 * i], d);
#pragma unroll
            for (int o = 16; o; o >>= 1) d += __shfl_xor_sync(0xffffffffu, d, o);
            if (lane == 0) g_Gm[f * 16 + g] = d;
        }
    } else {
        const int j = tid;
        float P = 0.f, G = 0.f;
        for (int c = 0; c < 256; c++) {
            float w = W1[c * 256 + j];
            P = fmaf(beta[c], w, P);
            G = fmaf(gamma[c], w, G);
        }
        g_C[j]  = P + b1[j];
        g_G[j]  = G;
        g_W2[j] = W2[j];
    }
}

// ================= prep kernel 2 =================
// [0,2000): bn stats  [2000,2008): packfm1  [2008,2032): q1
// [2032,2532): FH1 = (fh*gamma)@W1 via MMA, 32 rows/CTA
#define FA_HI 0
#define FA_LO 16384
__global__ void __launch_bounds__(256)
prep_k2(const float* __restrict__ final_h, const float* __restrict__ W_fm,
        const float* __restrict__ W1, const float* __restrict__ gamma)
{
    __shared__ __align__(1024) char s_frag[32768];
    const int bid = blockIdx.x;
    const int tid = threadIdx.x;

    if (bid < 2000) {
        const int wid = tid >> 5, lane = tid & 31;
        const int bn = bid * 8 + wid;
        const float4* fhp = (const float4*)&final_h[(size_t)bn * 256 + lane * 8];
        const float4 a0 = fhp[0], a1 = fhp[1];
        float s  = ((a0.x + a0.y) + (a0.z + a0.w)) + ((a1.x + a1.y) + (a1.z + a1.w));
        float s2 = fmaf(a0.x, a0.x, fmaf(a0.y, a0.y, fmaf(a0.z, a0.z, a0.w * a0.w)))
                 + fmaf(a1.x, a1.x, fmaf(a1.y, a1.y, fmaf(a1.z, a1.z, a1.w * a1.w)));
#pragma unroll
        for (int o = 16; o; o >>= 1) {
            s  += __shfl_xor_sync(0xffffffffu, s, o);
            s2 += __shfl_xor_sync(0xffffffffu, s2, o);
        }
        if (lane == 0) { g_Sfh[bn] = s; g_nfh[bn] = s2; }
#pragma unroll
        for (int f = 0; f < 16; f++) {
            const float4* wp = (const float4*)&W_fm[f * 256 + lane * 8];
            float4 w0 = __ldg(wp), w1 = __ldg(wp + 1);
            float d = fmaf(w0.x, a0.x, fmaf(w0.y, a0.y, fmaf(w0.z, a0.z, w0.w * a0.w)))
                    + fmaf(w1.x, a1.x, fmaf(w1.y, a1.y, fmaf(w1.z, a1.z, w1.w * a1.w)));
#pragma unroll
            for (int o = 16; o; o >>= 1) d += __shfl_xor_sync(0xffffffffu, d, o);
            if (lane == 0) g_F16[bn * 16 + f] = d;
        }
#pragma unroll
        for (int t = 0; t < T_HOR; t++) {
            const float4* qp = (const float4*)&g_qb[t * 256 + lane * 8];
            float4 q0 = qp[0], q1v = qp[1];
            float d = fmaf(q0.x, a0.x, fmaf(q0.y, a0.y, fmaf(q0.z, a0.z, q0.w * a0.w)))
                    + fmaf(q1v.x, a1.x, fmaf(q1v.y, a1.y, fmaf(q1v.z, a1.z, q1v.w * a1.w)));
#pragma unroll
            for (int o = 16; o; o >>= 1) d += __shfl_xor_sync(0xffffffffu, d, o);
            if (lane == 0) g_DOT[bn * T_HOR + t] = d;
        }
    } else if (bid < 2008) {
        const int k0 = (bid - 2000) * 2;
        const int n  = tid;
        float v0 = g_Wfm1[k0 * 256 + n];
        float v1 = g_Wfm1[(k0 + 1) * 256 + n];
        __half h0 = __float2half_rn(v0), h1 = __float2half_rn(v1);
        __half l0 = __float2half_rn(v0 - __half2float(h0));
        __half l1 = __float2half_rn(v1 - __half2float(h1));
        const int kk = k0 & 15;
        const int ntile = n >> 3;
        const int lane  = ((n & 7) << 2) | ((kk & 7) >> 1);
        const int reg   = (kk >> 3) & 1;
        const int idx = (ntile >> 1) * 128 + lane * 4 + (ntile & 1) * 2 + reg;
        __half2 hp = __halves2half2(h0, h1);
        __half2 lp = __halves2half2(l0, l1);
        g_BFMhi[idx] = *(uint32_t*)&hp;
        g_BFMlo[idx] = *(uint32_t*)&lp;
    } else if (bid < 2032) {
        const int t = bid - 2008, n = tid;
        float s = 0.f;
        for (int c = 0; c < 256; c++)
            s = fmaf(g_qb[t * 256 + c] * gamma[c], W1[c * 256 + n], s);
        g_Q1[t * 256 + n] = s;
    } else {
        // ---- FH1 MMA: 32 rows per CTA, K=256 (16 ksteps), N=256 (4 warps x 64) ----
        const uint32_t sbase = smem_u32(s_frag);
        const int bn0 = (bid - 2032) * 32;
        // stage fh*gamma hi/lo fragments
        for (int i = tid; i < 32 * 128; i += 256) {
            const int r  = i >> 7;
            const int cp = i & 127;
            const int c  = 2 * cp;
            float2 fh2 = *(const float2*)&final_h[(size_t)(bn0 + r) * 256 + c];
            float v0 = fh2.x * __ldg(&gamma[c]);
            float v1 = fh2.y * __ldg(&gamma[c + 1]);
            __half h0 = __float2half_rn(v0), h1 = __float2half_rn(v1);
            __half l0 = __float2half_rn(v0 - __half2float(h0));
            __half l1 = __float2half_rn(v1 - __half2float(h1));
            __half2 hp = __halves2half2(h0, h1);
            __half2 lp = __halves2half2(l0, l1);
            const uint32_t mtile  = (uint32_t)(r >> 4);
            const uint32_t mm     = (uint32_t)(r & 15);
            const uint32_t kk     = (uint32_t)(c & 15);
            const uint32_t lnA    = ((mm & 7) << 2) | ((kk & 7) >> 1);
            const uint32_t reg    = ((kk & 8) ? 2u : 0u) | ((mm >= 8) ? 1u : 0u);
            uint32_t off = ((mtile * 16 + (uint32_t)(c >> 4)) << 9) + (lnA << 4) + (reg << 2);
            off ^= (off >> 2) & 0x60;
            *(uint32_t*)(s_frag + FA_HI + off) = *(uint32_t*)&hp;
            *(uint32_t*)(s_frag + FA_LO + off) = *(uint32_t*)&lp;
        }
        __syncthreads();

        const int w = tid >> 5, lane = tid & 31;
        const int wm = w & 1, wn = w >> 1;          // wm: m-tile, wn: 64-col quarter
        const uint32_t laneOff = ((uint32_t)lane << 4) ^ (((uint32_t)lane & 0x18) << 2);
        const uint4* gBhi = (const uint4*)g_BW1hi;
        const uint4* gBlo = (const uint4*)g_BW1lo;

        float acc[8][4];
#pragma unroll
        for (int nt = 0; nt < 8; nt++)
#pragma unroll
            for (int e = 0; e < 4; e++) acc[nt][e] = 0.f;

        for (int ks = 0; ks < 16; ks++) {
            uint32_t ahi[4], alo[4];
            const uint32_t aRow = (((uint32_t)(wm * 16 + ks)) << 9) + laneOff;
            LDS128(ahi, sbase + FA_HI + aRow);
            LDS128(alo, sbase + FA_LO + aRow);
#pragma unroll
            for (int p = 0; p < 4; p++) {
                uint4 bh = __ldg(gBhi + ks * 512 + (wn * 4 + p) * 32 + lane);
                uint4 bl = __ldg(gBlo + ks * 512 + (wn * 4 + p) * 32 + lane);
                MMA_F32(acc[2 * p],     ahi, bh.x, bh.y);
                MMA_F32(acc[2 * p + 1], ahi, bh.z, bh.w);
                MMA_F32(acc[2 * p],     alo, bh.x, bh.y);
                MMA_F32(acc[2 * p + 1], alo, bh.z, bh.w);
                MMA_F32(acc[2 * p],     ahi, bl.x, bl.y);
                MMA_F32(acc[2 * p + 1], ahi, bl.z, bl.w);
            }
        }
        const int g8 = lane >> 2, cq = lane & 3;
#pragma unroll
        for (int nt = 0; nt < 8; nt++)
#pragma unroll
            for (int q = 0; q < 2; q++) {
                const int row = wm * 16 + q * 8 + g8;
                const int j   = wn * 64 + nt * 8 + cq * 2;
                *(float2*)&g_FH1[(size_t)(bn0 + row) * 256 + j] =
                    make_float2(acc[nt][q * 2], acc[nt][q * 2 + 1]);
            }
    }
}

// ================= main kernel (unchanged from R13) =================
__global__ void __launch_bounds__(TPB, 2)
dhh_main(const float* __restrict__ future_met,
         const float* __restrict__ b2,
         float* __restrict__ out)
{
    extern __shared__ __align__(1024) char smem[];
    float* smf = (float*)smem;
    const uint32_t sbase = smem_u32(smem);
    const int tid  = threadIdx.x;
    const int w    = tid >> 5;
    const int lane = tid & 31;
    const int m    = tid & 127, half = tid >> 7;
    int ln = m / 24; if (ln > 4) ln = 4;
    const int t = m % 24;

    const int b  = blockIdx.x / (N_SZ / GRP);
    const int n0 = (blockIdx.x % (N_SZ / GRP)) * GRP;
    const int bn = b * N_SZ + n0 + ln;

    if (half == 0) {
        float fmv[16];
        {
            const float4* fmp = (const float4*)&future_met[
                ((size_t)(b * T_HOR + t) * N_SZ + (n0 + ln)) * FMET];
            float4 x0 = fmp[0], x1 = fmp[1], x2 = fmp[2], x3 = fmp[3];
            fmv[0]=x0.x; fmv[1]=x0.y; fmv[2]=x0.z;  fmv[3]=x0.w;
            fmv[4]=x1.x; fmv[5]=x1.y; fmv[6]=x1.z;  fmv[7]=x1.w;
            fmv[8]=x2.x; fmv[9]=x2.y; fmv[10]=x2.z; fmv[11]=x2.w;
            fmv[12]=x3.x; fmv[13]=x3.y; fmv[14]=x3.z; fmv[15]=x3.w;
        }
        const uint32_t mbase  = (uint32_t)(m >> 4);
        const uint32_t lane_m = (uint32_t)(m & 7) << 2;
        const uint32_t reg_m  = ((m & 15) >= 8) ? 1u : 0u;
#pragma unroll
        for (int j = 0; j < 8; j++) {
            float v0 = fmv[2 * j], v1 = fmv[2 * j + 1];
            __half h0 = __float2half_rn(v0), h1 = __float2half_rn(v1);
            __half l0 = __float2half_rn(v0 - __half2float(h0));
            __half l1 = __float2half_rn(v1 - __half2float(h1));
            __half2 hp = __halves2half2(h0, h1);
            __half2 lp = __halves2half2(l0, l1);
            const uint32_t kk  = (uint32_t)(2 * j);
            const uint32_t lnA = lane_m | ((kk & 7) >> 1);
            const uint32_t reg = ((kk & 8) ? 2u : 0u) | reg_m;
            uint32_t off = (mbase << 9) + (lnA << 4) + (reg << 2);
            off ^= (off >> 2) & 0x60;
            *(uint32_t*)(smem + OFF_AHI + off) = *(uint32_t*)&hp;
            *(uint32_t*)(smem + OFF_ALO + off) = *(uint32_t*)&lp;
        }
        float mean256 = __ldg(&g_Sfh[bn]) + __ldg(&g_Sqb[t]);
        float ss = __ldg(&g_nfh[bn]) + __ldg(&g_nqb[t]) +
                   2.0f * __ldg(&g_DOT[bn * T_HOR + t]);
        float cross = 0.f, mf = 0.f;
#pragma unroll
        for (int f = 0; f < 16; f++) {
            mf    = fmaf(fmv[f], __ldg(&g_sfm[f]), mf);
            cross = fmaf(fmv[f], __ldg(&g_F16[bn * 16 + f]) + __ldg(&g_QB16[t * 16 + f]), cross);
        }
        mean256 += mf;
        ss += 2.0f * cross;
        float quad = 0.f;
#pragma unroll
        for (int f = 0; f < 16; f++) {
            float rd = 0.f;
#pragma unroll
            for (int g = 0; g < 16; g++)
                rd = fmaf(__ldg(&g_Gm[f * 16 + g]), fmv[g], rd);
            quad = fmaf(fmv[f], rd, quad);
        }
        ss += quad;
        const float mu   = mean256 * (1.0f / HIDDEN);
        const float var  = ss * (1.0f / HIDDEN) - mu * mu;
        const float rstd = rsqrtf(var + EPS_LN);
        smf[OFF_RSTD / 4 + m] = rstd;
        smf[OFF_MR   / 4 + m] = mu * rstd;
    }

#pragma unroll 4
    for (int tt = 0; tt < T_HOR; tt++)
        smf[OFF_Q1 / 4 + tt * 258 + tid] = __ldg(&g_Q1[tt * 256 + tid]);
#pragma unroll
    for (int lni = 0; lni < 6; lni++) {
        int src = lni < 4 ? lni : 4;
        smf[OFF_FH1 / 4 + lni * 258 + tid] =
            __ldg(&g_FH1[(size_t)(b * N_SZ + n0 + src) * 256 + tid]);
    }
    smf[OFF_CS  / 4 + tid] = g_C[tid];
    smf[OFF_GS  / 4 + tid] = g_G[tid];
    smf[OFF_W2S / 4 + tid] = g_W2[tid];
    __syncthreads();

    const int wm = w & 1, wn = w >> 1;
    const int g8 = lane >> 2, cq = lane & 3;
    const uint32_t laneOff = ((uint32_t)lane << 4) ^ (((uint32_t)lane & 0x18) << 2);
    const uint4* gFhi = (const uint4*)g_BFMhi;
    const uint4* gFlo = (const uint4*)g_BFMlo;
    u64 part2[8];
#pragma unroll
    for (int idx = 0; idx < 8; idx++) part2[idx] = 0ull;

    float rstd[8], mrn[8];
    int fhoff[8], q1off[8];
#pragma unroll
    for (int idx = 0; idx < 8; idx++) {
        const int row = wm * 64 + (idx >> 1) * 16 + (idx & 1) * 8 + g8;
        rstd[idx] = smf[OFF_RSTD / 4 + row];
        mrn[idx]  = -smf[OFF_MR  / 4 + row];
        const int lnr = row / 24;
        fhoff[idx] = OFF_FH1 / 4 + lnr * 258;
        q1off[idx] = OFF_Q1  / 4 + (row - lnr * 24) * 258;
    }

#pragma unroll
    for (int nh = 0; nh < 2; nh++) {
        u64 cs2[4], gs2[4], w22[4];
#pragma unroll
        for (int nt = 0; nt < 4; nt++) {
            const int j = nh * 128 + wn * 32 + nt * 8 + cq * 2;
            cs2[nt] = *(const u64*)&smf[OFF_CS  / 4 + j];
            gs2[nt] = *(const u64*)&smf[OFF_GS  / 4 + j];
            w22[nt] = *(const u64*)&smf[OFF_W2S / 4 + j];
        }
        const int pbase = nh * 8 + wn * 2;
        uint4 bh0 = __ldg(gFhi + (pbase + 0) * 32 + lane);
        uint4 bh1 = __ldg(gFhi + (pbase + 1) * 32 + lane);
        uint4 bl0 = __ldg(gFlo + (pbase + 0) * 32 + lane);
        uint4 bl1 = __ldg(gFlo + (pbase + 1) * 32 + lane);
#pragma unroll
        for (int mt = 0; mt < 4; mt++) {
            uint32_t ahi[4], alo[4];
            const uint32_t aRow = (((uint32_t)(wm * 4 + mt)) << 9) + laneOff;
            LDS128(ahi, sbase + OFF_AHI + aRow);
            LDS128(alo, sbase + OFF_ALO + aRow);
            float acc[4][4];
#pragma unroll
            for (int nt = 0; nt < 4; nt++)
#pragma unroll
                for (int e = 0; e < 4; e++) acc[nt][e] = 0.f;
            MMA_F32(acc[0], ahi, bh0.x, bh0.y);
            MMA_F32(acc[1], ahi, bh0.z, bh0.w);
            MMA_F32(acc[2], ahi, bh1.x, bh1.y);
            MMA_F32(acc[3], ahi, bh1.z, bh1.w);
            MMA_F32(acc[0], alo, bh0.x, bh0.y);
            MMA_F32(acc[1], alo, bh0.z, bh0.w);
            MMA_F32(acc[2], alo, bh1.x, bh1.y);
            MMA_F32(acc[3], alo, bh1.z, bh1.w);
            MMA_F32(acc[0], ahi, bl0.x, bl0.y);
            MMA_F32(acc[1], ahi, bl0.z, bl0.w);
            MMA_F32(acc[2], ahi, bl1.x, bl1.y);
            MMA_F32(acc[3], ahi, bl1.z, bl1.w);

#pragma unroll
            for (int nt = 0; nt < 4; nt++) {
                const int j = nh * 128 + wn * 32 + nt * 8 + cq * 2;
#pragma unroll
                for (int q = 0; q < 2; q++) {
                    const int idx = mt * 2 + q;
                    u64 fq = fadd2(*(const u64*)&smf[fhoff[idx] + j],
                                   *(const u64*)&smf[q1off[idx] + j]);
                    u64 S2 = fadd2(pk2(acc[nt][q * 2], acc[nt][q * 2 + 1]), fq);
                    u64 o2 = cs2[nt];
                    ffma2(o2, pk2(mrn[idx], mrn[idx]), gs2[nt]);
                    ffma2(o2, S2, pk2(rstd[idx], rstd[idx]));
                    float o0, o1; upk2(o2, o0, o1);
                    ffma2(part2[idx], pk2(gelu_exact(o0), gelu_exact(o1)), w22[nt]);
                }
            }
        }
    }

#pragma unroll
    for (int idx = 0; idx < 8; idx++) {
        const int row = wm * 64 + (idx >> 1) * 16 + (idx & 1) * 8 + g8;
        float plo, phi; upk2(part2[idx], plo, phi);
        smf[OFF_RED / 4 + row * 16 + wn * 4 + cq] = plo + phi;
    }
    __syncthreads();

    if (tid < GRP * T_HOR) {
        const int lno = tid / T_HOR, to = tid % T_HOR;
        const float4* rr = (const float4*)&smf[OFF_RED / 4 + tid * 16];
        float4 r0 = rr[0], r1 = rr[1], r2 = rr[2], r3 = rr[3];
        float s = ((r0.x + r0.y) + (r0.z + r0.w)) + ((r1.x + r1.y) + (r1.z + r1.w)) +
                  ((r2.x + r2.y) + (r2.z + r2.w)) + ((r3.x + r3.y) + (r3.z + r3.w));
        out[(size_t)(b * T_HOR + to) * N_SZ + (n0 + lno)] = s + b2[0];
    }
}

extern "C" void kernel_launch(void* const* d_in, const int* in_sizes, int n_in,
                              void* d_out, int out_size) {
    const float* final_h    = (const float*)d_in[0];
    const float* future_met = (const float*)d_in[1];
    const float* step_q     = (const float*)d_in[2];
    const float* W_fm       = (const float*)d_in[3];
    const float* b_fm       = (const float*)d_in[4];
    const float* gamma      = (const float*)d_in[5];
    const float* beta       = (const float*)d_in[6];
    const float* W1         = (const float*)d_in[7];
    const float* b1         = (const float*)d_in[8];
    const float* W2         = (const float*)d_in[9];
    const float* b2         = (const float*)d_in[10];
    float* out = (float*)d_out;

    prep_k1<<<185, 256>>>(final_h, gamma, W1, W_fm, step_q, b_fm, beta, b1, W2);
    prep_k2<<<2532, 256>>>(final_h, W_fm, W1, gamma);

    cudaFuncSetAttribute(dhh_main, cudaFuncAttributeMaxDynamicSharedMemorySize, SMEM_TOTAL);
    dhh_main<<<NCTA, TPB, SMEM_TOTAL>>>(future_met, b2, out);
}

// round 15
// speedup vs baseline: 4.6074x; 1.1226x over previous
#include <cuda_runtime.h>
#include <cuda_fp16.h>
#include <math.h>
#include <stdint.h>

#define HIDDEN 256
#define T_HOR  24
#define FMET   16
#define B_SZ   16
#define N_SZ   1000
#define GRP    5
#define TPB    256
#define NCTA   (B_SZ * (N_SZ / GRP))   // 3200
#define NBN    (B_SZ * N_SZ)           // 16000
#define EPS_LN 1e-5f

// ---- main kernel smem (bytes) ----
#define OFF_AHI  0
#define OFF_ALO  4096
#define OFF_Q1   8192
#define OFF_FH1  32960
#define OFF_RSTD 39152
#define OFF_MR   39664
#define OFF_CS   40176
#define OFF_GS   41200
#define OFF_W2S  42224
#define OFF_RED  43248
#define SMEM_TOTAL 51456

typedef unsigned long long u64;

__device__ __align__(16) uint32_t g_BW1hi[16 * 2048];
__device__ __align__(16) uint32_t g_BW1lo[16 * 2048];
__device__ __align__(16) uint32_t g_BFMhi[2048];
__device__ __align__(16) uint32_t g_BFMlo[2048];
__device__ float g_Wfm1p[16 * 8 * 256];
__device__ float g_Cp[8 * 256];
__device__ float g_Gp[8 * 256];
__device__ float g_Q1p[24 * 8 * 256];
__device__ float g_C[HIDDEN];
__device__ float g_G[HIDDEN];
__device__ float g_W2[HIDDEN];
__device__ float g_Q1[T_HOR * 256];
__device__ float g_FH1[(size_t)NBN * 256];
__device__ float g_Sqb[T_HOR];
__device__ float g_nqb[T_HOR];
__device__ float g_QB16[T_HOR * 16];
__device__ float g_sfm[16];
__device__ float g_Gm[16 * 16];
__device__ float g_Sfh[NBN];
__device__ float g_nfh[NBN];
__device__ float g_F16[NBN * 16];
__device__ float g_DOT[NBN * T_HOR];

__device__ __forceinline__ u64 pk2(float lo, float hi) {
    u64 r; asm("mov.b64 %0, {%1, %2};" : "=l"(r) : "f"(lo), "f"(hi)); return r;
}
__device__ __forceinline__ void upk2(u64 v, float &lo, float &hi) {
    asm("mov.b64 {%0, %1}, %2;" : "=f"(lo), "=f"(hi) : "l"(v));
}
__device__ __forceinline__ void ffma2(u64 &d, u64 a, u64 b) {
    asm("fma.rn.f32x2 %0, %1, %2, %0;" : "+l"(d) : "l"(a), "l"(b));
}
__device__ __forceinline__ u64 fadd2(u64 a, u64 b) {
    u64 d; asm("add.rn.f32x2 %0, %1, %2;" : "=l"(d) : "l"(a), "l"(b)); return d;
}
__device__ __forceinline__ uint32_t smem_u32(const void* p) {
    uint32_t a;
    asm("{ .reg .u64 t; cvta.to.shared.u64 t, %1; cvt.u32.u64 %0, t; }" : "=r"(a) : "l"(p));
    return a;
}
#define LDS128(r, addr) \
    asm volatile("ld.shared.v4.b32 {%0,%1,%2,%3}, [%4];" \
        : "=r"((r)[0]), "=r"((r)[1]), "=r"((r)[2]), "=r"((r)[3]) : "r"(addr))
#define MMA_F32(d, a, b0, b1v) \
    asm volatile("mma.sync.aligned.m16n8k16.row.col.f32.f16.f16.f32 " \
        "{%0,%1,%2,%3}, {%4,%5,%6,%7}, {%8,%9}, {%0,%1,%2,%3};" \
        : "+f"((d)[0]), "+f"((d)[1]), "+f"((d)[2]), "+f"((d)[3]) \
        : "r"((a)[0]), "r"((a)[1]), "r"((a)[2]), "r"((a)[3]), \
          "r"(b0), "r"(b1v))

__device__ __forceinline__ float gelu_exact(float x) {
    return 0.5f * x * (1.0f + erff(x * 0.70710678118654752440f));
}

__device__ __forceinline__ float block_sum(float v, float* red, int tid) {
#pragma unroll
    for (int o = 16; o; o >>= 1) v += __shfl_xor_sync(0xffffffffu, v, o);
    if ((tid & 31) == 0) red[tid >> 5] = v;
    __syncthreads();
    float x = 0.f;
    if (tid < 32) {
        x = (tid < 8) ? red[tid] : 0.f;
#pragma unroll
        for (int o = 4; o; o >>= 1) x += __shfl_xor_sync(0xffffffffu, x, o);
    }
    __syncthreads();
    return x;
}

__device__ __forceinline__ float dot8(float4 a0, float4 a1, float4 b0, float4 b1) {
    return fmaf(a0.x, b0.x, fmaf(a0.y, b0.y, fmaf(a0.z, b0.z, fmaf(a0.w, b0.w,
           fmaf(a1.x, b1.x, fmaf(a1.y, b1.y, fmaf(a1.z, b1.z, a1.w * b1.w)))))));
}

// ================= prep kernel 1 =================
// [0,128): W1 pack   [128,256): wfm1 partial   [256,280): qt
// [280,296): gm      [296,304): cg partial     [304,496): q1 partial
// [496,996): bn-stats, 4 bn per warp
__global__ void __launch_bounds__(256)
prep_k1(const float* __restrict__ final_h, const float* __restrict__ gamma,
        const float* __restrict__ W1, const float* __restrict__ W_fm,
        const float* __restrict__ step_q, const float* __restrict__ b_fm,
        const float* __restrict__ beta)
{
    __shared__ float s_buf[256];
    __shared__ float s_red[8];
    const int bid = blockIdx.x;
    const int tid = threadIdx.x;

    if (bid < 128) {
        const int k0 = bid * 2;
        const int n  = tid;
        float v0 = W1[k0 * 256 + n];
        float v1 = W1[(k0 + 1) * 256 + n];
        __half h0 = __float2half_rn(v0), h1 = __float2half_rn(v1);
        __half l0 = __float2half_rn(v0 - __half2float(h0));
        __half l1 = __float2half_rn(v1 - __half2float(h1));
        const int ks = k0 >> 4, kk = k0 & 15;
        const int ntile = n >> 3;
        const int lane  = ((n & 7) << 2) | ((kk & 7) >> 1);
        const int reg   = (kk >> 3) & 1;
        const int idx = ks * 2048 + (ntile >> 1) * 128 + lane * 4 + (ntile & 1) * 2 + reg;
        __half2 hp = __halves2half2(h0, h1);
        __half2 lp = __halves2half2(l0, l1);
        g_BW1hi[idx] = *(uint32_t*)&hp;
        g_BW1lo[idx] = *(uint32_t*)&lp;
    } else if (bid < 256) {
        const int idx = bid - 128;
        const int f = idx >> 3, ch = idx & 7, n = tid;
        float s = 0.f;
#pragma unroll 8
        for (int c = ch * 32; c < ch * 32 + 32; c++)
            s = fmaf(W_fm[f * 256 + c] * gamma[c], W1[c * 256 + n], s);
        g_Wfm1p[(f * 8 + ch) * 256 + n] = s;
    } else if (bid < 280) {
        const int t = bid - 256, c = tid;
        const int w = c >> 5, lane = c & 31;
        float qb = step_q[t * 256 + c] + b_fm[c];
        s_buf[c] = qb;
        __syncthreads();
        float s = block_sum(qb, s_red, c);
        if (c == 0) g_Sqb[t] = s;
        float s2 = block_sum(qb * qb, s_red, c);
        if (c == 0) g_nqb[t] = s2;
#pragma unroll
        for (int q = 0; q < 2; q++) {
            int f = w * 2 + q;
            float d = 0.f;
#pragma unroll
            for (int i = 0; i < 8; i++)
                d = fmaf(W_fm[f * 256 + lane + 32 * i], s_buf[lane + 32 * i], d);
#pragma unroll
            for (int o = 16; o; o >>= 1) d += __shfl_xor_sync(0xffffffffu, d, o);
            if (lane == 0) g_QB16[t * 16 + f] = d;
        }
    } else if (bid < 296) {
        const int f = bid - 280, c = tid;
        const int w = c >> 5, lane = c & 31;
        float wf = W_fm[f * 256 + c];
        s_buf[c] = wf;
        __syncthreads();
        float s = block_sum(wf, s_red, c);
        if (c == 0) g_sfm[f] = s;
#pragma unroll
        for (int q = 0; q < 2; q++) {
            int g = w * 2 + q;
            float d = 0.f;
#pragma unroll
            for (int i = 0; i < 8; i++)
                d = fmaf(W_fm[g * 256 + lane + 32 * i], s_buf[lane + 32 * i], d);
#pragma unroll
            for (int o = 16; o; o >>= 1) d += __shfl_xor_sync(0xffffffffu, d, o);
            if (lane == 0) g_Gm[f * 16 + g] = d;
        }
    } else if (bid < 304) {
        const int ch = bid - 296, j = tid;
        float P = 0.f, G = 0.f;
#pragma unroll 8
        for (int c = ch * 32; c < ch * 32 + 32; c++) {
            float w = W1[c * 256 + j];
            P = fmaf(beta[c], w, P);
            G = fmaf(gamma[c], w, G);
        }
        g_Cp[ch * 256 + j] = P;
        g_Gp[ch * 256 + j] = G;
    } else if (bid < 496) {
        const int idx = bid - 304;
        const int t = idx >> 3, ch = idx & 7, n = tid;
        float s = 0.f;
#pragma unroll 8
        for (int c = ch * 32; c < ch * 32 + 32; c++) {
            float qb = step_q[t * 256 + c] + b_fm[c];
            s = fmaf(qb * gamma[c], W1[c * 256 + n], s);
        }
        g_Q1p[(t * 8 + ch) * 256 + n] = s;
    } else {
        // bn-stats: warp handles 4 consecutive bn rows
        const int wid = tid >> 5, lane = tid & 31;
        const int bn0 = ((bid - 496) * 8 + wid) * 4;
        float4 f0[4], f1[4];
#pragma unroll
        for (int i = 0; i < 4; i++) {
            const float4* p = (const float4*)&final_h[(size_t)(bn0 + i) * 256 + lane * 8];
            f0[i] = p[0]; f1[i] = p[1];
        }
        const float4* bfp = (const float4*)&b_fm[lane * 8];
        float4 bf0 = __ldg(bfp), bf1 = __ldg(bfp + 1);
        // Sfh / nfh
#pragma unroll
        for (int i = 0; i < 4; i++) {
            float s  = ((f0[i].x + f0[i].y) + (f0[i].z + f0[i].w)) +
                       ((f1[i].x + f1[i].y) + (f1[i].z + f1[i].w));
            float s2 = dot8(f0[i], f1[i], f0[i], f1[i]);
#pragma unroll
            for (int o = 16; o; o >>= 1) {
                s  += __shfl_xor_sync(0xffffffffu, s, o);
                s2 += __shfl_xor_sync(0xffffffffu, s2, o);
            }
            if (lane == 0) { g_Sfh[bn0 + i] = s; g_nfh[bn0 + i] = s2; }
        }
        // F16
#pragma unroll
        for (int f = 0; f < 16; f++) {
            const float4* wp = (const float4*)&W_fm[f * 256 + lane * 8];
            float4 w0 = __ldg(wp), w1 = __ldg(wp + 1);
#pragma unroll
            for (int i = 0; i < 4; i++) {
                float d = dot8(w0, w1, f0[i], f1[i]);
#pragma unroll
                for (int o = 16; o; o >>= 1) d += __shfl_xor_sync(0xffffffffu, d, o);
                if (lane == 0) g_F16[(bn0 + i) * 16 + f] = d;
            }
        }
        // DOT (qb computed inline)
#pragma unroll 4
        for (int t = 0; t < T_HOR; t++) {
            const float4* qp = (const float4*)&step_q[t * 256 + lane * 8];
            float4 q0 = __ldg(qp), q1 = __ldg(qp + 1);
            q0.x += bf0.x; q0.y += bf0.y; q0.z += bf0.z; q0.w += bf0.w;
            q1.x += bf1.x; q1.y += bf1.y; q1.z += bf1.z; q1.w += bf1.w;
#pragma unroll
            for (int i = 0; i < 4; i++) {
                float d = dot8(q0, q1, f0[i], f1[i]);
#pragma unroll
                for (int o = 16; o; o >>= 1) d += __shfl_xor_sync(0xffffffffu, d, o);
                if (lane == 0) g_DOT[(bn0 + i) * T_HOR + t] = d;
            }
        }
    }
}

// ================= prep kernel 2 =================
// [0,8): wfm1 reduce + pack   8: cg reduce   [9,33): q1 reduce
// [33,533): FH1 = (fh*gamma)@W1 via MMA, 32 rows/CTA
#define FA_HI 0
#define FA_LO 16384
__global__ void __launch_bounds__(256)
prep_k2(const float* __restrict__ final_h, const float* __restrict__ gamma,
        const float* __restrict__ b1, const float* __restrict__ W2)
{
    __shared__ __align__(1024) char s_frag[32768];
    const int bid = blockIdx.x;
    const int tid = threadIdx.x;

    if (bid < 8) {
        const int k0 = bid * 2;
        const int n  = tid;
        float v0 = 0.f, v1 = 0.f;
#pragma unroll
        for (int ch = 0; ch < 8; ch++) {
            v0 += g_Wfm1p[(k0 * 8 + ch) * 256 + n];
            v1 += g_Wfm1p[((k0 + 1) * 8 + ch) * 256 + n];
        }
        __half h0 = __float2half_rn(v0), h1 = __float2half_rn(v1);
        __half l0 = __float2half_rn(v0 - __half2float(h0));
        __half l1 = __float2half_rn(v1 - __half2float(h1));
        const int kk = k0 & 15;
        const int ntile = n >> 3;
        const int lane  = ((n & 7) << 2) | ((kk & 7) >> 1);
        const int reg   = (kk >> 3) & 1;
        const int idx = (ntile >> 1) * 128 + lane * 4 + (ntile & 1) * 2 + reg;
        __half2 hp = __halves2half2(h0, h1);
        __half2 lp = __halves2half2(l0, l1);
        g_BFMhi[idx] = *(uint32_t*)&hp;
        g_BFMlo[idx] = *(uint32_t*)&lp;
    } else if (bid == 8) {
        const int j = tid;
        float P = 0.f, G = 0.f;
#pragma unroll
        for (int ch = 0; ch < 8; ch++) {
            P += g_Cp[ch * 256 + j];
            G += g_Gp[ch * 256 + j];
        }
        g_C[j]  = P + b1[j];
        g_G[j]  = G;
        g_W2[j] = W2[j];
    } else if (bid < 33) {
        const int t = bid - 9, n = tid;
        float s = 0.f;
#pragma unroll
        for (int ch = 0; ch < 8; ch++)
            s += g_Q1p[(t * 8 + ch) * 256 + n];
        g_Q1[t * 256 + n] = s;
    } else {
        // FH1 MMA: 32 rows per CTA
        const uint32_t sbase = smem_u32(s_frag);
        const int bn0 = (bid - 33) * 32;
        for (int i = tid; i < 32 * 128; i += 256) {
            const int r  = i >> 7;
            const int cp = i & 127;
            const int c  = 2 * cp;
            float2 fh2 = *(const float2*)&final_h[(size_t)(bn0 + r) * 256 + c];
            float v0 = fh2.x * __ldg(&gamma[c]);
            float v1 = fh2.y * __ldg(&gamma[c + 1]);
            __half h0 = __float2half_rn(v0), h1 = __float2half_rn(v1);
            __half l0 = __float2half_rn(v0 - __half2float(h0));
            __half l1 = __float2half_rn(v1 - __half2float(h1));
            __half2 hp = __halves2half2(h0, h1);
            __half2 lp = __halves2half2(l0, l1);
            const uint32_t mtile  = (uint32_t)(r >> 4);
            const uint32_t mm     = (uint32_t)(r & 15);
            const uint32_t kk     = (uint32_t)(c & 15);
            const uint32_t lnA    = ((mm & 7) << 2) | ((kk & 7) >> 1);
            const uint32_t reg    = ((kk & 8) ? 2u : 0u) | ((mm >= 8) ? 1u : 0u);
            uint32_t off = ((mtile * 16 + (uint32_t)(c >> 4)) << 9) + (lnA << 4) + (reg << 2);
            off ^= (off >> 2) & 0x60;
            *(uint32_t*)(s_frag + FA_HI + off) = *(uint32_t*)&hp;
            *(uint32_t*)(s_frag + FA_LO + off) = *(uint32_t*)&lp;
        }
        __syncthreads();

        const int w = tid >> 5, lane = tid & 31;
        const int wm = w & 1, wn = w >> 1;
        const uint32_t laneOff = ((uint32_t)lane << 4) ^ (((uint32_t)lane & 0x18) << 2);
        const uint4* gBhi = (const uint4*)g_BW1hi;
        const uint4* gBlo = (const uint4*)g_BW1lo;

        float acc[8][4];
#pragma unroll
        for (int nt = 0; nt < 8; nt++)
#pragma unroll
            for (int e = 0; e < 4; e++) acc[nt][e] = 0.f;

#pragma unroll 2
        for (int ks = 0; ks < 16; ks++) {
            uint32_t ahi[4], alo[4];
            const uint32_t aRow = (((uint32_t)(wm * 16 + ks)) << 9) + laneOff;
            LDS128(ahi, sbase + FA_HI + aRow);
            LDS128(alo, sbase + FA_LO + aRow);
#pragma unroll
            for (int p = 0; p < 4; p++) {
                uint4 bh = __ldg(gBhi + ks * 512 + (wn * 4 + p) * 32 + lane);
                uint4 bl = __ldg(gBlo + ks * 512 + (wn * 4 + p) * 32 + lane);
                MMA_F32(acc[2 * p],     ahi, bh.x, bh.y);
                MMA_F32(acc[2 * p + 1], ahi, bh.z, bh.w);
                MMA_F32(acc[2 * p],     alo, bh.x, bh.y);
                MMA_F32(acc[2 * p + 1], alo, bh.z, bh.w);
                MMA_F32(acc[2 * p],     ahi, bl.x, bl.y);
                MMA_F32(acc[2 * p + 1], ahi, bl.z, bl.w);
            }
        }
        const int g8 = lane >> 2, cq = lane & 3;
#pragma unroll
        for (int nt = 0; nt < 8; nt++)
#pragma unroll
            for (int q = 0; q < 2; q++) {
                const int row = wm * 16 + q * 8 + g8;
                const int j   = wn * 64 + nt * 8 + cq * 2;
                *(float2*)&g_FH1[(size_t)(bn0 + row) * 256 + j] =
                    make_float2(acc[nt][q * 2], acc[nt][q * 2 + 1]);
            }
    }
}

// ================= main kernel (unchanged from R14) =================
__global__ void __launch_bounds__(TPB, 2)
dhh_main(const float* __restrict__ future_met,
         const float* __restrict__ b2,
         float* __restrict__ out)
{
    extern __shared__ __align__(1024) char smem[];
    float* smf = (float*)smem;
    const uint32_t sbase = smem_u32(smem);
    const int tid  = threadIdx.x;
    const int w    = tid >> 5;
    const int lane = tid & 31;
    const int m    = tid & 127, half = tid >> 7;
    int ln = m / 24; if (ln > 4) ln = 4;
    const int t = m % 24;

    const int b  = blockIdx.x / (N_SZ / GRP);
    const int n0 = (blockIdx.x % (N_SZ / GRP)) * GRP;
    const int bn = b * N_SZ + n0 + ln;

    if (half == 0) {
        float fmv[16];
        {
            const float4* fmp = (const float4*)&future_met[
                ((size_t)(b * T_HOR + t) * N_SZ + (n0 + ln)) * FMET];
            float4 x0 = fmp[0], x1 = fmp[1], x2 = fmp[2], x3 = fmp[3];
            fmv[0]=x0.x; fmv[1]=x0.y; fmv[2]=x0.z;  fmv[3]=x0.w;
            fmv[4]=x1.x; fmv[5]=x1.y; fmv[6]=x1.z;  fmv[7]=x1.w;
            fmv[8]=x2.x; fmv[9]=x2.y; fmv[10]=x2.z; fmv[11]=x2.w;
            fmv[12]=x3.x; fmv[13]=x3.y; fmv[14]=x3.z; fmv[15]=x3.w;
        }
        const uint32_t mbase  = (uint32_t)(m >> 4);
        const uint32_t lane_m = (uint32_t)(m & 7) << 2;
        const uint32_t reg_m  = ((m & 15) >= 8) ? 1u : 0u;
#pragma unroll
        for (int j = 0; j < 8; j++) {
            float v0 = fmv[2 * j], v1 = fmv[2 * j + 1];
            __half h0 = __float2half_rn(v0), h1 = __float2half_rn(v1);
            __half l0 = __float2half_rn(v0 - __half2float(h0));
            __half l1 = __float2half_rn(v1 - __half2float(h1));
            __half2 hp = __halves2half2(h0, h1);
            __half2 lp = __halves2half2(l0, l1);
            const uint32_t kk  = (uint32_t)(2 * j);
            const uint32_t lnA = lane_m | ((kk & 7) >> 1);
            const uint32_t reg = ((kk & 8) ? 2u : 0u) | reg_m;
            uint32_t off = (mbase << 9) + (lnA << 4) + (reg << 2);
            off ^= (off >> 2) & 0x60;
            *(uint32_t*)(smem + OFF_AHI + off) = *(uint32_t*)&hp;
            *(uint32_t*)(smem + OFF_ALO + off) = *(uint32_t*)&lp;
        }
        float mean256 = __ldg(&g_Sfh[bn]) + __ldg(&g_Sqb[t]);
        float ss = __ldg(&g_nfh[bn]) + __ldg(&g_nqb[t]) +
                   2.0f * __ldg(&g_DOT[bn * T_HOR + t]);
        float cross = 0.f, mf = 0.f;
#pragma unroll
        for (int f = 0; f < 16; f++) {
            mf    = fmaf(fmv[f], __ldg(&g_sfm[f]), mf);
            cross = fmaf(fmv[f], __ldg(&g_F16[bn * 16 + f]) + __ldg(&g_QB16[t * 16 + f]), cross);
        }
        mean256 += mf;
        ss += 2.0f * cross;
        float quad = 0.f;
#pragma unroll
        for (int f = 0; f < 16; f++) {
            float rd = 0.f;
#pragma unroll
            for (int g = 0; g < 16; g++)
                rd = fmaf(__ldg(&g_Gm[f * 16 + g]), fmv[g], rd);
            quad = fmaf(fmv[f], rd, quad);
        }
        ss += quad;
        const float mu   = mean256 * (1.0f / HIDDEN);
        const float var  = ss * (1.0f / HIDDEN) - mu * mu;
        const float rstd = rsqrtf(var + EPS_LN);
        smf[OFF_RSTD / 4 + m] = rstd;
        smf[OFF_MR   / 4 + m] = mu * rstd;
    }

#pragma unroll 4
    for (int tt = 0; tt < T_HOR; tt++)
        smf[OFF_Q1 / 4 + tt * 258 + tid] = __ldg(&g_Q1[tt * 256 + tid]);
#pragma unroll
    for (int lni = 0; lni < 6; lni++) {
        int src = lni < 4 ? lni : 4;
        smf[OFF_FH1 / 4 + lni * 258 + tid] =
            __ldg(&g_FH1[(size_t)(b * N_SZ + n0 + src) * 256 + tid]);
    }
    smf[OFF_CS  / 4 + tid] = g_C[tid];
    smf[OFF_GS  / 4 + tid] = g_G[tid];
    smf[OFF_W2S / 4 + tid] = g_W2[tid];
    __syncthreads();

    const int wm = w & 1, wn = w >> 1;
    const int g8 = lane >> 2, cq = lane & 3;
    const uint32_t laneOff = ((uint32_t)lane << 4) ^ (((uint32_t)lane & 0x18) << 2);
    const uint4* gFhi = (const uint4*)g_BFMhi;
    const uint4* gFlo = (const uint4*)g_BFMlo;
    u64 part2[8];
#pragma unroll
    for (int idx = 0; idx < 8; idx++) part2[idx] = 0ull;

    float rstd[8], mrn[8];
    int fhoff[8], q1off[8];
#pragma unroll
    for (int idx = 0; idx < 8; idx++) {
        const int row = wm * 64 + (idx >> 1) * 16 + (idx & 1) * 8 + g8;
        rstd[idx] = smf[OFF_RSTD / 4 + row];
        mrn[idx]  = -smf[OFF_MR  / 4 + row];
        const int lnr = row / 24;
        fhoff[idx] = OFF_FH1 / 4 + lnr * 258;
        q1off[idx] = OFF_Q1  / 4 + (row - lnr * 24) * 258;
    }

#pragma unroll
    for (int nh = 0; nh < 2; nh++) {
        u64 cs2[4], gs2[4], w22[4];
#pragma unroll
        for (int nt = 0; nt < 4; nt++) {
            const int j = nh * 128 + wn * 32 + nt * 8 + cq * 2;
            cs2[nt] = *(const u64*)&smf[OFF_CS  / 4 + j];
            gs2[nt] = *(const u64*)&smf[OFF_GS  / 4 + j];
            w22[nt] = *(const u64*)&smf[OFF_W2S / 4 + j];
        }
        const int pbase = nh * 8 + wn * 2;
        uint4 bh0 = __ldg(gFhi + (pbase + 0) * 32 + lane);
        uint4 bh1 = __ldg(gFhi + (pbase + 1) * 32 + lane);
        uint4 bl0 = __ldg(gFlo + (pbase + 0) * 32 + lane);
        uint4 bl1 = __ldg(gFlo + (pbase + 1) * 32 + lane);
#pragma unroll
        for (int mt = 0; mt < 4; mt++) {
            uint32_t ahi[4], alo[4];
            const uint32_t aRow = (((uint32_t)(wm * 4 + mt)) << 9) + laneOff;
            LDS128(ahi, sbase + OFF_AHI + aRow);
            LDS128(alo, sbase + OFF_ALO + aRow);
            float acc[4][4];
#pragma unroll
            for (int nt = 0; nt < 4; nt++)
#pragma unroll
                for (int e = 0; e < 4; e++) acc[nt][e] = 0.f;
            MMA_F32(acc[0], ahi, bh0.x, bh0.y);
            MMA_F32(acc[1], ahi, bh0.z, bh0.w);
            MMA_F32(acc[2], ahi, bh1.x, bh1.y);
            MMA_F32(acc[3], ahi, bh1.z, bh1.w);
            MMA_F32(acc[0], alo, bh0.x, bh0.y);
            MMA_F32(acc[1], alo, bh0.z, bh0.w);
            MMA_F32(acc[2], alo, bh1.x, bh1.y);
            MMA_F32(acc[3], alo, bh1.z, bh1.w);
            MMA_F32(acc[0], ahi, bl0.x, bl0.y);
            MMA_F32(acc[1], ahi, bl0.z, bl0.w);
            MMA_F32(acc[2], ahi, bl1.x, bl1.y);
            MMA_F32(acc[3], ahi, bl1.z, bl1.w);

#pragma unroll
            for (int nt = 0; nt < 4; nt++) {
                const int j = nh * 128 + wn * 32 + nt * 8 + cq * 2;
#pragma unroll
                for (int q = 0; q < 2; q++) {
                    const int idx = mt * 2 + q;
                    u64 fq = fadd2(*(const u64*)&smf[fhoff[idx] + j],
                                   *(const u64*)&smf[q1off[idx] + j]);
                    u64 S2 = fadd2(pk2(acc[nt][q * 2], acc[nt][q * 2 + 1]), fq);
                    u64 o2 = cs2[nt];
                    ffma2(o2, pk2(mrn[idx], mrn[idx]), gs2[nt]);
                    ffma2(o2, S2, pk2(rstd[idx], rstd[idx]));
                    float o0, o1; upk2(o2, o0, o1);
                    ffma2(part2[idx], pk2(gelu_exact(o0), gelu_exact(o1)), w22[nt]);
                }
            }
        }
    }

#pragma unroll
    for (int idx = 0; idx < 8; idx++) {
        const int row = wm * 64 + (idx >> 1) * 16 + (idx & 1) * 8 + g8;
        float plo, phi; upk2(part2[idx], plo, phi);
        smf[OFF_RED / 4 + row * 16 + wn * 4 + cq] = plo + phi;
    }
    __syncthreads();

    if (tid < GRP * T_HOR) {
        const int lno = tid / T_HOR, to = tid % T_HOR;
        const float4* rr = (const float4*)&smf[OFF_RED / 4 + tid * 16];
        float4 r0 = rr[0], r1 = rr[1], r2 = rr[2], r3 = rr[3];
        float s = ((r0.x + r0.y) + (r0.z + r0.w)) + ((r1.x + r1.y) + (r1.z + r1.w)) +
                  ((r2.x + r2.y) + (r2.z + r2.w)) + ((r3.x + r3.y) + (r3.z + r3.w));
        out[(size_t)(b * T_HOR + to) * N_SZ + (n0 + lno)] = s + b2[0];
    }
}

extern "C" void kernel_launch(void* const* d_in, const int* in_sizes, int n_in,
                              void* d_out, int out_size) {
    const float* final_h    = (const float*)d_in[0];
    const float* future_met = (const float*)d_in[1];
    const float* step_q     = (const float*)d_in[2];
    const float* W_fm       = (const float*)d_in[3];
    const float* b_fm       = (const float*)d_in[4];
    const float* gamma      = (const float*)d_in[5];
    const float* beta       = (const float*)d_in[6];
    const float* W1         = (const float*)d_in[7];
    const float* b1         = (const float*)d_in[8];
    const float* W2         = (const float*)d_in[9];
    const float* b2         = (const float*)d_in[10];
    float* out = (float*)d_out;

    prep_k1<<<996, 256>>>(final_h, gamma, W1, W_fm, step_q, b_fm, beta);
    prep_k2<<<533, 256>>>(final_h, gamma, b1, W2);

    cudaFuncSetAttribute(dhh_main, cudaFuncAttributeMaxDynamicSharedMemorySize, SMEM_TOTAL);
    dhh_main<<<NCTA, TPB, SMEM_TOTAL>>>(future_met, b2, out);
}

// round 16
// speedup vs baseline: 4.9292x; 1.0699x over previous
#include <cuda_runtime.h>
#include <cuda_fp16.h>
#include <math.h>
#include <stdint.h>

#define HIDDEN 256
#define T_HOR  24
#define FMET   16
#define B_SZ   16
#define N_SZ   1000
#define GRP    5
#define TPB    256
#define NCTA   (B_SZ * (N_SZ / GRP))   // 3200
#define NBN    (B_SZ * N_SZ)           // 16000
#define EPS_LN 1e-5f

// ---- main kernel smem (bytes) ----
#define OFF_AHI  0
#define OFF_ALO  4096
#define OFF_Q1   8192
#define OFF_FH1  32960
#define OFF_RSTD 39152
#define OFF_MR   39664
#define OFF_CS   40176
#define OFF_GS   41200
#define OFF_W2S  42224
#define OFF_RED  43248
#define SMEM_TOTAL 51456

typedef unsigned long long u64;

__device__ __align__(16) uint32_t g_BW1hi[16 * 2048];
__device__ __align__(16) uint32_t g_BW1lo[16 * 2048];
__device__ __align__(16) uint32_t g_BFMhi[2048];
__device__ __align__(16) uint32_t g_BFMlo[2048];
__device__ float g_Wfm1p[16 * 8 * 256];
__device__ float g_Cp[8 * 256];
__device__ float g_Gp[8 * 256];
__device__ float g_Q1p[24 * 8 * 256];
__device__ float g_C[HIDDEN];
__device__ float g_G[HIDDEN];
__device__ float g_W2[HIDDEN];
__device__ float g_Q1[T_HOR * 256];
__device__ float g_FH1[(size_t)NBN * 256];
__device__ float g_Sqb[T_HOR];
__device__ float g_nqb[T_HOR];
__device__ float g_QB16[T_HOR * 16];
__device__ float g_sfm[16];
__device__ float g_Gm[16 * 16];
__device__ float g_Sfh[NBN];
__device__ float g_nfh[NBN];
__device__ float g_F16[NBN * 16];
__device__ float g_DOT[NBN * T_HOR];

__device__ __forceinline__ u64 pk2(float lo, float hi) {
    u64 r; asm("mov.b64 %0, {%1, %2};" : "=l"(r) : "f"(lo), "f"(hi)); return r;
}
__device__ __forceinline__ void upk2(u64 v, float &lo, float &hi) {
    asm("mov.b64 {%0, %1}, %2;" : "=f"(lo), "=f"(hi) : "l"(v));
}
__device__ __forceinline__ void ffma2(u64 &d, u64 a, u64 b) {
    asm("fma.rn.f32x2 %0, %1, %2, %0;" : "+l"(d) : "l"(a), "l"(b));
}
__device__ __forceinline__ u64 fadd2(u64 a, u64 b) {
    u64 d; asm("add.rn.f32x2 %0, %1, %2;" : "=l"(d) : "l"(a), "l"(b)); return d;
}
__device__ __forceinline__ u64 fmul2(u64 a, u64 b) {
    u64 d; asm("mul.rn.f32x2 %0, %1, %2;" : "=l"(d) : "l"(a), "l"(b)); return d;
}
__device__ __forceinline__ float frcp_fast(float x) {
    float r; asm("rcp.approx.f32 %0, %1;" : "=f"(r) : "f"(x)); return r;
}
__device__ __forceinline__ float fex2(float x) {
    float r; asm("ex2.approx.f32 %0, %1;" : "=f"(r) : "f"(x)); return r;
}
__device__ __forceinline__ uint32_t smem_u32(const void* p) {
    uint32_t a;
    asm("{ .reg .u64 t; cvta.to.shared.u64 t, %1; cvt.u32.u64 %0, t; }" : "=r"(a) : "l"(p));
    return a;
}
#define LDS128(r, addr) \
    asm volatile("ld.shared.v4.b32 {%0,%1,%2,%3}, [%4];" \
        : "=r"((r)[0]), "=r"((r)[1]), "=r"((r)[2]), "=r"((r)[3]) : "r"(addr))
#define MMA_F32(d, a, b0, b1v) \
    asm volatile("mma.sync.aligned.m16n8k16.row.col.f32.f16.f16.f32 " \
        "{%0,%1,%2,%3}, {%4,%5,%6,%7}, {%8,%9}, {%0,%1,%2,%3};" \
        : "+f"((d)[0]), "+f"((d)[1]), "+f"((d)[2]), "+f"((d)[3]) \
        : "r"((a)[0]), "r"((a)[1]), "r"((a)[2]), "r"((a)[3]), \
          "r"(b0), "r"(b1v))

__device__ __forceinline__ float block_sum(float v, float* red, int tid) {
#pragma unroll
    for (int o = 16; o; o >>= 1) v += __shfl_xor_sync(0xffffffffu, v, o);
    if ((tid & 31) == 0) red[tid >> 5] = v;
    __syncthreads();
    float x = 0.f;
    if (tid < 32) {
        x = (tid < 8) ? red[tid] : 0.f;
#pragma unroll
        for (int o = 4; o; o >>= 1) x += __shfl_xor_sync(0xffffffffu, x, o);
    }
    __syncthreads();
    return x;
}

__device__ __forceinline__ float dot8(float4 a0, float4 a1, float4 b0, float4 b1) {
    return fmaf(a0.x, b0.x, fmaf(a0.y, b0.y, fmaf(a0.z, b0.z, fmaf(a0.w, b0.w,
           fmaf(a1.x, b1.x, fmaf(a1.y, b1.y, fmaf(a1.z, b1.z, a1.w * b1.w)))))));
}

// ================= prep kernel 1 (unchanged from R15) =================
__global__ void __launch_bounds__(256)
prep_k1(const float* __restrict__ final_h, const float* __restrict__ gamma,
        const float* __restrict__ W1, const float* __restrict__ W_fm,
        const float* __restrict__ step_q, const float* __restrict__ b_fm,
        const float* __restrict__ beta)
{
    __shared__ float s_buf[256];
    __shared__ float s_red[8];
    const int bid = blockIdx.x;
    const int tid = threadIdx.x;

    if (bid < 128) {
        const int k0 = bid * 2;
        const int n  = tid;
        float v0 = W1[k0 * 256 + n];
        float v1 = W1[(k0 + 1) * 256 + n];
        __half h0 = __float2half_rn(v0), h1 = __float2half_rn(v1);
        __half l0 = __float2half_rn(v0 - __half2float(h0));
        __half l1 = __float2half_rn(v1 - __half2float(h1));
        const int ks = k0 >> 4, kk = k0 & 15;
        const int ntile = n >> 3;
        const int lane  = ((n & 7) << 2) | ((kk & 7) >> 1);
        const int reg   = (kk >> 3) & 1;
        const int idx = ks * 2048 + (ntile >> 1) * 128 + lane * 4 + (ntile & 1) * 2 + reg;
        __half2 hp = __halves2half2(h0, h1);
        __half2 lp = __halves2half2(l0, l1);
        g_BW1hi[idx] = *(uint32_t*)&hp;
        g_BW1lo[idx] = *(uint32_t*)&lp;
    } else if (bid < 256) {
        const int idx = bid - 128;
        const int f = idx >> 3, ch = idx & 7, n = tid;
        float s = 0.f;
#pragma unroll 8
        for (int c = ch * 32; c < ch * 32 + 32; c++)
            s = fmaf(W_fm[f * 256 + c] * gamma[c], W1[c * 256 + n], s);
        g_Wfm1p[(f * 8 + ch) * 256 + n] = s;
    } else if (bid < 280) {
        const int t = bid - 256, c = tid;
        const int w = c >> 5, lane = c & 31;
        float qb = step_q[t * 256 + c] + b_fm[c];
        s_buf[c] = qb;
        __syncthreads();
        float s = block_sum(qb, s_red, c);
        if (c == 0) g_Sqb[t] = s;
        float s2 = block_sum(qb * qb, s_red, c);
        if (c == 0) g_nqb[t] = s2;
#pragma unroll
        for (int q = 0; q < 2; q++) {
            int f = w * 2 + q;
            float d = 0.f;
#pragma unroll
            for (int i = 0; i < 8; i++)
                d = fmaf(W_fm[f * 256 + lane + 32 * i], s_buf[lane + 32 * i], d);
#pragma unroll
            for (int o = 16; o; o >>= 1) d += __shfl_xor_sync(0xffffffffu, d, o);
            if (lane == 0) g_QB16[t * 16 + f] = d;
        }
    } else if (bid < 296) {
        const int f = bid - 280, c = tid;
        const int w = c >> 5, lane = c & 31;
        float wf = W_fm[f * 256 + c];
        s_buf[c] = wf;
        __syncthreads();
        float s = block_sum(wf, s_red, c);
        if (c == 0) g_sfm[f] = s;
#pragma unroll
        for (int q = 0; q < 2; q++) {
            int g = w * 2 + q;
            float d = 0.f;
#pragma unroll
            for (int i = 0; i < 8; i++)
                d = fmaf(W_fm[g * 256 + lane + 32 * i], s_buf[lane + 32 * i], d);
#pragma unroll
            for (int o = 16; o; o >>= 1) d += __shfl_xor_sync(0xffffffffu, d, o);
            if (lane == 0) g_Gm[f * 16 + g] = d;
        }
    } else if (bid < 304) {
        const int ch = bid - 296, j = tid;
        float P = 0.f, G = 0.f;
#pragma unroll 8
        for (int c = ch * 32; c < ch * 32 + 32; c++) {
            float w = W1[c * 256 + j];
            P = fmaf(beta[c], w, P);
            G = fmaf(gamma[c], w, G);
        }
        g_Cp[ch * 256 + j] = P;
        g_Gp[ch * 256 + j] = G;
    } else if (bid < 496) {
        const int idx = bid - 304;
        const int t = idx >> 3, ch = idx & 7, n = tid;
        float s = 0.f;
#pragma unroll 8
        for (int c = ch * 32; c < ch * 32 + 32; c++) {
            float qb = step_q[t * 256 + c] + b_fm[c];
            s = fmaf(qb * gamma[c], W1[c * 256 + n], s);
        }
        g_Q1p[(t * 8 + ch) * 256 + n] = s;
    } else {
        const int wid = tid >> 5, lane = tid & 31;
        const int bn0 = ((bid - 496) * 8 + wid) * 4;
        float4 f0[4], f1[4];
#pragma unroll
        for (int i = 0; i < 4; i++) {
            const float4* p = (const float4*)&final_h[(size_t)(bn0 + i) * 256 + lane * 8];
            f0[i] = p[0]; f1[i] = p[1];
        }
        const float4* bfp = (const float4*)&b_fm[lane * 8];
        float4 bf0 = __ldg(bfp), bf1 = __ldg(bfp + 1);
#pragma unroll
        for (int i = 0; i < 4; i++) {
            float s  = ((f0[i].x + f0[i].y) + (f0[i].z + f0[i].w)) +
                       ((f1[i].x + f1[i].y) + (f1[i].z + f1[i].w));
            float s2 = dot8(f0[i], f1[i], f0[i], f1[i]);
#pragma unroll
            for (int o = 16; o; o >>= 1) {
                s  += __shfl_xor_sync(0xffffffffu, s, o);
                s2 += __shfl_xor_sync(0xffffffffu, s2, o);
            }
            if (lane == 0) { g_Sfh[bn0 + i] = s; g_nfh[bn0 + i] = s2; }
        }
#pragma unroll
        for (int f = 0; f < 16; f++) {
            const float4* wp = (const float4*)&W_fm[f * 256 + lane * 8];
            float4 w0 = __ldg(wp), w1 = __ldg(wp + 1);
#pragma unroll
            for (int i = 0; i < 4; i++) {
                float d = dot8(w0, w1, f0[i], f1[i]);
#pragma unroll
                for (int o = 16; o; o >>= 1) d += __shfl_xor_sync(0xffffffffu, d, o);
                if (lane == 0) g_F16[(bn0 + i) * 16 + f] = d;
            }
        }
#pragma unroll 4
        for (int t = 0; t < T_HOR; t++) {
            const float4* qp = (const float4*)&step_q[t * 256 + lane * 8];
            float4 q0 = __ldg(qp), q1 = __ldg(qp + 1);
            q0.x += bf0.x; q0.y += bf0.y; q0.z += bf0.z; q0.w += bf0.w;
            q1.x += bf1.x; q1.y += bf1.y; q1.z += bf1.z; q1.w += bf1.w;
#pragma unroll
            for (int i = 0; i < 4; i++) {
                float d = dot8(q0, q1, f0[i], f1[i]);
#pragma unroll
                for (int o = 16; o; o >>= 1) d += __shfl_xor_sync(0xffffffffu, d, o);
                if (lane == 0) g_DOT[(bn0 + i) * T_HOR + t] = d;
            }
        }
    }
}

// ================= prep kernel 2 (W2 pre-halved) =================
#define FA_HI 0
#define FA_LO 16384
__global__ void __launch_bounds__(256)
prep_k2(const float* __restrict__ final_h, const float* __restrict__ gamma,
        const float* __restrict__ b1, const float* __restrict__ W2)
{
    __shared__ __align__(1024) char s_frag[32768];
    const int bid = blockIdx.x;
    const int tid = threadIdx.x;

    if (bid < 8) {
        const int k0 = bid * 2;
        const int n  = tid;
        float v0 = 0.f, v1 = 0.f;
#pragma unroll
        for (int ch = 0; ch < 8; ch++) {
            v0 += g_Wfm1p[(k0 * 8 + ch) * 256 + n];
            v1 += g_Wfm1p[((k0 + 1) * 8 + ch) * 256 + n];
        }
        __half h0 = __float2half_rn(v0), h1 = __float2half_rn(v1);
        __half l0 = __float2half_rn(v0 - __half2float(h0));
        __half l1 = __float2half_rn(v1 - __half2float(h1));
        const int kk = k0 & 15;
        const int ntile = n >> 3;
        const int lane  = ((n & 7) << 2) | ((kk & 7) >> 1);
        const int reg   = (kk >> 3) & 1;
        const int idx = (ntile >> 1) * 128 + lane * 4 + (ntile & 1) * 2 + reg;
        __half2 hp = __halves2half2(h0, h1);
        __half2 lp = __halves2half2(l0, l1);
        g_BFMhi[idx] = *(uint32_t*)&hp;
        g_BFMlo[idx] = *(uint32_t*)&lp;
    } else if (bid == 8) {
        const int j = tid;
        float P = 0.f, G = 0.f;
#pragma unroll
        for (int ch = 0; ch < 8; ch++) {
            P += g_Cp[ch * 256 + j];
            G += g_Gp[ch * 256 + j];
        }
        g_C[j]  = P + b1[j];
        g_G[j]  = G;
        g_W2[j] = W2[j] * 0.5f;          // fold GELU's 0.5
    } else if (bid < 33) {
        const int t = bid - 9, n = tid;
        float s = 0.f;
#pragma unroll
        for (int ch = 0; ch < 8; ch++)
            s += g_Q1p[(t * 8 + ch) * 256 + n];
        g_Q1[t * 256 + n] = s;
    } else {
        const uint32_t sbase = smem_u32(s_frag);
        const int bn0 = (bid - 33) * 32;
        for (int i = tid; i < 32 * 128; i += 256) {
            const int r  = i >> 7;
            const int cp = i & 127;
            const int c  = 2 * cp;
            float2 fh2 = *(const float2*)&final_h[(size_t)(bn0 + r) * 256 + c];
            float v0 = fh2.x * __ldg(&gamma[c]);
            float v1 = fh2.y * __ldg(&gamma[c + 1]);
            __half h0 = __float2half_rn(v0), h1 = __float2half_rn(v1);
            __half l0 = __float2half_rn(v0 - __half2float(h0));
            __half l1 = __float2half_rn(v1 - __half2float(h1));
            __half2 hp = __halves2half2(h0, h1);
            __half2 lp = __halves2half2(l0, l1);
            const uint32_t mtile  = (uint32_t)(r >> 4);
            const uint32_t mm     = (uint32_t)(r & 15);
            const uint32_t kk     = (uint32_t)(c & 15);
            const uint32_t lnA    = ((mm & 7) << 2) | ((kk & 7) >> 1);
            const uint32_t reg    = ((kk & 8) ? 2u : 0u) | ((mm >= 8) ? 1u : 0u);
            uint32_t off = ((mtile * 16 + (uint32_t)(c >> 4)) << 9) + (lnA << 4) + (reg << 2);
            off ^= (off >> 2) & 0x60;
            *(uint32_t*)(s_frag + FA_HI + off) = *(uint32_t*)&hp;
            *(uint32_t*)(s_frag + FA_LO + off) = *(uint32_t*)&lp;
        }
        __syncthreads();

        const int w = tid >> 5, lane = tid & 31;
        const int wm = w & 1, wn = w >> 1;
        const uint32_t laneOff = ((uint32_t)lane << 4) ^ (((uint32_t)lane & 0x18) << 2);
        const uint4* gBhi = (const uint4*)g_BW1hi;
        const uint4* gBlo = (const uint4*)g_BW1lo;

        float acc[8][4];
#pragma unroll
        for (int nt = 0; nt < 8; nt++)
#pragma unroll
            for (int e = 0; e < 4; e++) acc[nt][e] = 0.f;

#pragma unroll 2
        for (int ks = 0; ks < 16; ks++) {
            uint32_t ahi[4], alo[4];
            const uint32_t aRow = (((uint32_t)(wm * 16 + ks)) << 9) + laneOff;
            LDS128(ahi, sbase + FA_HI + aRow);
            LDS128(alo, sbase + FA_LO + aRow);
#pragma unroll
            for (int p = 0; p < 4; p++) {
                uint4 bh = __ldg(gBhi + ks * 512 + (wn * 4 + p) * 32 + lane);
                uint4 bl = __ldg(gBlo + ks * 512 + (wn * 4 + p) * 32 + lane);
                MMA_F32(acc[2 * p],     ahi, bh.x, bh.y);
                MMA_F32(acc[2 * p + 1], ahi, bh.z, bh.w);
                MMA_F32(acc[2 * p],     alo, bh.x, bh.y);
                MMA_F32(acc[2 * p + 1], alo, bh.z, bh.w);
                MMA_F32(acc[2 * p],     ahi, bl.x, bl.y);
                MMA_F32(acc[2 * p + 1], ahi, bl.z, bl.w);
            }
        }
        const int g8 = lane >> 2, cq = lane & 3;
#pragma unroll
        for (int nt = 0; nt < 8; nt++)
#pragma unroll
            for (int q = 0; q < 2; q++) {
                const int row = wm * 16 + q * 8 + g8;
                const int j   = wn * 64 + nt * 8 + cq * 2;
                *(float2*)&g_FH1[(size_t)(bn0 + row) * 256 + j] =
                    make_float2(acc[nt][q * 2], acc[nt][q * 2 + 1]);
            }
    }
}

// ================= main kernel =================
__global__ void __launch_bounds__(TPB, 2)
dhh_main(const float* __restrict__ future_met,
         const float* __restrict__ b2,
         float* __restrict__ out)
{
    extern __shared__ __align__(1024) char smem[];
    float* smf = (float*)smem;
    const uint32_t sbase = smem_u32(smem);
    const int tid  = threadIdx.x;
    const int w    = tid >> 5;
    const int lane = tid & 31;
    const int m    = tid & 127, half = tid >> 7;
    int ln = m / 24; if (ln > 4) ln = 4;
    const int t = m % 24;

    const int b  = blockIdx.x / (N_SZ / GRP);
    const int n0 = (blockIdx.x % (N_SZ / GRP)) * GRP;
    const int bn = b * N_SZ + n0 + ln;

    if (half == 0) {
        float fmv[16];
        {
            const float4* fmp = (const float4*)&future_met[
                ((size_t)(b * T_HOR + t) * N_SZ + (n0 + ln)) * FMET];
            float4 x0 = fmp[0], x1 = fmp[1], x2 = fmp[2], x3 = fmp[3];
            fmv[0]=x0.x; fmv[1]=x0.y; fmv[2]=x0.z;  fmv[3]=x0.w;
            fmv[4]=x1.x; fmv[5]=x1.y; fmv[6]=x1.z;  fmv[7]=x1.w;
            fmv[8]=x2.x; fmv[9]=x2.y; fmv[10]=x2.z; fmv[11]=x2.w;
            fmv[12]=x3.x; fmv[13]=x3.y; fmv[14]=x3.z; fmv[15]=x3.w;
        }
        const uint32_t mbase  = (uint32_t)(m >> 4);
        const uint32_t lane_m = (uint32_t)(m & 7) << 2;
        const uint32_t reg_m  = ((m & 15) >= 8) ? 1u : 0u;
#pragma unroll
        for (int j = 0; j < 8; j++) {
            float v0 = fmv[2 * j], v1 = fmv[2 * j + 1];
            __half h0 = __float2half_rn(v0), h1 = __float2half_rn(v1);
            __half l0 = __float2half_rn(v0 - __half2float(h0));
            __half l1 = __float2half_rn(v1 - __half2float(h1));
            __half2 hp = __halves2half2(h0, h1);
            __half2 lp = __halves2half2(l0, l1);
            const uint32_t kk  = (uint32_t)(2 * j);
            const uint32_t lnA = lane_m | ((kk & 7) >> 1);
            const uint32_t reg = ((kk & 8) ? 2u : 0u) | reg_m;
            uint32_t off = (mbase << 9) + (lnA << 4) + (reg << 2);
            off ^= (off >> 2) & 0x60;
            *(uint32_t*)(smem + OFF_AHI + off) = *(uint32_t*)&hp;
            *(uint32_t*)(smem + OFF_ALO + off) = *(uint32_t*)&lp;
        }
        float mean256 = __ldg(&g_Sfh[bn]) + __ldg(&g_Sqb[t]);
        float ss = __ldg(&g_nfh[bn]) + __ldg(&g_nqb[t]) +
                   2.0f * __ldg(&g_DOT[bn * T_HOR + t]);
        float cross = 0.f, mf = 0.f;
#pragma unroll
        for (int f = 0; f < 16; f++) {
            mf    = fmaf(fmv[f], __ldg(&g_sfm[f]), mf);
            cross = fmaf(fmv[f], __ldg(&g_F16[bn * 16 + f]) + __ldg(&g_QB16[t * 16 + f]), cross);
        }
        mean256 += mf;
        ss += 2.0f * cross;
        float quad = 0.f;
#pragma unroll
        for (int f = 0; f < 16; f++) {
            float rd = 0.f;
#pragma unroll
            for (int g = 0; g < 16; g++)
                rd = fmaf(__ldg(&g_Gm[f * 16 + g]), fmv[g], rd);
            quad = fmaf(fmv[f], rd, quad);
        }
        ss += quad;
        const float mu   = mean256 * (1.0f / HIDDEN);
        const float var  = ss * (1.0f / HIDDEN) - mu * mu;
        const float rstd = rsqrtf(var + EPS_LN);
        smf[OFF_RSTD / 4 + m] = rstd;
        smf[OFF_MR   / 4 + m] = mu * rstd;
    }

#pragma unroll 4
    for (int tt = 0; tt < T_HOR; tt++)
        smf[OFF_Q1 / 4 + tt * 258 + tid] = __ldg(&g_Q1[tt * 256 + tid]);
#pragma unroll
    for (int lni = 0; lni < 6; lni++) {
        int src = lni < 4 ? lni : 4;
        smf[OFF_FH1 / 4 + lni * 258 + tid] =
            __ldg(&g_FH1[(size_t)(b * N_SZ + n0 + src) * 256 + tid]);
    }
    smf[OFF_CS  / 4 + tid] = g_C[tid];
    smf[OFF_GS  / 4 + tid] = g_G[tid];
    smf[OFF_W2S / 4 + tid] = g_W2[tid];
    __syncthreads();

    const int wm = w & 1, wn = w >> 1;
    const int g8 = lane >> 2, cq = lane & 3;
    const uint32_t laneOff = ((uint32_t)lane << 4) ^ (((uint32_t)lane & 0x18) << 2);
    const uint4* gFhi = (const uint4*)g_BFMhi;
    const uint4* gFlo = (const uint4*)g_BFMlo;
    u64 part2[8];
#pragma unroll
    for (int idx = 0; idx < 8; idx++) part2[idx] = 0ull;

    float rstd[8], mrn[8];
    int fhoff[8], q1off[8];
#pragma unroll
    for (int idx = 0; idx < 8; idx++) {
        const int row = wm * 64 + (idx >> 1) * 16 + (idx & 1) * 8 + g8;
        rstd[idx] = smf[OFF_RSTD / 4 + row];
        mrn[idx]  = -smf[OFF_MR  / 4 + row];
        const int lnr = row / 24;
        fhoff[idx] = OFF_FH1 / 4 + lnr * 258;
        q1off[idx] = OFF_Q1  / 4 + (row - lnr * 24) * 258;
    }

    // A&S 7.1.26 packed constants (a-coeffs negated so erf = 1 + polyN(k)*e)
    const u64 C_IS2  = pk2(0.70710678118654752f, 0.70710678118654752f);
    const u64 C_ONE  = pk2(1.0f, 1.0f);
    const u64 C_P    = pk2(0.3275911f, 0.3275911f);
    const u64 C_NL2E = pk2(-1.4426950408889634f, -1.4426950408889634f);
    const u64 C_A5   = pk2(-1.061405429f, -1.061405429f);
    const u64 C_A4   = pk2(1.453152027f, 1.453152027f);
    const u64 C_A3   = pk2(-1.421413741f, -1.421413741f);
    const u64 C_A2   = pk2(0.284496736f, 0.284496736f);
    const u64 C_A1   = pk2(-0.254829592f, -0.254829592f);

#pragma unroll
    for (int nh = 0; nh < 2; nh++) {
        u64 cs2[4], gs2[4], w22[4];
#pragma unroll
        for (int nt = 0; nt < 4; nt++) {
            const int j = nh * 128 + wn * 32 + nt * 8 + cq * 2;
            cs2[nt] = *(const u64*)&smf[OFF_CS  / 4 + j];
            gs2[nt] = *(const u64*)&smf[OFF_GS  / 4 + j];
            w22[nt] = *(const u64*)&smf[OFF_W2S / 4 + j];
        }
        const int pbase = nh * 8 + wn * 2;
        uint4 bh0 = __ldg(gFhi + (pbase + 0) * 32 + lane);
        uint4 bh1 = __ldg(gFhi + (pbase + 1) * 32 + lane);
        uint4 bl0 = __ldg(gFlo + (pbase + 0) * 32 + lane);
        uint4 bl1 = __ldg(gFlo + (pbase + 1) * 32 + lane);
#pragma unroll
        for (int mt = 0; mt < 4; mt++) {
            uint32_t ahi[4], alo[4];
            const uint32_t aRow = (((uint32_t)(wm * 4 + mt)) << 9) + laneOff;
            LDS128(ahi, sbase + OFF_AHI + aRow);
            LDS128(alo, sbase + OFF_ALO + aRow);
            float acc[4][4];
#pragma unroll
            for (int nt = 0; nt < 4; nt++)
#pragma unroll
                for (int e = 0; e < 4; e++) acc[nt][e] = 0.f;
            MMA_F32(acc[0], ahi, bh0.x, bh0.y);
            MMA_F32(acc[1], ahi, bh0.z, bh0.w);
            MMA_F32(acc[2], ahi, bh1.x, bh1.y);
            MMA_F32(acc[3], ahi, bh1.z, bh1.w);
            MMA_F32(acc[0], alo, bh0.x, bh0.y);
            MMA_F32(acc[1], alo, bh0.z, bh0.w);
            MMA_F32(acc[2], alo, bh1.x, bh1.y);
            MMA_F32(acc[3], alo, bh1.z, bh1.w);
            MMA_F32(acc[0], ahi, bl0.x, bl0.y);
            MMA_F32(acc[1], ahi, bl0.z, bl0.w);
            MMA_F32(acc[2], ahi, bl1.x, bl1.y);
            MMA_F32(acc[3], ahi, bl1.z, bl1.w);

#pragma unroll
            for (int nt = 0; nt < 4; nt++) {
                const int j = nh * 128 + wn * 32 + nt * 8 + cq * 2;
#pragma unroll
                for (int q = 0; q < 2; q++) {
                    const int idx = mt * 2 + q;
                    u64 fq = fadd2(*(const u64*)&smf[fhoff[idx] + j],
                                   *(const u64*)&smf[q1off[idx] + j]);
                    u64 S2 = fadd2(pk2(acc[nt][q * 2], acc[nt][q * 2 + 1]), fq);
                    u64 o2 = cs2[nt];
                    ffma2(o2, pk2(mrn[idx], mrn[idx]), gs2[nt]);
                    ffma2(o2, S2, pk2(rstd[idx], rstd[idx]));

                    // ---- packed A&S erf GELU ----
                    u64 y2v = fmul2(o2, C_IS2);
                    float y0, y1; upk2(y2v, y0, y1);
                    u64 a2p = pk2(fabsf(y0), fabsf(y1));
                    u64 d2 = C_ONE; ffma2(d2, a2p, C_P);
                    float dd0, dd1; upk2(d2, dd0, dd1);
                    u64 k2v = pk2(frcp_fast(dd0), frcp_fast(dd1));
                    u64 t2v = fmul2(a2p, a2p);
                    u64 ea2 = fmul2(t2v, C_NL2E);
                    float ea0, ea1; upk2(ea2, ea0, ea1);
                    u64 e2v = pk2(fex2(ea0), fex2(ea1));
                    u64 p2 = C_A4; ffma2(p2, C_A5, k2v);
                    u64 p3 = C_A3; ffma2(p3, p2, k2v);
                    u64 p4 = C_A2; ffma2(p4, p3, k2v);
                    u64 p5 = C_A1; ffma2(p5, p4, k2v);
                    u64 pkk = fmul2(p5, k2v);
                    u64 er = C_ONE; ffma2(er, pkk, e2v);   // erf(|y|)
                    float er0, er1; upk2(er, er0, er1);
                    er0 = copysignf(er0, y0);
                    er1 = copysignf(er1, y1);
                    u64 onep = fadd2(pk2(er0, er1), C_ONE);
                    u64 gv = fmul2(o2, onep);              // x*(1+erf); 0.5 folded in W2
                    ffma2(part2[idx], gv, w22[nt]);
                }
            }
        }
    }

#pragma unroll
    for (int idx = 0; idx < 8; idx++) {
        const int row = wm * 64 + (idx >> 1) * 16 + (idx & 1) * 8 + g8;
        float plo, phi; upk2(part2[idx], plo, phi);
        smf[OFF_RED / 4 + row * 16 + wn * 4 + cq] = plo + phi;
    }
    __syncthreads();

    if (tid < GRP * T_HOR) {
        const int lno = tid / T_HOR, to = tid % T_HOR;
        const float4* rr = (const float4*)&smf[OFF_RED / 4 + tid * 16];
        float4 r0 = rr[0], r1 = rr[1], r2 = rr[2], r3 = rr[3];
        float s = ((r0.x + r0.y) + (r0.z + r0.w)) + ((r1.x + r1.y) + (r1.z + r1.w)) +
                  ((r2.x + r2.y) + (r2.z + r2.w)) + ((r3.x + r3.y) + (r3.z + r3.w));
        out[(size_t)(b * T_HOR + to) * N_SZ + (n0 + lno)] = s + b2[0];
    }
}

extern "C" void kernel_launch(void* const* d_in, const int* in_sizes, int n_in,
                              void* d_out, int out_size) {
    const float* final_h    = (const float*)d_in[0];
    const float* future_met = (const float*)d_in[1];
    const float* step_q     = (const float*)d_in[2];
    const float* W_fm       = (const float*)d_in[3];
    const float* b_fm       = (const float*)d_in[4];
    const float* gamma      = (const float*)d_in[5];
    const float* beta       = (const float*)d_in[6];
    const float* W1         = (const float*)d_in[7];
    const float* b1         = (const float*)d_in[8];
    const float* W2         = (const float*)d_in[9];
    const float* b2         = (const float*)d_in[10];
    float* out = (float*)d_out;

    prep_k1<<<996, 256>>>(final_h, gamma, W1, W_fm, step_q, b_fm, beta);
    prep_k2<<<533, 256>>>(final_h, gamma, b1, W2);

    cudaFuncSetAttribute(dhh_main, cudaFuncAttributeMaxDynamicSharedMemorySize, SMEM_TOTAL);
    dhh_main<<<NCTA, TPB, SMEM_TOTAL>>>(future_met, b2, out);
}

// round 17
// speedup vs baseline: 5.1930x; 1.0535x over previous
#include <cuda_runtime.h>
#include <cuda_fp16.h>
#include <math.h>
#include <stdint.h>

#define HIDDEN 256
#define T_HOR  24
#define FMET   16
#define B_SZ   16
#define N_SZ   1000
#define GRP    5
#define TPB    256
#define NCTA   (B_SZ * (N_SZ / GRP))   // 3200
#define NBN    (B_SZ * N_SZ)           // 16000
#define EPS_LN 1e-5f

// ---- main kernel smem (bytes) ----
#define OFF_AHI  0
#define OFF_ALO  4096
#define OFF_Q1   8192
#define OFF_FH1  32960
#define OFF_RSTD 39152
#define OFF_MR   39664
#define OFF_CS   40176
#define OFF_GS   41200
#define OFF_W2S  42224
#define OFF_RED  43248
#define SMEM_TOTAL 51456

typedef unsigned long long u64;

__device__ __align__(16) uint32_t g_BW1hi[16 * 2048];
__device__ __align__(16) uint32_t g_BW1lo[16 * 2048];
__device__ __align__(16) uint32_t g_BFMhi[2048];
__device__ __align__(16) uint32_t g_BFMlo[2048];
__device__ float g_Wfm1p[16 * 8 * 256];
__device__ float g_Cp[8 * 256];
__device__ float g_Gp[8 * 256];
__device__ float g_Q1p[24 * 8 * 256];
__device__ float g_C[HIDDEN];
__device__ float g_G[HIDDEN];
__device__ float g_W2[HIDDEN];
__device__ float g_Q1[T_HOR * 256];
__device__ float g_FH1[(size_t)NBN * 256];
__device__ float g_Sqb[T_HOR];
__device__ float g_nqb[T_HOR];
__device__ float g_QB16[T_HOR * 16];
__device__ float g_sfm[16];
__device__ float g_Gm[16 * 16];
__device__ float g_Sfh[NBN];
__device__ float g_nfh[NBN];
__device__ float g_F16[NBN * 16];
__device__ float g_DOT[NBN * T_HOR];

__device__ __forceinline__ u64 pk2(float lo, float hi) {
    u64 r; asm("mov.b64 %0, {%1, %2};" : "=l"(r) : "f"(lo), "f"(hi)); return r;
}
__device__ __forceinline__ void upk2(u64 v, float &lo, float &hi) {
    asm("mov.b64 {%0, %1}, %2;" : "=f"(lo), "=f"(hi) : "l"(v));
}
__device__ __forceinline__ void ffma2(u64 &d, u64 a, u64 b) {
    asm("fma.rn.f32x2 %0, %1, %2, %0;" : "+l"(d) : "l"(a), "l"(b));
}
__device__ __forceinline__ u64 fadd2(u64 a, u64 b) {
    u64 d; asm("add.rn.f32x2 %0, %1, %2;" : "=l"(d) : "l"(a), "l"(b)); return d;
}
__device__ __forceinline__ u64 fmul2(u64 a, u64 b) {
    u64 d; asm("mul.rn.f32x2 %0, %1, %2;" : "=l"(d) : "l"(a), "l"(b)); return d;
}
__device__ __forceinline__ float fex2(float x) {
    float r; asm("ex2.approx.f32 %0, %1;" : "=f"(r) : "f"(x)); return r;
}
__device__ __forceinline__ uint32_t smem_u32(const void* p) {
    uint32_t a;
    asm("{ .reg .u64 t; cvta.to.shared.u64 t, %1; cvt.u32.u64 %0, t; }" : "=r"(a) : "l"(p));
    return a;
}
#define LDS128(r, addr) \
    asm volatile("ld.shared.v4.b32 {%0,%1,%2,%3}, [%4];" \
        : "=r"((r)[0]), "=r"((r)[1]), "=r"((r)[2]), "=r"((r)[3]) : "r"(addr))
#define MMA_F32(d, a, b0, b1v) \
    asm volatile("mma.sync.aligned.m16n8k16.row.col.f32.f16.f16.f32 " \
        "{%0,%1,%2,%3}, {%4,%5,%6,%7}, {%8,%9}, {%0,%1,%2,%3};" \
        : "+f"((d)[0]), "+f"((d)[1]), "+f"((d)[2]), "+f"((d)[3]) \
        : "r"((a)[0]), "r"((a)[1]), "r"((a)[2]), "r"((a)[3]), \
          "r"(b0), "r"(b1v))

__device__ __forceinline__ float block_sum(float v, float* red, int tid) {
#pragma unroll
    for (int o = 16; o; o >>= 1) v += __shfl_xor_sync(0xffffffffu, v, o);
    if ((tid & 31) == 0) red[tid >> 5] = v;
    __syncthreads();
    float x = 0.f;
    if (tid < 32) {
        x = (tid < 8) ? red[tid] : 0.f;
#pragma unroll
        for (int o = 4; o; o >>= 1) x += __shfl_xor_sync(0xffffffffu, x, o);
    }
    __syncthreads();
    return x;
}

__device__ __forceinline__ float dot8(float4 a0, float4 a1, float4 b0, float4 b1) {
    return fmaf(a0.x, b0.x, fmaf(a0.y, b0.y, fmaf(a0.z, b0.z, fmaf(a0.w, b0.w,
           fmaf(a1.x, b1.x, fmaf(a1.y, b1.y, fmaf(a1.z, b1.z, a1.w * b1.w)))))));
}

// ================= prep kernel A: independent small work =================
// [0,128): W1 pack  [128,256): wfm1 partial  [256,280): qt
// [280,296): gm     [296,304): cg partial    [304,496): q1 partial
__global__ void __launch_bounds__(256)
prep_pack(const float* __restrict__ gamma,
          const float* __restrict__ W1, const float* __restrict__ W_fm,
          const float* __restrict__ step_q, const float* __restrict__ b_fm,
          const float* __restrict__ beta)
{
    __shared__ float s_buf[256];
    __shared__ float s_red[8];
    const int bid = blockIdx.x;
    const int tid = threadIdx.x;

    if (bid < 128) {
        const int k0 = bid * 2;
        const int n  = tid;
        float v0 = W1[k0 * 256 + n];
        float v1 = W1[(k0 + 1) * 256 + n];
        __half h0 = __float2half_rn(v0), h1 = __float2half_rn(v1);
        __half l0 = __float2half_rn(v0 - __half2float(h0));
        __half l1 = __float2half_rn(v1 - __half2float(h1));
        const int ks = k0 >> 4, kk = k0 & 15;
        const int ntile = n >> 3;
        const int lane  = ((n & 7) << 2) | ((kk & 7) >> 1);
        const int reg   = (kk >> 3) & 1;
        const int idx = ks * 2048 + (ntile >> 1) * 128 + lane * 4 + (ntile & 1) * 2 + reg;
        __half2 hp = __halves2half2(h0, h1);
        __half2 lp = __halves2half2(l0, l1);
        g_BW1hi[idx] = *(uint32_t*)&hp;
        g_BW1lo[idx] = *(uint32_t*)&lp;
    } else if (bid < 256) {
        const int idx = bid - 128;
        const int f = idx >> 3, ch = idx & 7, n = tid;
        float s = 0.f;
#pragma unroll 8
        for (int c = ch * 32; c < ch * 32 + 32; c++)
            s = fmaf(W_fm[f * 256 + c] * gamma[c], W1[c * 256 + n], s);
        g_Wfm1p[(f * 8 + ch) * 256 + n] = s;
    } else if (bid < 280) {
        const int t = bid - 256, c = tid;
        const int w = c >> 5, lane = c & 31;
        float qb = step_q[t * 256 + c] + b_fm[c];
        s_buf[c] = qb;
        __syncthreads();
        float s = block_sum(qb, s_red, c);
        if (c == 0) g_Sqb[t] = s;
        float s2 = block_sum(qb * qb, s_red, c);
        if (c == 0) g_nqb[t] = s2;
#pragma unroll
        for (int q = 0; q < 2; q++) {
            int f = w * 2 + q;
            float d = 0.f;
#pragma unroll
            for (int i = 0; i < 8; i++)
                d = fmaf(W_fm[f * 256 + lane + 32 * i], s_buf[lane + 32 * i], d);
#pragma unroll
            for (int o = 16; o; o >>= 1) d += __shfl_xor_sync(0xffffffffu, d, o);
            if (lane == 0) g_QB16[t * 16 + f] = d;
        }
    } else if (bid < 296) {
        const int f = bid - 280, c = tid;
        const int w = c >> 5, lane = c & 31;
        float wf = W_fm[f * 256 + c];
        s_buf[c] = wf;
        __syncthreads();
        float s = block_sum(wf, s_red, c);
        if (c == 0) g_sfm[f] = s;
#pragma unroll
        for (int q = 0; q < 2; q++) {
            int g = w * 2 + q;
            float d = 0.f;
#pragma unroll
            for (int i = 0; i < 8; i++)
                d = fmaf(W_fm[g * 256 + lane + 32 * i], s_buf[lane + 32 * i], d);
#pragma unroll
            for (int o = 16; o; o >>= 1) d += __shfl_xor_sync(0xffffffffu, d, o);
            if (lane == 0) g_Gm[f * 16 + g] = d;
        }
    } else if (bid < 304) {
        const int ch = bid - 296, j = tid;
        float P = 0.f, G = 0.f;
#pragma unroll 8
        for (int c = ch * 32; c < ch * 32 + 32; c++) {
            float w = W1[c * 256 + j];
            P = fmaf(beta[c], w, P);
            G = fmaf(gamma[c], w, G);
        }
        g_Cp[ch * 256 + j] = P;
        g_Gp[ch * 256 + j] = G;
    } else {
        const int idx = bid - 304;
        const int t = idx >> 3, ch = idx & 7, n = tid;
        float s = 0.f;
#pragma unroll 8
        for (int c = ch * 32; c < ch * 32 + 32; c++) {
            float qb = step_q[t * 256 + c] + b_fm[c];
            s = fmaf(qb * gamma[c], W1[c * 256 + n], s);
        }
        g_Q1p[(t * 8 + ch) * 256 + n] = s;
    }
}

// ================= prep kernel B: tensor + shfl branches mixed =================
// [0,500): FH1 MMA   [500,1000): bn-stats   [1000,1008): wfm1 reduce+pack
// 1008: cg reduce    [1009,1033): q1 reduce
#define FA_HI 0
#define FA_LO 16384
__global__ void __launch_bounds__(256)
prep_big(const float* __restrict__ final_h, const float* __restrict__ gamma,
         const float* __restrict__ W_fm, const float* __restrict__ step_q,
         const float* __restrict__ b_fm, const float* __restrict__ b1,
         const float* __restrict__ W2)
{
    __shared__ __align__(1024) char s_frag[32768];
    const int bid = blockIdx.x;
    const int tid = threadIdx.x;

    if (bid < 500) {
        // FH1 = (fh*gamma)@W1 via MMA, 32 rows/CTA
        const uint32_t sbase = smem_u32(s_frag);
        const int bn0 = bid * 32;
        for (int i = tid; i < 32 * 128; i += 256) {
            const int r  = i >> 7;
            const int cp = i & 127;
            const int c  = 2 * cp;
            float2 fh2 = *(const float2*)&final_h[(size_t)(bn0 + r) * 256 + c];
            float v0 = fh2.x * __ldg(&gamma[c]);
            float v1 = fh2.y * __ldg(&gamma[c + 1]);
            __half h0 = __float2half_rn(v0), h1 = __float2half_rn(v1);
            __half l0 = __float2half_rn(v0 - __half2float(h0));
            __half l1 = __float2half_rn(v1 - __half2float(h1));
            __half2 hp = __halves2half2(h0, h1);
            __half2 lp = __halves2half2(l0, l1);
            const uint32_t mtile  = (uint32_t)(r >> 4);
            const uint32_t mm     = (uint32_t)(r & 15);
            const uint32_t kk     = (uint32_t)(c & 15);
            const uint32_t lnA    = ((mm & 7) << 2) | ((kk & 7) >> 1);
            const uint32_t reg    = ((kk & 8) ? 2u : 0u) | ((mm >= 8) ? 1u : 0u);
            uint32_t off = ((mtile * 16 + (uint32_t)(c >> 4)) << 9) + (lnA << 4) + (reg << 2);
            off ^= (off >> 2) & 0x60;
            *(uint32_t*)(s_frag + FA_HI + off) = *(uint32_t*)&hp;
            *(uint32_t*)(s_frag + FA_LO + off) = *(uint32_t*)&lp;
        }
        __syncthreads();

        const int w = tid >> 5, lane = tid & 31;
        const int wm = w & 1, wn = w >> 1;
        const uint32_t laneOff = ((uint32_t)lane << 4) ^ (((uint32_t)lane & 0x18) << 2);
        const uint4* gBhi = (const uint4*)g_BW1hi;
        const uint4* gBlo = (const uint4*)g_BW1lo;

        float acc[8][4];
#pragma unroll
        for (int nt = 0; nt < 8; nt++)
#pragma unroll
            for (int e = 0; e < 4; e++) acc[nt][e] = 0.f;

#pragma unroll 2
        for (int ks = 0; ks < 16; ks++) {
            uint32_t ahi[4], alo[4];
            const uint32_t aRow = (((uint32_t)(wm * 16 + ks)) << 9) + laneOff;
            LDS128(ahi, sbase + FA_HI + aRow);
            LDS128(alo, sbase + FA_LO + aRow);
#pragma unroll
            for (int p = 0; p < 4; p++) {
                uint4 bh = __ldg(gBhi + ks * 512 + (wn * 4 + p) * 32 + lane);
                uint4 bl = __ldg(gBlo + ks * 512 + (wn * 4 + p) * 32 + lane);
                MMA_F32(acc[2 * p],     ahi, bh.x, bh.y);
                MMA_F32(acc[2 * p + 1], ahi, bh.z, bh.w);
                MMA_F32(acc[2 * p],     alo, bh.x, bh.y);
                MMA_F32(acc[2 * p + 1], alo, bh.z, bh.w);
                MMA_F32(acc[2 * p],     ahi, bl.x, bl.y);
                MMA_F32(acc[2 * p + 1], ahi, bl.z, bl.w);
            }
        }
        const int g8 = lane >> 2, cq = lane & 3;
#pragma unroll
        for (int nt = 0; nt < 8; nt++)
#pragma unroll
            for (int q = 0; q < 2; q++) {
                const int row = wm * 16 + q * 8 + g8;
                const int j   = wn * 64 + nt * 8 + cq * 2;
                *(float2*)&g_FH1[(size_t)(bn0 + row) * 256 + j] =
                    make_float2(acc[nt][q * 2], acc[nt][q * 2 + 1]);
            }
    } else if (bid < 1000) {
        // bn-stats: warp handles 4 consecutive bn rows
        const int wid = tid >> 5, lane = tid & 31;
        const int bn0 = ((bid - 500) * 8 + wid) * 4;
        float4 f0[4], f1[4];
#pragma unroll
        for (int i = 0; i < 4; i++) {
            const float4* p = (const float4*)&final_h[(size_t)(bn0 + i) * 256 + lane * 8];
            f0[i] = p[0]; f1[i] = p[1];
        }
        const float4* bfp = (const float4*)&b_fm[lane * 8];
        float4 bf0 = __ldg(bfp), bf1 = __ldg(bfp + 1);
#pragma unroll
        for (int i = 0; i < 4; i++) {
            float s  = ((f0[i].x + f0[i].y) + (f0[i].z + f0[i].w)) +
                       ((f1[i].x + f1[i].y) + (f1[i].z + f1[i].w));
            float s2 = dot8(f0[i], f1[i], f0[i], f1[i]);
#pragma unroll
            for (int o = 16; o; o >>= 1) {
                s  += __shfl_xor_sync(0xffffffffu, s, o);
                s2 += __shfl_xor_sync(0xffffffffu, s2, o);
            }
            if (lane == 0) { g_Sfh[bn0 + i] = s; g_nfh[bn0 + i] = s2; }
        }
#pragma unroll
        for (int f = 0; f < 16; f++) {
            const float4* wp = (const float4*)&W_fm[f * 256 + lane * 8];
            float4 w0 = __ldg(wp), w1 = __ldg(wp + 1);
#pragma unroll
            for (int i = 0; i < 4; i++) {
                float d = dot8(w0, w1, f0[i], f1[i]);
#pragma unroll
                for (int o = 16; o; o >>= 1) d += __shfl_xor_sync(0xffffffffu, d, o);
                if (lane == 0) g_F16[(bn0 + i) * 16 + f] = d;
            }
        }
#pragma unroll 4
        for (int t = 0; t < T_HOR; t++) {
            const float4* qp = (const float4*)&step_q[t * 256 + lane * 8];
            float4 q0 = __ldg(qp), q1 = __ldg(qp + 1);
            q0.x += bf0.x; q0.y += bf0.y; q0.z += bf0.z; q0.w += bf0.w;
            q1.x += bf1.x; q1.y += bf1.y; q1.z += bf1.z; q1.w += bf1.w;
#pragma unroll
            for (int i = 0; i < 4; i++) {
                float d = dot8(q0, q1, f0[i], f1[i]);
#pragma unroll
                for (int o = 16; o; o >>= 1) d += __shfl_xor_sync(0xffffffffu, d, o);
                if (lane == 0) g_DOT[(bn0 + i) * T_HOR + t] = d;
            }
        }
    } else if (bid < 1008) {
        const int k0 = (bid - 1000) * 2;
        const int n  = tid;
        float v0 = 0.f, v1 = 0.f;
#pragma unroll
        for (int ch = 0; ch < 8; ch++) {
            v0 += g_Wfm1p[(k0 * 8 + ch) * 256 + n];
            v1 += g_Wfm1p[((k0 + 1) * 8 + ch) * 256 + n];
        }
        __half h0 = __float2half_rn(v0), h1 = __float2half_rn(v1);
        __half l0 = __float2half_rn(v0 - __half2float(h0));
        __half l1 = __float2half_rn(v1 - __half2float(h1));
        const int kk = k0 & 15;
        const int ntile = n >> 3;
        const int lane  = ((n & 7) << 2) | ((kk & 7) >> 1);
        const int reg   = (kk >> 3) & 1;
        const int idx = (ntile >> 1) * 128 + lane * 4 + (ntile & 1) * 2 + reg;
        __half2 hp = __halves2half2(h0, h1);
        __half2 lp = __halves2half2(l0, l1);
        g_BFMhi[idx] = *(uint32_t*)&hp;
        g_BFMlo[idx] = *(uint32_t*)&lp;
    } else if (bid == 1008) {
        const int j = tid;
        float P = 0.f, G = 0.f;
#pragma unroll
        for (int ch = 0; ch < 8; ch++) {
            P += g_Cp[ch * 256 + j];
            G += g_Gp[ch * 256 + j];
        }
        g_C[j]  = P + b1[j];
        g_G[j]  = G;
        g_W2[j] = W2[j] * 0.5f;
    } else {
        const int t = bid - 1009, n = tid;
        float s = 0.f;
#pragma unroll
        for (int ch = 0; ch < 8; ch++)
            s += g_Q1p[(t * 8 + ch) * 256 + n];
        g_Q1[t * 256 + n] = s;
    }
}

// ================= main kernel =================
__global__ void __launch_bounds__(TPB, 2)
dhh_main(const float* __restrict__ future_met,
         const float* __restrict__ b2,
         float* __restrict__ out)
{
    extern __shared__ __align__(1024) char smem[];
    float* smf = (float*)smem;
    const uint32_t sbase = smem_u32(smem);
    const int tid  = threadIdx.x;
    const int w    = tid >> 5;
    const int lane = tid & 31;
    const int m    = tid & 127, half = tid >> 7;
    int ln = m / 24; if (ln > 4) ln = 4;
    const int t = m % 24;

    const int b  = blockIdx.x / (N_SZ / GRP);
    const int n0 = (blockIdx.x % (N_SZ / GRP)) * GRP;
    const int bn = b * N_SZ + n0 + ln;

    if (half == 0) {
        float fmv[16];
        {
            const float4* fmp = (const float4*)&future_met[
                ((size_t)(b * T_HOR + t) * N_SZ + (n0 + ln)) * FMET];
            float4 x0 = fmp[0], x1 = fmp[1], x2 = fmp[2], x3 = fmp[3];
            fmv[0]=x0.x; fmv[1]=x0.y; fmv[2]=x0.z;  fmv[3]=x0.w;
            fmv[4]=x1.x; fmv[5]=x1.y; fmv[6]=x1.z;  fmv[7]=x1.w;
            fmv[8]=x2.x; fmv[9]=x2.y; fmv[10]=x2.z; fmv[11]=x2.w;
            fmv[12]=x3.x; fmv[13]=x3.y; fmv[14]=x3.z; fmv[15]=x3.w;
        }
        const uint32_t mbase  = (uint32_t)(m >> 4);
        const uint32_t lane_m = (uint32_t)(m & 7) << 2;
        const uint32_t reg_m  = ((m & 15) >= 8) ? 1u : 0u;
#pragma unroll
        for (int j = 0; j < 8; j++) {
            float v0 = fmv[2 * j], v1 = fmv[2 * j + 1];
            __half h0 = __float2half_rn(v0), h1 = __float2half_rn(v1);
            __half l0 = __float2half_rn(v0 - __half2float(h0));
            __half l1 = __float2half_rn(v1 - __half2float(h1));
            __half2 hp = __halves2half2(h0, h1);
            __half2 lp = __halves2half2(l0, l1);
            const uint32_t kk  = (uint32_t)(2 * j);
            const uint32_t lnA = lane_m | ((kk & 7) >> 1);
            const uint32_t reg = ((kk & 8) ? 2u : 0u) | reg_m;
            uint32_t off = (mbase << 9) + (lnA << 4) + (reg << 2);
            off ^= (off >> 2) & 0x60;
            *(uint32_t*)(smem + OFF_AHI + off) = *(uint32_t*)&hp;
            *(uint32_t*)(smem + OFF_ALO + off) = *(uint32_t*)&lp;
        }
        float mean256 = __ldg(&g_Sfh[bn]) + __ldg(&g_Sqb[t]);
        float ss = __ldg(&g_nfh[bn]) + __ldg(&g_nqb[t]) +
                   2.0f * __ldg(&g_DOT[bn * T_HOR + t]);
        float cross = 0.f, mf = 0.f;
#pragma unroll
        for (int f = 0; f < 16; f++) {
            mf    = fmaf(fmv[f], __ldg(&g_sfm[f]), mf);
            cross = fmaf(fmv[f], __ldg(&g_F16[bn * 16 + f]) + __ldg(&g_QB16[t * 16 + f]), cross);
        }
        mean256 += mf;
        ss += 2.0f * cross;
        float quad = 0.f;
#pragma unroll
        for (int f = 0; f < 16; f++) {
            float rd = 0.f;
#pragma unroll
            for (int g = 0; g < 16; g++)
                rd = fmaf(__ldg(&g_Gm[f * 16 + g]), fmv[g], rd);
            quad = fmaf(fmv[f], rd, quad);
        }
        ss += quad;
        const float mu   = mean256 * (1.0f / HIDDEN);
        const float var  = ss * (1.0f / HIDDEN) - mu * mu;
        const float rstd = rsqrtf(var + EPS_LN);
        smf[OFF_RSTD / 4 + m] = rstd;
        smf[OFF_MR   / 4 + m] = mu * rstd;
    }

#pragma unroll 4
    for (int tt = 0; tt < T_HOR; tt++)
        smf[OFF_Q1 / 4 + tt * 258 + tid] = __ldg(&g_Q1[tt * 256 + tid]);
#pragma unroll
    for (int lni = 0; lni < 6; lni++) {
        int src = lni < 4 ? lni : 4;
        smf[OFF_FH1 / 4 + lni * 258 + tid] =
            __ldg(&g_FH1[(size_t)(b * N_SZ + n0 + src) * 256 + tid]);
    }
    smf[OFF_CS  / 4 + tid] = g_C[tid];
    smf[OFF_GS  / 4 + tid] = g_G[tid];
    smf[OFF_W2S / 4 + tid] = g_W2[tid];
    __syncthreads();

    const int wm = w & 1, wn = w >> 1;
    const int g8 = lane >> 2, cq = lane & 3;
    const uint32_t laneOff = ((uint32_t)lane << 4) ^ (((uint32_t)lane & 0x18) << 2);
    const uint4* gFhi = (const uint4*)g_BFMhi;
    const uint4* gFlo = (const uint4*)g_BFMlo;
    u64 part2[8];
#pragma unroll
    for (int idx = 0; idx < 8; idx++) part2[idx] = 0ull;

    float rstd[8], mrn[8];
    int fhoff[8], q1off[8];
#pragma unroll
    for (int idx = 0; idx < 8; idx++) {
        const int row = wm * 64 + (idx >> 1) * 16 + (idx & 1) * 8 + g8;
        rstd[idx] = smf[OFF_RSTD / 4 + row];
        mrn[idx]  = -smf[OFF_MR  / 4 + row];
        const int lnr = row / 24;
        fhoff[idx] = OFF_FH1 / 4 + lnr * 258;
        q1off[idx] = OFF_Q1  / 4 + (row - lnr * 24) * 258;
    }

    // A&S 7.1.26 with Newton-reciprocal (no rcp MUFU)
    const u64 C_IS2  = pk2(0.70710678118654752f, 0.70710678118654752f);
    const u64 C_ONE  = pk2(1.0f, 1.0f);
    const u64 C_TWO  = pk2(2.0f, 2.0f);
    const u64 C_NEG1 = pk2(-1.0f, -1.0f);
    const u64 C_NP   = pk2(-0.3275911f, -0.3275911f);
    const u64 C_S0   = pk2(1.98739f, 1.98739f);
    const u64 C_S1   = pk2(1.26045f, 1.26045f);
    const u64 C_S2c  = pk2(0.25634f, 0.25634f);
    const u64 C_NL2E = pk2(-1.4426950408889634f, -1.4426950408889634f);
    const u64 C_A5   = pk2(-1.061405429f, -1.061405429f);
    const u64 C_A4   = pk2(1.453152027f, 1.453152027f);
    const u64 C_A3   = pk2(-1.421413741f, -1.421413741f);
    const u64 C_A2   = pk2(0.284496736f, 0.284496736f);
    const u64 C_A1   = pk2(-0.254829592f, -0.254829592f);

#pragma unroll
    for (int nh = 0; nh < 2; nh++) {
        u64 cs2[4], gs2[4], w22[4];
#pragma unroll
        for (int nt = 0; nt < 4; nt++) {
            const int j = nh * 128 + wn * 32 + nt * 8 + cq * 2;
            cs2[nt] = *(const u64*)&smf[OFF_CS  / 4 + j];
            gs2[nt] = *(const u64*)&smf[OFF_GS  / 4 + j];
            w22[nt] = *(const u64*)&smf[OFF_W2S / 4 + j];
        }
        const int pbase = nh * 8 + wn * 2;
        uint4 bh0 = __ldg(gFhi + (pbase + 0) * 32 + lane);
        uint4 bh1 = __ldg(gFhi + (pbase + 1) * 32 + lane);
        uint4 bl0 = __ldg(gFlo + (pbase + 0) * 32 + lane);
        uint4 bl1 = __ldg(gFlo + (pbase + 1) * 32 + lane);
#pragma unroll
        for (int mt = 0; mt < 4; mt++) {
            uint32_t ahi[4], alo[4];
            const uint32_t aRow = (((uint32_t)(wm * 4 + mt)) << 9) + laneOff;
            LDS128(ahi, sbase + OFF_AHI + aRow);
            LDS128(alo, sbase + OFF_ALO + aRow);
            float acc[4][4];
#pragma unroll
            for (int nt = 0; nt < 4; nt++)
#pragma unroll
                for (int e = 0; e < 4; e++) acc[nt][e] = 0.f;
            MMA_F32(acc[0], ahi, bh0.x, bh0.y);
            MMA_F32(acc[1], ahi, bh0.z, bh0.w);
            MMA_F32(acc[2], ahi, bh1.x, bh1.y);
            MMA_F32(acc[3], ahi, bh1.z, bh1.w);
            MMA_F32(acc[0], alo, bh0.x, bh0.y);
            MMA_F32(acc[1], alo, bh0.z, bh0.w);
            MMA_F32(acc[2], alo, bh1.x, bh1.y);
            MMA_F32(acc[3], alo, bh1.z, bh1.w);
            MMA_F32(acc[0], ahi, bl0.x, bl0.y);
            MMA_F32(acc[1], ahi, bl0.z, bl0.w);
            MMA_F32(acc[2], ahi, bl1.x, bl1.y);
            MMA_F32(acc[3], ahi, bl1.z, bl1.w);

#pragma unroll
            for (int nt = 0; nt < 4; nt++) {
                const int j = nh * 128 + wn * 32 + nt * 8 + cq * 2;
#pragma unroll
                for (int q = 0; q < 2; q++) {
                    const int idx = mt * 2 + q;
                    u64 fq = fadd2(*(const u64*)&smf[fhoff[idx] + j],
                                   *(const u64*)&smf[q1off[idx] + j]);
                    u64 S2 = fadd2(pk2(acc[nt][q * 2], acc[nt][q * 2 + 1]), fq);
                    u64 o2 = cs2[nt];
                    ffma2(o2, pk2(mrn[idx], mrn[idx]), gs2[nt]);
                    ffma2(o2, S2, pk2(rstd[idx], rstd[idx]));

                    // ---- packed A&S erf GELU (Newton reciprocal) ----
                    u64 y2v = fmul2(o2, C_IS2);
                    float y0, y1; upk2(y2v, y0, y1);
                    u64 a2p = pk2(fminf(fabsf(y0), 3.9f), fminf(fabsf(y1), 3.9f));
                    u64 wn2 = C_NEG1; ffma2(wn2, a2p, C_NP);     // -(1+p*a)
                    u64 s2v = C_S1;  ffma2(s2v, C_S2c, wn2);
                    u64 k2v = C_S0;  ffma2(k2v, s2v, wn2);       // quadratic seed
                    u64 t2a = C_TWO; ffma2(t2a, wn2, k2v); k2v = fmul2(k2v, t2a);
                    u64 t2b = C_TWO; ffma2(t2b, wn2, k2v); k2v = fmul2(k2v, t2b);
                    u64 sq2 = fmul2(a2p, a2p);
                    u64 ea2 = fmul2(sq2, C_NL2E);
                    float ea0, ea1; upk2(ea2, ea0, ea1);
                    u64 e2v = pk2(fex2(ea0), fex2(ea1));
                    u64 p2 = C_A4; ffma2(p2, C_A5, k2v);
                    u64 p3 = C_A3; ffma2(p3, p2, k2v);
                    u64 p4 = C_A2; ffma2(p4, p3, k2v);
                    u64 p5 = C_A1; ffma2(p5, p4, k2v);
                    u64 pkk = fmul2(p5, k2v);
                    u64 er = C_ONE; ffma2(er, pkk, e2v);         // erf(|y|)
                    float er0, er1; upk2(er, er0, er1);
                    er0 = copysignf(er0, y0);
                    er1 = copysignf(er1, y1);
                    u64 onep = fadd2(pk2(er0, er1), C_ONE);
                    u64 gv = fmul2(o2, onep);                    // 0.5 folded in W2
                    ffma2(part2[idx], gv, w22[nt]);
                }
            }
        }
    }

#pragma unroll
    for (int idx = 0; idx < 8; idx++) {
        const int row = wm * 64 + (idx >> 1) * 16 + (idx & 1) * 8 + g8;
        float plo, phi; upk2(part2[idx], plo, phi);
        smf[OFF_RED / 4 + row * 16 + wn * 4 + cq] = plo + phi;
    }
    __syncthreads();

    if (tid < GRP * T_HOR) {
        const int lno = tid / T_HOR, to = tid % T_HOR;
        const float4* rr = (const float4*)&smf[OFF_RED / 4 + tid * 16];
        float4 r0 = rr[0], r1 = rr[1], r2 = rr[2], r3 = rr[3];
        float s = ((r0.x + r0.y) + (r0.z + r0.w)) + ((r1.x + r1.y) + (r1.z + r1.w)) +
                  ((r2.x + r2.y) + (r2.z + r2.w)) + ((r3.x + r3.y) + (r3.z + r3.w));
        out[(size_t)(b * T_HOR + to) * N_SZ + (n0 + lno)] = s + b2[0];
    }
}

extern "C" void kernel_launch(void* const* d_in, const int* in_sizes, int n_in,
                              void* d_out, int out_size) {
    const float* final_h    = (const float*)d_in[0];
    const float* future_met = (const float*)d_in[1];
    const float* step_q     = (const float*)d_in[2];
    const float* W_fm       = (const float*)d_in[3];
    const float* b_fm       = (const float*)d_in[4];
    const float* gamma      = (const float*)d_in[5];
    const float* beta       = (const float*)d_in[6];
    const float* W1         = (const float*)d_in[7];
    const float* b1         = (const float*)d_in[8];
    const float* W2         = (const float*)d_in[9];
    const float* b2         = (const float*)d_in[10];
    float* out = (float*)d_out;

    prep_pack<<<496, 256>>>(gamma, W1, W_fm, step_q, b_fm, beta);
    prep_big<<<1033, 256>>>(final_h, gamma, W_fm, step_q, b_fm, b1, W2);

    cudaFuncSetAttribute(dhh_main, cudaFuncAttributeMaxDynamicSharedMemorySize, SMEM_TOTAL);
    dhh_main<<<NCTA, TPB, SMEM_TOTAL>>>(future_met, b2, out);
}